// round 4
// baseline (speedup 1.0000x reference)
#include <cuda_runtime.h>
#include <cuda_bf16.h>
#include <cstdint>

#define NH     16
#define DMODEL 1024
#define HDIM   64
#define NEMB   40001
#define NB     2
#define SEQ    512

// ---------------- device scratch ----------------
__device__ float g_Tx[NEMB * NH];
__device__ float g_Ty[NEMB * NH];
__device__ float g_Qp[NB * NH * SEQ * HDIM];
__device__ float g_Kp[NB * NH * SEQ * HDIM];
__device__ float g_Vp[NB * NH * SEQ * HDIM];
__device__ float g_bias[(size_t)NB * NH * SEQ * SEQ];

// bf16 hi/lo split operands
__device__ __nv_bfloat16 g_actH[3 * DMODEL * DMODEL];   // q,k,v activations [m][k]
__device__ __nv_bfloat16 g_actL[3 * DMODEL * DMODEL];
__device__ __nv_bfloat16 g_WtH[4 * DMODEL * DMODEL];    // Wq,Wk,Wv,Wo transposed [n][k]
__device__ __nv_bfloat16 g_WtL[4 * DMODEL * DMODEL];
__device__ __nv_bfloat16 g_attH[DMODEL * DMODEL];       // attn out hi/lo [b*q][h*64+d]
__device__ __nv_bfloat16 g_attL[DMODEL * DMODEL];

// ---------------- non-gated PTX helpers ----------------
__device__ __forceinline__ uint32_t smem_u32(const void* p) {
    uint32_t a;
    asm("{ .reg .u64 t; cvta.to.shared.u64 t, %1; cvt.u32.u64 %0, t; }" : "=r"(a) : "l"(p));
    return a;
}
__device__ __forceinline__ void cp_async16(uint32_t saddr, const void* gptr) {
    asm volatile("cp.async.cg.shared.global [%0], [%1], 16;" :: "r"(saddr), "l"(gptr) : "memory");
}
#define CP_COMMIT() asm volatile("cp.async.commit_group;" ::: "memory")
#define CP_WAIT(n)  asm volatile("cp.async.wait_group %0;" :: "n"(n) : "memory")

__device__ __forceinline__ void ldsm_x4(uint32_t* r, uint32_t addr) {
    asm volatile("ldmatrix.sync.aligned.m8n8.x4.shared.b16 {%0,%1,%2,%3}, [%4];"
                 : "=r"(r[0]), "=r"(r[1]), "=r"(r[2]), "=r"(r[3]) : "r"(addr));
}
__device__ __forceinline__ void ldsm_x2(uint32_t* r, uint32_t addr) {
    asm volatile("ldmatrix.sync.aligned.m8n8.x2.shared.b16 {%0,%1}, [%2];"
                 : "=r"(r[0]), "=r"(r[1]) : "r"(addr));
}
__device__ __forceinline__ void mma16816(float* d, const uint32_t* a, const uint32_t* b) {
    asm volatile("mma.sync.aligned.m16n8k16.row.col.f32.bf16.bf16.f32 "
                 "{%0,%1,%2,%3}, {%4,%5,%6,%7}, {%8,%9}, {%0,%1,%2,%3};"
                 : "+f"(d[0]), "+f"(d[1]), "+f"(d[2]), "+f"(d[3])
                 : "r"(a[0]), "r"(a[1]), "r"(a[2]), "r"(a[3]), "r"(b[0]), "r"(b[1]));
}

// ---------------- kernel 1: project embedding tables through Wb ----------------
__global__ __launch_bounds__(256) void k_project(const float* __restrict__ xt,
                                                 const float* __restrict__ yt,
                                                 const float* __restrict__ Wb) {
    int id = blockIdx.x * 256 + threadIdx.x;
    if (id >= 2 * NEMB * NH) return;
    int which = (id >= NEMB * NH);
    int rid = which ? id - NEMB * NH : id;
    int r = rid >> 4, h = rid & 15;
    const float4* row = (const float4*)((which ? yt : xt) + (size_t)r * 256 + h * 16);
    const float4* wb = (const float4*)Wb;
    float s = 0.f;
#pragma unroll
    for (int q = 0; q < 4; q++) {
        float4 v = row[q], w = wb[q];
        s += v.x * w.x + v.y * w.y + v.z * w.z + v.w * w.w;
    }
    (which ? g_Ty : g_Tx)[rid] = s;
}

// ---------------- kernel 2: positional bias ----------------
__global__ __launch_bounds__(256) void k_bias(const float* __restrict__ qx,
                                              const float* __restrict__ qy,
                                              const float* __restrict__ kx,
                                              const float* __restrict__ ky,
                                              const float* __restrict__ bbp) {
    __shared__ float sm[16 * 256];
    int b = blockIdx.z;
    int i0 = blockIdx.y * 16, j0 = blockIdx.x * 16;
    int t = threadIdx.x;
    int i = i0 + (t >> 4), j = j0 + (t & 15);
    float bb = bbp[0];
    float dx = qx[b * SEQ + j] - kx[b * SEQ + i];
    float dy = qy[b * SEQ + j] - ky[b * SEQ + i];
    dx = fminf(fmaxf(dx, -1000.f), 1000.f);
    dy = fminf(fmaxf(dy, -1000.f), 1000.f);
    int ix = (int)rintf((dx + 1000.f) * 20.f);
    int iy = (int)rintf((dy + 1000.f) * 20.f);
    const float4* px = (const float4*)(g_Tx + (size_t)ix * 16);
    const float4* py = (const float4*)(g_Ty + (size_t)iy * 16);
#pragma unroll
    for (int q = 0; q < 4; q++) {
        float4 a = px[q], c = py[q];
        float v0 = a.x + c.x + bb, v1 = a.y + c.y + bb;
        float v2 = a.z + c.z + bb, v3 = a.w + c.w + bb;
        sm[(q * 4 + 0) * 256 + t] = 1.f / (1.f + __expf(-v0));
        sm[(q * 4 + 1) * 256 + t] = 1.f / (1.f + __expf(-v1));
        sm[(q * 4 + 2) * 256 + t] = 1.f / (1.f + __expf(-v2));
        sm[(q * 4 + 3) * 256 + t] = 1.f / (1.f + __expf(-v3));
    }
    __syncthreads();
    int h = t >> 4, w = t & 15;
#pragma unroll
    for (int ii = 0; ii < 16; ii++) {
        g_bias[(((size_t)(b * NH + h)) * SEQ + (i0 + ii)) * SEQ + (j0 + w)] =
            sm[h * 256 + ii * 16 + w];
    }
}

// ---------------- bf16 hi/lo split helpers ----------------
__device__ __forceinline__ void split4(float4 x, __nv_bfloat162* ph, __nv_bfloat162* pl) {
    __nv_bfloat162 h01 = __floats2bfloat162_rn(x.x, x.y);
    __nv_bfloat162 h23 = __floats2bfloat162_rn(x.z, x.w);
    __nv_bfloat162 l01 = __floats2bfloat162_rn(x.x - __bfloat162float(__low2bfloat16(h01)),
                                               x.y - __bfloat162float(__high2bfloat16(h01)));
    __nv_bfloat162 l23 = __floats2bfloat162_rn(x.z - __bfloat162float(__low2bfloat16(h23)),
                                               x.w - __bfloat162float(__high2bfloat16(h23)));
    ph[0] = h01; ph[1] = h23; pl[0] = l01; pl[1] = l23;
}

__global__ __launch_bounds__(256) void k_convA(const float* __restrict__ q,
                                               const float* __restrict__ k,
                                               const float* __restrict__ v) {
    int z = blockIdx.z;
    const float* src = (z == 0) ? q : (z == 1) ? k : v;
    __nv_bfloat16* H = g_actH + (size_t)z * DMODEL * DMODEL;
    __nv_bfloat16* L = g_actL + (size_t)z * DMODEL * DMODEL;
    int i = blockIdx.x * 256 + threadIdx.x;
    float4 x = ((const float4*)src)[i];
    split4(x, (__nv_bfloat162*)(H + (size_t)i * 4), (__nv_bfloat162*)(L + (size_t)i * 4));
}

__global__ void k_convW(const float* __restrict__ Wq, const float* __restrict__ Wk,
                        const float* __restrict__ Wv, const float* __restrict__ Wo) {
    __shared__ float t[32][33];
    int z = blockIdx.z;
    const float* W = (z == 0) ? Wq : (z == 1) ? Wk : (z == 2) ? Wv : Wo;
    __nv_bfloat16* H = g_WtH + (size_t)z * DMODEL * DMODEL;
    __nv_bfloat16* L = g_WtL + (size_t)z * DMODEL * DMODEL;
    int nb = blockIdx.x * 32, kb = blockIdx.y * 32;
    int tx = threadIdx.x, ty = threadIdx.y;  // 32 x 8
#pragma unroll
    for (int i = 0; i < 4; i++)
        t[ty + i * 8][tx] = W[(size_t)(kb + ty + i * 8) * DMODEL + nb + tx];
    __syncthreads();
#pragma unroll
    for (int i = 0; i < 4; i++) {
        int n = nb + ty + i * 8, k = kb + tx;
        float v = t[tx][ty + i * 8];
        __nv_bfloat16 h = __float2bfloat16(v);
        H[(size_t)n * DMODEL + k] = h;
        L[(size_t)n * DMODEL + k] = __float2bfloat16(v - __bfloat162float(h));
    }
}

// ---------------- warp-mma GEMM: C = A @ Wt^T + bias ----------------
// 3-term hi/lo split folded into one K=3072 GEMM (phases: AhBh, AlBh, AhBl).
// BM=BN=128, BK=32, 8 warps (2m x 4n), 3-stage cp.async pipeline, 1 sync/iter.
#define NKITER 96
#define STAGES 3

template <int MODE>
__device__ __forceinline__ void mma_body(const __nv_bfloat16* __restrict__ Ah,
                                         const __nv_bfloat16* __restrict__ Al,
                                         const __nv_bfloat16* __restrict__ Bh,
                                         const __nv_bfloat16* __restrict__ Bl,
                                         const float* __restrict__ bias,
                                         float* __restrict__ C) {
    __shared__ __align__(1024) char smem[STAGES][16384];   // per stage: A 8KB | B 8KB
    int tid = threadIdx.x, lane = tid & 31, wid = tid >> 5;
    int wm = wid & 1, wn = wid >> 1;                  // 2 x 4 warp grid
    int m0 = blockIdx.y * 128, n0 = blockIdx.x * 128;
    uint32_t sbase = smem_u32(smem);

    float acc[4][4][4];
#pragma unroll
    for (int i = 0; i < 4; i++)
#pragma unroll
        for (int j = 0; j < 4; j++)
#pragma unroll
            for (int r = 0; r < 4; r++) acc[i][j][r] = 0.f;

    auto issue_tile = [&](int ki, int s) {
        int phase = ki >> 5;
        int kk = (ki & 31) * 32;
        const __nv_bfloat16* Ap = (phase == 1) ? Al : Ah;
        const __nv_bfloat16* Bp = (phase == 2) ? Bl : Bh;
        uint32_t sA = sbase + s * 16384, sB = sA + 8192;
#pragma unroll
        for (int j = 0; j < 2; j++) {
            int idx = tid + j * 256;                   // 512 chunks
            int row = idx >> 2, c = idx & 3;
            int cs = c ^ ((row >> 1) & 3);
            cp_async16(sA + row * 64 + cs * 16, Ap + (size_t)(m0 + row) * DMODEL + kk + c * 8);
            cp_async16(sB + row * 64 + cs * 16, Bp + (size_t)(n0 + row) * DMODEL + kk + c * 8);
        }
        CP_COMMIT();
    };

    issue_tile(0, 0);
    issue_tile(1, 1);
    for (int ki = 0; ki < NKITER; ki++) {
        int s = ki % STAGES;
        if (ki + 1 < NKITER) { CP_WAIT(1); } else { CP_WAIT(0); }
        __syncthreads();
        if (ki + STAGES - 1 < NKITER)
            issue_tile(ki + STAGES - 1, (ki + STAGES - 1) % STAGES);
        uint32_t sA = sbase + s * 16384, sB = sA + 8192;
#pragma unroll
        for (int kq = 0; kq < 2; kq++) {
            uint32_t af[4][4], bf[4][2];
#pragma unroll
            for (int im = 0; im < 4; im++) {
                int row = wm * 64 + im * 16 + (lane & 15);
                int c = kq * 2 + (lane >> 4);
                int cs = c ^ ((row >> 1) & 3);
                ldsm_x4(af[im], sA + row * 64 + cs * 16);
            }
#pragma unroll
            for (int jn = 0; jn < 4; jn++) {
                int row = wn * 32 + jn * 8 + (lane & 7);
                int c = kq * 2 + ((lane >> 3) & 1);
                int cs = c ^ ((row >> 1) & 3);
                ldsm_x2(bf[jn], sB + row * 64 + cs * 16);
            }
#pragma unroll
            for (int im = 0; im < 4; im++)
#pragma unroll
                for (int jn = 0; jn < 4; jn++) mma16816(acc[im][jn], af[im], bf[jn]);
        }
    }

    // epilogue
#pragma unroll
    for (int im = 0; im < 4; im++) {
#pragma unroll
        for (int jn = 0; jn < 4; jn++) {
            int col = n0 + wn * 32 + jn * 8 + 2 * (lane & 3);
            float b0 = bias[col], b1 = bias[col + 1];
#pragma unroll
            for (int half = 0; half < 2; half++) {
                int m = m0 + wm * 64 + im * 16 + (lane >> 2) + half * 8;
                size_t idx;
                if (MODE == 0) {
                    int bidx = m >> 9, nseq = m & 511;
                    int h = col >> 6, d = col & 63;
                    idx = (((size_t)(bidx * NH + h)) * SEQ + nseq) * HDIM + d;
                } else {
                    idx = (size_t)m * DMODEL + col;
                }
                float2 v = make_float2(acc[im][jn][half * 2 + 0] + b0,
                                       acc[im][jn][half * 2 + 1] + b1);
                *(float2*)(C + idx) = v;
            }
        }
    }
}

__global__ __launch_bounds__(256, 2) void k_mma_qkv(const float* __restrict__ bq,
                                                    const float* __restrict__ bk,
                                                    const float* __restrict__ bv) {
    int z = blockIdx.z;
    const __nv_bfloat16* Ah = g_actH + (size_t)z * DMODEL * DMODEL;
    const __nv_bfloat16* Al = g_actL + (size_t)z * DMODEL * DMODEL;
    const __nv_bfloat16* Bh = g_WtH + (size_t)z * DMODEL * DMODEL;
    const __nv_bfloat16* Bl = g_WtL + (size_t)z * DMODEL * DMODEL;
    const float* bias = (z == 0) ? bq : (z == 1) ? bk : bv;
    float* C = (z == 0) ? g_Qp : (z == 1) ? g_Kp : g_Vp;
    mma_body<0>(Ah, Al, Bh, Bl, bias, C);
}

__global__ __launch_bounds__(256, 2) void k_mma_out(const float* __restrict__ bo,
                                                    float* __restrict__ out) {
    mma_body<1>(g_attH, g_attL,
                g_WtH + (size_t)3 * DMODEL * DMODEL, g_WtL + (size_t)3 * DMODEL * DMODEL,
                bo, out);
}

// ---------------- fused attention (flash-style, fp32 SIMT, q-tile 32) ----------------
__global__ __launch_bounds__(256) void k_attn() {
    __shared__ float Qs[64][32];   // [d][i]  Q transposed
    __shared__ float KP[64][64];   // K as [d][j], reused for P as [i][j]
    __shared__ float Vs[64][64];   // [k][d]
    int b = blockIdx.z, h = blockIdx.y, q0 = blockIdx.x * 32;
    int t = threadIdx.x, tx = t & 15, ty = t >> 4;
    const float* Qg = g_Qp + (size_t)(b * NH + h) * SEQ * HDIM;
    const float* Kg = g_Kp + (size_t)(b * NH + h) * SEQ * HDIM;
    const float* Vg = g_Vp + (size_t)(b * NH + h) * SEQ * HDIM;
    const float* Bg = g_bias + ((size_t)(b * NH + h) * SEQ + q0) * SEQ;

    // load Q tile (32 rows) transposed
#pragma unroll
    for (int u = 0; u < 2; u++) {
        int f = t + u * 256;
        int r = f & 31, cq = f >> 5;
        float4 v = *(const float4*)(Qg + (size_t)(q0 + r) * HDIM + cq * 4);
        Qs[cq * 4 + 0][r] = v.x; Qs[cq * 4 + 1][r] = v.y;
        Qs[cq * 4 + 2][r] = v.z; Qs[cq * 4 + 3][r] = v.w;
    }

    float m_[2], l_[2], acc[2][4];
#pragma unroll
    for (int i = 0; i < 2; i++) {
        m_[i] = -1e30f; l_[i] = 0.f;
#pragma unroll
        for (int j = 0; j < 4; j++) acc[i][j] = 0.f;
    }

    for (int k0 = 0; k0 < SEQ; k0 += 64) {
        __syncthreads();
#pragma unroll
        for (int u = 0; u < 4; u++) {
            int f = t + u * 256;
            int r = f & 63, cq = f >> 6;
            float4 kv = *(const float4*)(Kg + (size_t)(k0 + r) * HDIM + cq * 4);
            KP[cq * 4 + 0][r] = kv.x; KP[cq * 4 + 1][r] = kv.y;
            KP[cq * 4 + 2][r] = kv.z; KP[cq * 4 + 3][r] = kv.w;
            int rv = f >> 4, cv = (f & 15) * 4;
            float4 vv = *(const float4*)(Vg + (size_t)(k0 + rv) * HDIM + cv);
            *(float4*)&Vs[rv][cv] = vv;
        }
        __syncthreads();

        float s[2][4];
#pragma unroll
        for (int i = 0; i < 2; i++)
#pragma unroll
            for (int j = 0; j < 4; j++) s[i][j] = 0.f;
#pragma unroll 8
        for (int d = 0; d < 64; d++) {
            float2 qf = *(float2*)&Qs[d][ty * 2];
            float4 kf = *(float4*)&KP[d][tx * 4];
            float qa[2] = {qf.x, qf.y};
            float ka[4] = {kf.x, kf.y, kf.z, kf.w};
#pragma unroll
            for (int i = 0; i < 2; i++)
#pragma unroll
                for (int j = 0; j < 4; j++) s[i][j] += qa[i] * ka[j];
        }

#pragma unroll
        for (int ii = 0; ii < 2; ii++) {
            float4 bf = *(const float4*)(Bg + (size_t)(ty * 2 + ii) * SEQ + k0 + tx * 4);
            s[ii][0] = s[ii][0] * 0.125f + bf.x;
            s[ii][1] = s[ii][1] * 0.125f + bf.y;
            s[ii][2] = s[ii][2] * 0.125f + bf.z;
            s[ii][3] = s[ii][3] * 0.125f + bf.w;
            float mx = fmaxf(fmaxf(s[ii][0], s[ii][1]), fmaxf(s[ii][2], s[ii][3]));
#pragma unroll
            for (int o = 1; o < 16; o <<= 1) mx = fmaxf(mx, __shfl_xor_sync(0xffffffffu, mx, o));
            float mn = fmaxf(m_[ii], mx);
            float corr = __expf(m_[ii] - mn);
            float rs = 0.f;
#pragma unroll
            for (int j = 0; j < 4; j++) {
                float p = __expf(s[ii][j] - mn);
                s[ii][j] = p; rs += p;
            }
#pragma unroll
            for (int o = 1; o < 16; o <<= 1) rs += __shfl_xor_sync(0xffffffffu, rs, o);
            l_[ii] = l_[ii] * corr + rs;
            m_[ii] = mn;
#pragma unroll
            for (int j = 0; j < 4; j++) acc[ii][j] *= corr;
        }

        __syncthreads();
#pragma unroll
        for (int ii = 0; ii < 2; ii++)
            *(float4*)&KP[ty * 2 + ii][tx * 4] =
                make_float4(s[ii][0], s[ii][1], s[ii][2], s[ii][3]);
        __syncthreads();

#pragma unroll 8
        for (int k = 0; k < 64; k++) {
            float4 vf = *(float4*)&Vs[k][tx * 4];
            float va[4] = {vf.x, vf.y, vf.z, vf.w};
#pragma unroll
            for (int ii = 0; ii < 2; ii++) {
                float p = KP[ty * 2 + ii][k];
                acc[ii][0] += p * va[0]; acc[ii][1] += p * va[1];
                acc[ii][2] += p * va[2]; acc[ii][3] += p * va[3];
            }
        }
    }

    // epilogue: normalize + write bf16 hi/lo directly (feeds output GEMM)
#pragma unroll
    for (int ii = 0; ii < 2; ii++) {
        float rl = 1.f / l_[ii];
        int q = q0 + ty * 2 + ii;
        float4 o = make_float4(acc[ii][0] * rl, acc[ii][1] * rl,
                               acc[ii][2] * rl, acc[ii][3] * rl);
        size_t idx = ((size_t)(b * SEQ + q) * NH + h) * HDIM + tx * 4;  // [b*q][h*64+d]
        split4(o, (__nv_bfloat162*)(g_attH + idx), (__nv_bfloat162*)(g_attL + idx));
    }
}

// ---------------- launch ----------------
extern "C" void kernel_launch(void* const* d_in, const int* in_sizes, int n_in,
                              void* d_out, int out_size) {
    (void)in_sizes; (void)n_in; (void)out_size;
    const float* query = (const float*)d_in[0];
    const float* key   = (const float*)d_in[1];
    const float* value = (const float*)d_in[2];
    const float* qx    = (const float*)d_in[3];
    const float* qy    = (const float*)d_in[4];
    const float* kx    = (const float*)d_in[5];
    const float* ky    = (const float*)d_in[6];
    const float* Wq    = (const float*)d_in[7];
    const float* bq    = (const float*)d_in[8];
    const float* Wk    = (const float*)d_in[9];
    const float* bk    = (const float*)d_in[10];
    const float* Wv    = (const float*)d_in[11];
    const float* bv    = (const float*)d_in[12];
    const float* Wo    = (const float*)d_in[13];
    const float* bo    = (const float*)d_in[14];
    const float* xt    = (const float*)d_in[15];
    const float* yt    = (const float*)d_in[16];
    const float* Wb    = (const float*)d_in[17];
    const float* bb    = (const float*)d_in[18];
    float* out = (float*)d_out;

    k_project<<<(2 * NEMB * NH + 255) / 256, 256>>>(xt, yt, Wb);
    k_bias<<<dim3(SEQ / 16, SEQ / 16, NB), 256>>>(qx, qy, kx, ky, bb);
    k_convA<<<dim3(DMODEL * DMODEL / 4 / 256, 1, 3), 256>>>(query, key, value);
    k_convW<<<dim3(32, 32, 4), dim3(32, 8)>>>(Wq, Wk, Wv, Wo);
    k_mma_qkv<<<dim3(8, 8, 3), 256>>>(bq, bk, bv);
    k_attn<<<dim3(SEQ / 32, NH, NB), 256>>>();
    k_mma_out<<<dim3(8, 8), 256>>>(bo, out);
}

// round 5
// speedup vs baseline: 1.1781x; 1.1781x over previous
#include <cuda_runtime.h>
#include <cuda_bf16.h>
#include <cstdint>

#define NH     16
#define DMODEL 1024
#define HDIM   64
#define NEMB   40001
#define NB     2
#define SEQ    512

// ---------------- device scratch ----------------
__device__ float g_Tx[NEMB * NH];
__device__ float g_Ty[NEMB * NH];
__device__ float g_bias[(size_t)NB * NH * SEQ * SEQ];

// bf16 hi/lo split operands
__device__ __nv_bfloat16 g_actH[3 * DMODEL * DMODEL];   // q,k,v activations [m][k]
__device__ __nv_bfloat16 g_actL[3 * DMODEL * DMODEL];
__device__ __nv_bfloat16 g_WtH[4 * DMODEL * DMODEL];    // Wq,Wk,Wv,Wo transposed [n][k]
__device__ __nv_bfloat16 g_WtL[4 * DMODEL * DMODEL];
// projected Q/K/V in [b][h][seq][d], bf16 hi/lo (Q pre-scaled by 0.125)
__device__ __nv_bfloat16 g_QH[NB * NH * SEQ * HDIM], g_QL[NB * NH * SEQ * HDIM];
__device__ __nv_bfloat16 g_KH[NB * NH * SEQ * HDIM], g_KL[NB * NH * SEQ * HDIM];
__device__ __nv_bfloat16 g_VH[NB * NH * SEQ * HDIM], g_VL[NB * NH * SEQ * HDIM];
// attention output hi/lo, [b*q][h*64+d] row-major 1024x1024
__device__ __nv_bfloat16 g_attH[DMODEL * DMODEL];
__device__ __nv_bfloat16 g_attL[DMODEL * DMODEL];

// ---------------- non-gated PTX helpers ----------------
__device__ __forceinline__ uint32_t smem_u32(const void* p) {
    uint32_t a;
    asm("{ .reg .u64 t; cvta.to.shared.u64 t, %1; cvt.u32.u64 %0, t; }" : "=r"(a) : "l"(p));
    return a;
}
__device__ __forceinline__ void cp_async16(uint32_t saddr, const void* gptr) {
    asm volatile("cp.async.cg.shared.global [%0], [%1], 16;" :: "r"(saddr), "l"(gptr) : "memory");
}
#define CP_COMMIT() asm volatile("cp.async.commit_group;" ::: "memory")
#define CP_WAIT(n)  asm volatile("cp.async.wait_group %0;" :: "n"(n) : "memory")

__device__ __forceinline__ void ldsm_x4(uint32_t* r, uint32_t addr) {
    asm volatile("ldmatrix.sync.aligned.m8n8.x4.shared.b16 {%0,%1,%2,%3}, [%4];"
                 : "=r"(r[0]), "=r"(r[1]), "=r"(r[2]), "=r"(r[3]) : "r"(addr));
}
__device__ __forceinline__ void ldsm_x2(uint32_t* r, uint32_t addr) {
    asm volatile("ldmatrix.sync.aligned.m8n8.x2.shared.b16 {%0,%1}, [%2];"
                 : "=r"(r[0]), "=r"(r[1]) : "r"(addr));
}
__device__ __forceinline__ void ldsm_x2_trans(uint32_t* r, uint32_t addr) {
    asm volatile("ldmatrix.sync.aligned.m8n8.x2.trans.shared.b16 {%0,%1}, [%2];"
                 : "=r"(r[0]), "=r"(r[1]) : "r"(addr));
}
__device__ __forceinline__ void mma16816(float* d, const uint32_t* a, const uint32_t* b) {
    asm volatile("mma.sync.aligned.m16n8k16.row.col.f32.bf16.bf16.f32 "
                 "{%0,%1,%2,%3}, {%4,%5,%6,%7}, {%8,%9}, {%0,%1,%2,%3};"
                 : "+f"(d[0]), "+f"(d[1]), "+f"(d[2]), "+f"(d[3])
                 : "r"(a[0]), "r"(a[1]), "r"(a[2]), "r"(a[3]), "r"(b[0]), "r"(b[1]));
}
// pack two floats into bf16x2 hi part + bf16x2 residual part
__device__ __forceinline__ void packhl(float a, float b, uint32_t& hh, uint32_t& ll) {
    __nv_bfloat162 h2 = __floats2bfloat162_rn(a, b);
    float ra = a - __bfloat162float(__low2bfloat16(h2));
    float rb = b - __bfloat162float(__high2bfloat16(h2));
    __nv_bfloat162 l2 = __floats2bfloat162_rn(ra, rb);
    hh = *reinterpret_cast<uint32_t*>(&h2);
    ll = *reinterpret_cast<uint32_t*>(&l2);
}

// ---------------- kernel 1: project embedding tables through Wb ----------------
__global__ __launch_bounds__(256) void k_project(const float* __restrict__ xt,
                                                 const float* __restrict__ yt,
                                                 const float* __restrict__ Wb) {
    int id = blockIdx.x * 256 + threadIdx.x;
    if (id >= 2 * NEMB * NH) return;
    int which = (id >= NEMB * NH);
    int rid = which ? id - NEMB * NH : id;
    int r = rid >> 4, h = rid & 15;
    const float4* row = (const float4*)((which ? yt : xt) + (size_t)r * 256 + h * 16);
    const float4* wb = (const float4*)Wb;
    float s = 0.f;
#pragma unroll
    for (int q = 0; q < 4; q++) {
        float4 v = row[q], w = wb[q];
        s += v.x * w.x + v.y * w.y + v.z * w.z + v.w * w.w;
    }
    (which ? g_Ty : g_Tx)[rid] = s;
}

// ---------------- kernel 2: positional bias ----------------
__global__ __launch_bounds__(256) void k_bias(const float* __restrict__ qx,
                                              const float* __restrict__ qy,
                                              const float* __restrict__ kx,
                                              const float* __restrict__ ky,
                                              const float* __restrict__ bbp) {
    __shared__ float sm[16 * 256];
    int b = blockIdx.z;
    int i0 = blockIdx.y * 16, j0 = blockIdx.x * 16;
    int t = threadIdx.x;
    int i = i0 + (t >> 4), j = j0 + (t & 15);
    float bb = bbp[0];
    float dx = qx[b * SEQ + j] - kx[b * SEQ + i];
    float dy = qy[b * SEQ + j] - ky[b * SEQ + i];
    dx = fminf(fmaxf(dx, -1000.f), 1000.f);
    dy = fminf(fmaxf(dy, -1000.f), 1000.f);
    int ix = (int)rintf((dx + 1000.f) * 20.f);
    int iy = (int)rintf((dy + 1000.f) * 20.f);
    const float4* px = (const float4*)(g_Tx + (size_t)ix * 16);
    const float4* py = (const float4*)(g_Ty + (size_t)iy * 16);
#pragma unroll
    for (int q = 0; q < 4; q++) {
        float4 a = px[q], c = py[q];
        float v0 = a.x + c.x + bb, v1 = a.y + c.y + bb;
        float v2 = a.z + c.z + bb, v3 = a.w + c.w + bb;
        sm[(q * 4 + 0) * 256 + t] = 1.f / (1.f + __expf(-v0));
        sm[(q * 4 + 1) * 256 + t] = 1.f / (1.f + __expf(-v1));
        sm[(q * 4 + 2) * 256 + t] = 1.f / (1.f + __expf(-v2));
        sm[(q * 4 + 3) * 256 + t] = 1.f / (1.f + __expf(-v3));
    }
    __syncthreads();
    int h = t >> 4, w = t & 15;
#pragma unroll
    for (int ii = 0; ii < 16; ii++) {
        g_bias[(((size_t)(b * NH + h)) * SEQ + (i0 + ii)) * SEQ + (j0 + w)] =
            sm[h * 256 + ii * 16 + w];
    }
}

// ---------------- bf16 hi/lo split helpers ----------------
__device__ __forceinline__ void split4(float4 x, __nv_bfloat162* ph, __nv_bfloat162* pl) {
    __nv_bfloat162 h01 = __floats2bfloat162_rn(x.x, x.y);
    __nv_bfloat162 h23 = __floats2bfloat162_rn(x.z, x.w);
    __nv_bfloat162 l01 = __floats2bfloat162_rn(x.x - __bfloat162float(__low2bfloat16(h01)),
                                               x.y - __bfloat162float(__high2bfloat16(h01)));
    __nv_bfloat162 l23 = __floats2bfloat162_rn(x.z - __bfloat162float(__low2bfloat16(h23)),
                                               x.w - __bfloat162float(__high2bfloat16(h23)));
    ph[0] = h01; ph[1] = h23; pl[0] = l01; pl[1] = l23;
}

__global__ __launch_bounds__(256) void k_convA(const float* __restrict__ q,
                                               const float* __restrict__ k,
                                               const float* __restrict__ v) {
    int z = blockIdx.z;
    const float* src = (z == 0) ? q : (z == 1) ? k : v;
    __nv_bfloat16* H = g_actH + (size_t)z * DMODEL * DMODEL;
    __nv_bfloat16* L = g_actL + (size_t)z * DMODEL * DMODEL;
    int i = blockIdx.x * 256 + threadIdx.x;
    float4 x = ((const float4*)src)[i];
    split4(x, (__nv_bfloat162*)(H + (size_t)i * 4), (__nv_bfloat162*)(L + (size_t)i * 4));
}

__global__ void k_convW(const float* __restrict__ Wq, const float* __restrict__ Wk,
                        const float* __restrict__ Wv, const float* __restrict__ Wo) {
    __shared__ float t[32][33];
    int z = blockIdx.z;
    const float* W = (z == 0) ? Wq : (z == 1) ? Wk : (z == 2) ? Wv : Wo;
    __nv_bfloat16* H = g_WtH + (size_t)z * DMODEL * DMODEL;
    __nv_bfloat16* L = g_WtL + (size_t)z * DMODEL * DMODEL;
    int nb = blockIdx.x * 32, kb = blockIdx.y * 32;
    int tx = threadIdx.x, ty = threadIdx.y;  // 32 x 8
#pragma unroll
    for (int i = 0; i < 4; i++)
        t[ty + i * 8][tx] = W[(size_t)(kb + ty + i * 8) * DMODEL + nb + tx];
    __syncthreads();
#pragma unroll
    for (int i = 0; i < 4; i++) {
        int n = nb + ty + i * 8, k = kb + tx;
        float v = t[tx][ty + i * 8];
        __nv_bfloat16 h = __float2bfloat16(v);
        H[(size_t)n * DMODEL + k] = h;
        L[(size_t)n * DMODEL + k] = __float2bfloat16(v - __bfloat162float(h));
    }
}

// ---------------- warp-mma GEMM: C = A @ Wt^T + bias (R3 config) ----------------
// 3-term hi/lo split folded into one K=3072 GEMM (phases: AhBh, AlBh, AhBl).
// BM=BN=128, BK=32, 8 warps (2m x 4n), 2-stage cp.async pipeline.
// MODE 0: write bf16 hi/lo to OH/OL in [b][h][seq][d], value=(acc+bias)*scale.
// MODE 1: write f32 row-major to OF.
#define NKITER 96

template <int MODE>
__device__ __forceinline__ void mma_body(const __nv_bfloat16* __restrict__ Ah,
                                         const __nv_bfloat16* __restrict__ Al,
                                         const __nv_bfloat16* __restrict__ Bh,
                                         const __nv_bfloat16* __restrict__ Bl,
                                         const float* __restrict__ bias,
                                         __nv_bfloat16* __restrict__ OH,
                                         __nv_bfloat16* __restrict__ OL,
                                         float* __restrict__ OF,
                                         float scale) {
    __shared__ __align__(1024) char smem[2][16384];   // per stage: A 8KB | B 8KB
    int tid = threadIdx.x, lane = tid & 31, wid = tid >> 5;
    int wm = wid & 1, wn = wid >> 1;                  // 2 x 4 warp grid
    int m0 = blockIdx.y * 128, n0 = blockIdx.x * 128;
    uint32_t sbase = smem_u32(smem);

    float acc[4][4][4];
#pragma unroll
    for (int i = 0; i < 4; i++)
#pragma unroll
        for (int j = 0; j < 4; j++)
#pragma unroll
            for (int r = 0; r < 4; r++) acc[i][j][r] = 0.f;

    auto issue_tile = [&](int ki, int s) {
        int phase = ki >> 5;
        int kk = (ki & 31) * 32;
        const __nv_bfloat16* Ap = (phase == 1) ? Al : Ah;
        const __nv_bfloat16* Bp = (phase == 2) ? Bl : Bh;
        uint32_t sA = sbase + s * 16384, sB = sA + 8192;
#pragma unroll
        for (int j = 0; j < 2; j++) {
            int idx = tid + j * 256;                   // 512 chunks
            int row = idx >> 2, c = idx & 3;
            int cs = c ^ ((row >> 1) & 3);
            cp_async16(sA + row * 64 + cs * 16, Ap + (size_t)(m0 + row) * DMODEL + kk + c * 8);
            cp_async16(sB + row * 64 + cs * 16, Bp + (size_t)(n0 + row) * DMODEL + kk + c * 8);
        }
        CP_COMMIT();
    };

    issue_tile(0, 0);
    for (int ki = 0; ki < NKITER; ki++) {
        int s = ki & 1;
        if (ki + 1 < NKITER) {
            issue_tile(ki + 1, s ^ 1);
            CP_WAIT(1);
        } else {
            CP_WAIT(0);
        }
        __syncthreads();
        uint32_t sA = sbase + s * 16384, sB = sA + 8192;
#pragma unroll
        for (int kq = 0; kq < 2; kq++) {
            uint32_t af[4][4], bf[4][2];
#pragma unroll
            for (int im = 0; im < 4; im++) {
                int row = wm * 64 + im * 16 + (lane & 15);
                int c = kq * 2 + (lane >> 4);
                int cs = c ^ ((row >> 1) & 3);
                ldsm_x4(af[im], sA + row * 64 + cs * 16);
            }
#pragma unroll
            for (int jn = 0; jn < 4; jn++) {
                int row = wn * 32 + jn * 8 + (lane & 7);
                int c = kq * 2 + ((lane >> 3) & 1);
                int cs = c ^ ((row >> 1) & 3);
                ldsm_x2(bf[jn], sB + row * 64 + cs * 16);
            }
#pragma unroll
            for (int im = 0; im < 4; im++)
#pragma unroll
                for (int jn = 0; jn < 4; jn++) mma16816(acc[im][jn], af[im], bf[jn]);
        }
        __syncthreads();
    }

    // epilogue
#pragma unroll
    for (int im = 0; im < 4; im++) {
#pragma unroll
        for (int jn = 0; jn < 4; jn++) {
            int col = n0 + wn * 32 + jn * 8 + 2 * (lane & 3);
            float b0 = bias[col], b1 = bias[col + 1];
#pragma unroll
            for (int half = 0; half < 2; half++) {
                int m = m0 + wm * 64 + im * 16 + (lane >> 2) + half * 8;
                float v0 = (acc[im][jn][half * 2 + 0] + b0) * scale;
                float v1 = (acc[im][jn][half * 2 + 1] + b1) * scale;
                if (MODE == 0) {
                    int bidx = m >> 9, nseq = m & 511;
                    int h = col >> 6, d = col & 63;
                    size_t idx = (((size_t)(bidx * NH + h)) * SEQ + nseq) * HDIM + d;
                    uint32_t hh, ll;
                    packhl(v0, v1, hh, ll);
                    *(uint32_t*)(OH + idx) = hh;
                    *(uint32_t*)(OL + idx) = ll;
                } else {
                    *(float2*)(OF + (size_t)m * DMODEL + col) = make_float2(v0, v1);
                }
            }
        }
    }
}

__global__ __launch_bounds__(256) void k_mma_qkv(const float* __restrict__ bq,
                                                 const float* __restrict__ bk,
                                                 const float* __restrict__ bv) {
    int z = blockIdx.z;
    const __nv_bfloat16* Ah = g_actH + (size_t)z * DMODEL * DMODEL;
    const __nv_bfloat16* Al = g_actL + (size_t)z * DMODEL * DMODEL;
    const __nv_bfloat16* Bh = g_WtH + (size_t)z * DMODEL * DMODEL;
    const __nv_bfloat16* Bl = g_WtL + (size_t)z * DMODEL * DMODEL;
    const float* bias = (z == 0) ? bq : (z == 1) ? bk : bv;
    __nv_bfloat16* OH = (z == 0) ? g_QH : (z == 1) ? g_KH : g_VH;
    __nv_bfloat16* OL = (z == 0) ? g_QL : (z == 1) ? g_KL : g_VL;
    float scale = (z == 0) ? 0.125f : 1.0f;
    mma_body<0>(Ah, Al, Bh, Bl, bias, OH, OL, nullptr, scale);
}

__global__ __launch_bounds__(256) void k_mma_out(const float* __restrict__ bo,
                                                 float* __restrict__ out) {
    mma_body<1>(g_attH, g_attL,
                g_WtH + (size_t)3 * DMODEL * DMODEL, g_WtL + (size_t)3 * DMODEL * DMODEL,
                bo, nullptr, nullptr, out, 1.0f);
}

// ---------------- tensor-core flash attention ----------------
// 128 threads (4 warps), q-block 64 (warp = m16 rows), k-blocks of 64.
// S = QhKh + QlKh + QhKl (Q pre-scaled); P/V hi/lo for PV. XOR-8 smem swizzle.
__global__ __launch_bounds__(128) void k_attn() {
    __shared__ __align__(1024) __nv_bfloat16 QsH[64 * 64], QsL[64 * 64];
    __shared__ __align__(1024) __nv_bfloat16 KsH[64 * 64], KsL[64 * 64];
    __shared__ __align__(1024) __nv_bfloat16 VsH[64 * 64], VsL[64 * 64];
    int b = blockIdx.z, h = blockIdx.y, q0 = blockIdx.x * 64;
    int tid = threadIdx.x, lane = tid & 31, wid = tid >> 5;
    size_t hb = (size_t)(b * NH + h) * SEQ * HDIM;
    const __nv_bfloat16 *QHp = g_QH + hb, *QLp = g_QL + hb;
    const __nv_bfloat16 *KHp = g_KH + hb, *KLp = g_KL + hb;
    const __nv_bfloat16 *VHp = g_VH + hb, *VLp = g_VL + hb;
    const float* Bg = g_bias + ((size_t)(b * NH + h) * SEQ + q0) * SEQ;
    uint32_t sQH = smem_u32(QsH), sQL = smem_u32(QsL);
    uint32_t sKH = smem_u32(KsH), sKL = smem_u32(KsL);
    uint32_t sVH = smem_u32(VsH), sVL = smem_u32(VsL);

    // load Q tile (hi/lo), swizzled rows of 8x16B chunks
#pragma unroll
    for (int u = 0; u < 4; u++) {
        int idx = u * 128 + tid;
        int row = idx >> 3, c = idx & 7, cs = c ^ (row & 7);
        size_t go = (size_t)(q0 + row) * HDIM + c * 8;
        cp_async16(sQH + row * 128 + cs * 16, QHp + go);
        cp_async16(sQL + row * 128 + cs * 16, QLp + go);
    }
    CP_COMMIT();
    CP_WAIT(0);
    __syncthreads();

    // Q fragments (A operand, m16 x k16 per kk)
    uint32_t qh[4][4], ql[4][4];
#pragma unroll
    for (int kk = 0; kk < 4; kk++) {
        int row = wid * 16 + (lane & 15);
        int c = kk * 2 + (lane >> 4), cs = c ^ (row & 7);
        ldsm_x4(qh[kk], sQH + row * 128 + cs * 16);
        ldsm_x4(ql[kk], sQL + row * 128 + cs * 16);
    }

    float o[8][4];
#pragma unroll
    for (int j = 0; j < 8; j++)
#pragma unroll
        for (int r = 0; r < 4; r++) o[j][r] = 0.f;
    float m0 = -1e30f, m1 = -1e30f, l0 = 0.f, l1 = 0.f;
    int br0 = wid * 16 + (lane >> 2);
    int bc = 2 * (lane & 3);

    for (int k0 = 0; k0 < SEQ; k0 += 64) {
        __syncthreads();   // prev iter's reads of K/V smem done
#pragma unroll
        for (int u = 0; u < 4; u++) {
            int idx = u * 128 + tid;
            int row = idx >> 3, c = idx & 7, cs = c ^ (row & 7);
            size_t go = (size_t)(k0 + row) * HDIM + c * 8;
            cp_async16(sKH + row * 128 + cs * 16, KHp + go);
            cp_async16(sKL + row * 128 + cs * 16, KLp + go);
            cp_async16(sVH + row * 128 + cs * 16, VHp + go);
            cp_async16(sVL + row * 128 + cs * 16, VLp + go);
        }
        CP_COMMIT();
        // prefetch bias fragments (hidden under cp.async wait)
        float2 bias0[8], bias1[8];
#pragma unroll
        for (int j = 0; j < 8; j++) {
            bias0[j] = *(const float2*)(Bg + (size_t)br0 * SEQ + k0 + j * 8 + bc);
            bias1[j] = *(const float2*)(Bg + (size_t)(br0 + 8) * SEQ + k0 + j * 8 + bc);
        }
        CP_WAIT(0);
        __syncthreads();

        // S tiles: 8 n-tiles (seq cols), 3-term mma
        float s[8][4];
#pragma unroll
        for (int j = 0; j < 8; j++) {
            s[j][0] = s[j][1] = s[j][2] = s[j][3] = 0.f;
#pragma unroll
            for (int kk = 0; kk < 4; kk++) {
                uint32_t kh[2], kl[2];
                int row = j * 8 + (lane & 7);
                int c = kk * 2 + ((lane >> 3) & 1), cs = c ^ (row & 7);
                ldsm_x2(kh, sKH + row * 128 + cs * 16);
                ldsm_x2(kl, sKL + row * 128 + cs * 16);
                mma16816(s[j], qh[kk], kh);
                mma16816(s[j], ql[kk], kh);
                mma16816(s[j], qh[kk], kl);
            }
        }

        // bias + online softmax (rows br0, br0+8; quad-lane reductions)
        float mx0 = m0, mx1 = m1;
#pragma unroll
        for (int j = 0; j < 8; j++) {
            s[j][0] += bias0[j].x; s[j][1] += bias0[j].y;
            s[j][2] += bias1[j].x; s[j][3] += bias1[j].y;
            mx0 = fmaxf(mx0, fmaxf(s[j][0], s[j][1]));
            mx1 = fmaxf(mx1, fmaxf(s[j][2], s[j][3]));
        }
        mx0 = fmaxf(mx0, __shfl_xor_sync(0xffffffffu, mx0, 1));
        mx0 = fmaxf(mx0, __shfl_xor_sync(0xffffffffu, mx0, 2));
        mx1 = fmaxf(mx1, __shfl_xor_sync(0xffffffffu, mx1, 1));
        mx1 = fmaxf(mx1, __shfl_xor_sync(0xffffffffu, mx1, 2));
        float corr0 = __expf(m0 - mx0), corr1 = __expf(m1 - mx1);
        m0 = mx0; m1 = mx1;
        float rs0 = 0.f, rs1 = 0.f;
#pragma unroll
        for (int j = 0; j < 8; j++) {
            s[j][0] = __expf(s[j][0] - m0);
            s[j][1] = __expf(s[j][1] - m0);
            s[j][2] = __expf(s[j][2] - m1);
            s[j][3] = __expf(s[j][3] - m1);
            rs0 += s[j][0] + s[j][1];
            rs1 += s[j][2] + s[j][3];
        }
        rs0 += __shfl_xor_sync(0xffffffffu, rs0, 1);
        rs0 += __shfl_xor_sync(0xffffffffu, rs0, 2);
        rs1 += __shfl_xor_sync(0xffffffffu, rs1, 1);
        rs1 += __shfl_xor_sync(0xffffffffu, rs1, 2);
        l0 = l0 * corr0 + rs0;
        l1 = l1 * corr1 + rs1;
#pragma unroll
        for (int j = 0; j < 8; j++) {
            o[j][0] *= corr0; o[j][1] *= corr0;
            o[j][2] *= corr1; o[j][3] *= corr1;
        }

        // P fragments (C layout == A layout): hi + residual lo
        uint32_t ph[4][4], pl[4][4];
#pragma unroll
        for (int kk = 0; kk < 4; kk++) {
            packhl(s[2 * kk][0], s[2 * kk][1], ph[kk][0], pl[kk][0]);
            packhl(s[2 * kk][2], s[2 * kk][3], ph[kk][1], pl[kk][1]);
            packhl(s[2 * kk + 1][0], s[2 * kk + 1][1], ph[kk][2], pl[kk][2]);
            packhl(s[2 * kk + 1][2], s[2 * kk + 1][3], ph[kk][3], pl[kk][3]);
        }

        // O += P @ V (3-term), V via ldmatrix.trans
#pragma unroll
        for (int kk = 0; kk < 4; kk++) {
#pragma unroll
            for (int j = 0; j < 8; j++) {
                uint32_t vh[2], vl[2];
                int row = kk * 16 + (lane & 15);
                int cs = j ^ (row & 7);
                ldsm_x2_trans(vh, sVH + row * 128 + cs * 16);
                ldsm_x2_trans(vl, sVL + row * 128 + cs * 16);
                mma16816(o[j], ph[kk], vh);
                mma16816(o[j], pl[kk], vh);
                mma16816(o[j], ph[kk], vl);
            }
        }
    }

    // epilogue: normalize, write bf16 hi/lo to [b*q][h*64+d]
    float rl0 = 1.f / l0, rl1 = 1.f / l1;
    int rq0 = q0 + br0;
#pragma unroll
    for (int j = 0; j < 8; j++) {
        size_t i0 = ((size_t)(b * SEQ + rq0) * NH + h) * HDIM + j * 8 + bc;
        size_t i1 = ((size_t)(b * SEQ + rq0 + 8) * NH + h) * HDIM + j * 8 + bc;
        uint32_t hh, ll;
        packhl(o[j][0] * rl0, o[j][1] * rl0, hh, ll);
        *(uint32_t*)(g_attH + i0) = hh;
        *(uint32_t*)(g_attL + i0) = ll;
        packhl(o[j][2] * rl1, o[j][3] * rl1, hh, ll);
        *(uint32_t*)(g_attH + i1) = hh;
        *(uint32_t*)(g_attL + i1) = ll;
    }
}

// ---------------- launch ----------------
extern "C" void kernel_launch(void* const* d_in, const int* in_sizes, int n_in,
                              void* d_out, int out_size) {
    (void)in_sizes; (void)n_in; (void)out_size;
    const float* query = (const float*)d_in[0];
    const float* key   = (const float*)d_in[1];
    const float* value = (const float*)d_in[2];
    const float* qx    = (const float*)d_in[3];
    const float* qy    = (const float*)d_in[4];
    const float* kx    = (const float*)d_in[5];
    const float* ky    = (const float*)d_in[6];
    const float* Wq    = (const float*)d_in[7];
    const float* bq    = (const float*)d_in[8];
    const float* Wk    = (const float*)d_in[9];
    const float* bk    = (const float*)d_in[10];
    const float* Wv    = (const float*)d_in[11];
    const float* bv    = (const float*)d_in[12];
    const float* Wo    = (const float*)d_in[13];
    const float* bo    = (const float*)d_in[14];
    const float* xt    = (const float*)d_in[15];
    const float* yt    = (const float*)d_in[16];
    const float* Wb    = (const float*)d_in[17];
    const float* bb    = (const float*)d_in[18];
    float* out = (float*)d_out;

    k_project<<<(2 * NEMB * NH + 255) / 256, 256>>>(xt, yt, Wb);
    k_bias<<<dim3(SEQ / 16, SEQ / 16, NB), 256>>>(qx, qy, kx, ky, bb);
    k_convA<<<dim3(DMODEL * DMODEL / 4 / 256, 1, 3), 256>>>(query, key, value);
    k_convW<<<dim3(32, 32, 4), dim3(32, 8)>>>(Wq, Wk, Wv, Wo);
    k_mma_qkv<<<dim3(8, 8, 3), 256>>>(bq, bk, bv);
    k_attn<<<dim3(SEQ / 64, NH, NB), 128>>>();
    k_mma_out<<<dim3(8, 8), 256>>>(bo, out);
}

// round 6
// speedup vs baseline: 1.1794x; 1.0012x over previous
#include <cuda_runtime.h>
#include <cuda_bf16.h>
#include <cuda_fp16.h>
#include <cstdint>

#define NH     16
#define DMODEL 1024
#define HDIM   64
#define NEMB   40001
#define NB     2
#define SEQ    512

// ---------------- device scratch ----------------
__device__ float g_Tx[NEMB * NH];
__device__ float g_Ty[NEMB * NH];
__device__ __half g_bias[(size_t)NB * NH * SEQ * SEQ];   // fp16 bias (16.7MB)

// bf16 hi/lo split operands
__device__ __nv_bfloat16 g_actH[3 * DMODEL * DMODEL];   // q,k,v activations [m][k]
__device__ __nv_bfloat16 g_actL[3 * DMODEL * DMODEL];
__device__ __nv_bfloat16 g_WtH[4 * DMODEL * DMODEL];    // Wq,Wk,Wv,Wo transposed [n][k]
__device__ __nv_bfloat16 g_WtL[4 * DMODEL * DMODEL];
// projected Q/K/V in [b][h][seq][d], bf16 hi/lo (Q pre-scaled by 0.125)
__device__ __nv_bfloat16 g_QH[NB * NH * SEQ * HDIM], g_QL[NB * NH * SEQ * HDIM];
__device__ __nv_bfloat16 g_KH[NB * NH * SEQ * HDIM], g_KL[NB * NH * SEQ * HDIM];
__device__ __nv_bfloat16 g_VH[NB * NH * SEQ * HDIM], g_VL[NB * NH * SEQ * HDIM];
// attention output hi/lo, [b*q][h*64+d] row-major 1024x1024
__device__ __nv_bfloat16 g_attH[DMODEL * DMODEL];
__device__ __nv_bfloat16 g_attL[DMODEL * DMODEL];

// ---------------- non-gated PTX helpers ----------------
__device__ __forceinline__ uint32_t smem_u32(const void* p) {
    uint32_t a;
    asm("{ .reg .u64 t; cvta.to.shared.u64 t, %1; cvt.u32.u64 %0, t; }" : "=r"(a) : "l"(p));
    return a;
}
__device__ __forceinline__ void cp_async16(uint32_t saddr, const void* gptr) {
    asm volatile("cp.async.cg.shared.global [%0], [%1], 16;" :: "r"(saddr), "l"(gptr) : "memory");
}
#define CP_COMMIT() asm volatile("cp.async.commit_group;" ::: "memory")
#define CP_WAIT(n)  asm volatile("cp.async.wait_group %0;" :: "n"(n) : "memory")

__device__ __forceinline__ void ldsm_x4(uint32_t* r, uint32_t addr) {
    asm volatile("ldmatrix.sync.aligned.m8n8.x4.shared.b16 {%0,%1,%2,%3}, [%4];"
                 : "=r"(r[0]), "=r"(r[1]), "=r"(r[2]), "=r"(r[3]) : "r"(addr));
}
__device__ __forceinline__ void ldsm_x2(uint32_t* r, uint32_t addr) {
    asm volatile("ldmatrix.sync.aligned.m8n8.x2.shared.b16 {%0,%1}, [%2];"
                 : "=r"(r[0]), "=r"(r[1]) : "r"(addr));
}
__device__ __forceinline__ void ldsm_x2_trans(uint32_t* r, uint32_t addr) {
    asm volatile("ldmatrix.sync.aligned.m8n8.x2.trans.shared.b16 {%0,%1}, [%2];"
                 : "=r"(r[0]), "=r"(r[1]) : "r"(addr));
}
__device__ __forceinline__ void mma16816(float* d, const uint32_t* a, const uint32_t* b) {
    asm volatile("mma.sync.aligned.m16n8k16.row.col.f32.bf16.bf16.f32 "
                 "{%0,%1,%2,%3}, {%4,%5,%6,%7}, {%8,%9}, {%0,%1,%2,%3};"
                 : "+f"(d[0]), "+f"(d[1]), "+f"(d[2]), "+f"(d[3])
                 : "r"(a[0]), "r"(a[1]), "r"(a[2]), "r"(a[3]), "r"(b[0]), "r"(b[1]));
}
// pack two floats into bf16x2 hi part + bf16x2 residual part
__device__ __forceinline__ void packhl(float a, float b, uint32_t& hh, uint32_t& ll) {
    __nv_bfloat162 h2 = __floats2bfloat162_rn(a, b);
    float ra = a - __bfloat162float(__low2bfloat16(h2));
    float rb = b - __bfloat162float(__high2bfloat16(h2));
    __nv_bfloat162 l2 = __floats2bfloat162_rn(ra, rb);
    hh = *reinterpret_cast<uint32_t*>(&h2);
    ll = *reinterpret_cast<uint32_t*>(&l2);
}

// ---------------- kernel 1: project embedding tables through Wb ----------------
__global__ __launch_bounds__(256) void k_project(const float* __restrict__ xt,
                                                 const float* __restrict__ yt,
                                                 const float* __restrict__ Wb) {
    int id = blockIdx.x * 256 + threadIdx.x;
    if (id >= 2 * NEMB * NH) return;
    int which = (id >= NEMB * NH);
    int rid = which ? id - NEMB * NH : id;
    int r = rid >> 4, h = rid & 15;
    const float4* row = (const float4*)((which ? yt : xt) + (size_t)r * 256 + h * 16);
    const float4* wb = (const float4*)Wb;
    float s = 0.f;
#pragma unroll
    for (int q = 0; q < 4; q++) {
        float4 v = row[q], w = wb[q];
        s += v.x * w.x + v.y * w.y + v.z * w.z + v.w * w.w;
    }
    (which ? g_Ty : g_Tx)[rid] = s;
}

// ---------------- kernel 2: positional bias (fp16 output) ----------------
__global__ __launch_bounds__(256) void k_bias(const float* __restrict__ qx,
                                              const float* __restrict__ qy,
                                              const float* __restrict__ kx,
                                              const float* __restrict__ ky,
                                              const float* __restrict__ bbp) {
    __shared__ float sm[16 * 256];
    int b = blockIdx.z;
    int i0 = blockIdx.y * 16, j0 = blockIdx.x * 16;
    int t = threadIdx.x;
    int i = i0 + (t >> 4), j = j0 + (t & 15);
    float bb = bbp[0];
    float dx = qx[b * SEQ + j] - kx[b * SEQ + i];
    float dy = qy[b * SEQ + j] - ky[b * SEQ + i];
    dx = fminf(fmaxf(dx, -1000.f), 1000.f);
    dy = fminf(fmaxf(dy, -1000.f), 1000.f);
    int ix = (int)rintf((dx + 1000.f) * 20.f);
    int iy = (int)rintf((dy + 1000.f) * 20.f);
    const float4* px = (const float4*)(g_Tx + (size_t)ix * 16);
    const float4* py = (const float4*)(g_Ty + (size_t)iy * 16);
#pragma unroll
    for (int q = 0; q < 4; q++) {
        float4 a = px[q], c = py[q];
        float v0 = a.x + c.x + bb, v1 = a.y + c.y + bb;
        float v2 = a.z + c.z + bb, v3 = a.w + c.w + bb;
        sm[(q * 4 + 0) * 256 + t] = 1.f / (1.f + __expf(-v0));
        sm[(q * 4 + 1) * 256 + t] = 1.f / (1.f + __expf(-v1));
        sm[(q * 4 + 2) * 256 + t] = 1.f / (1.f + __expf(-v2));
        sm[(q * 4 + 3) * 256 + t] = 1.f / (1.f + __expf(-v3));
    }
    __syncthreads();
    int h = t >> 4, w = t & 15;
#pragma unroll
    for (int ii = 0; ii < 16; ii++) {
        g_bias[(((size_t)(b * NH + h)) * SEQ + (i0 + ii)) * SEQ + (j0 + w)] =
            __float2half(sm[h * 256 + ii * 16 + w]);
    }
}

// ---------------- bf16 hi/lo split helpers ----------------
__device__ __forceinline__ void split4(float4 x, __nv_bfloat162* ph, __nv_bfloat162* pl) {
    __nv_bfloat162 h01 = __floats2bfloat162_rn(x.x, x.y);
    __nv_bfloat162 h23 = __floats2bfloat162_rn(x.z, x.w);
    __nv_bfloat162 l01 = __floats2bfloat162_rn(x.x - __bfloat162float(__low2bfloat16(h01)),
                                               x.y - __bfloat162float(__high2bfloat16(h01)));
    __nv_bfloat162 l23 = __floats2bfloat162_rn(x.z - __bfloat162float(__low2bfloat16(h23)),
                                               x.w - __bfloat162float(__high2bfloat16(h23)));
    ph[0] = h01; ph[1] = h23; pl[0] = l01; pl[1] = l23;
}

__global__ __launch_bounds__(256) void k_convA(const float* __restrict__ q,
                                               const float* __restrict__ k,
                                               const float* __restrict__ v) {
    int z = blockIdx.z;
    const float* src = (z == 0) ? q : (z == 1) ? k : v;
    __nv_bfloat16* H = g_actH + (size_t)z * DMODEL * DMODEL;
    __nv_bfloat16* L = g_actL + (size_t)z * DMODEL * DMODEL;
    int i = blockIdx.x * 256 + threadIdx.x;
    float4 x = ((const float4*)src)[i];
    split4(x, (__nv_bfloat162*)(H + (size_t)i * 4), (__nv_bfloat162*)(L + (size_t)i * 4));
}

__global__ void k_convW(const float* __restrict__ Wq, const float* __restrict__ Wk,
                        const float* __restrict__ Wv, const float* __restrict__ Wo) {
    __shared__ float t[32][33];
    int z = blockIdx.z;
    const float* W = (z == 0) ? Wq : (z == 1) ? Wk : (z == 2) ? Wv : Wo;
    __nv_bfloat16* H = g_WtH + (size_t)z * DMODEL * DMODEL;
    __nv_bfloat16* L = g_WtL + (size_t)z * DMODEL * DMODEL;
    int nb = blockIdx.x * 32, kb = blockIdx.y * 32;
    int tx = threadIdx.x, ty = threadIdx.y;  // 32 x 8
#pragma unroll
    for (int i = 0; i < 4; i++)
        t[ty + i * 8][tx] = W[(size_t)(kb + ty + i * 8) * DMODEL + nb + tx];
    __syncthreads();
#pragma unroll
    for (int i = 0; i < 4; i++) {
        int n = nb + ty + i * 8, k = kb + tx;
        float v = t[tx][ty + i * 8];
        __nv_bfloat16 h = __float2bfloat16(v);
        H[(size_t)n * DMODEL + k] = h;
        L[(size_t)n * DMODEL + k] = __float2bfloat16(v - __bfloat162float(h));
    }
}

// ---------------- warp-mma GEMM: C = A @ Wt^T + bias ----------------
// 3-term hi/lo split folded into one K=3072 GEMM (phases: AhBh, AlBh, AhBl).
// BM=BN=128, BK=32, 8 warps (2m x 4n), 3-stage cp.async pipeline, 1 sync/iter.
#define NKITER 96
#define STAGES 3

template <int MODE>
__device__ __forceinline__ void mma_body(const __nv_bfloat16* __restrict__ Ah,
                                         const __nv_bfloat16* __restrict__ Al,
                                         const __nv_bfloat16* __restrict__ Bh,
                                         const __nv_bfloat16* __restrict__ Bl,
                                         const float* __restrict__ bias,
                                         __nv_bfloat16* __restrict__ OH,
                                         __nv_bfloat16* __restrict__ OL,
                                         float* __restrict__ OF,
                                         float scale) {
    __shared__ __align__(1024) char smem[STAGES][16384];   // per stage: A 8KB | B 8KB
    int tid = threadIdx.x, lane = tid & 31, wid = tid >> 5;
    int wm = wid & 1, wn = wid >> 1;                  // 2 x 4 warp grid
    int m0 = blockIdx.y * 128, n0 = blockIdx.x * 128;
    uint32_t sbase = smem_u32(smem);

    float acc[4][4][4];
#pragma unroll
    for (int i = 0; i < 4; i++)
#pragma unroll
        for (int j = 0; j < 4; j++)
#pragma unroll
            for (int r = 0; r < 4; r++) acc[i][j][r] = 0.f;

    auto issue_tile = [&](int ki, int s) {
        int phase = ki >> 5;
        int kk = (ki & 31) * 32;
        const __nv_bfloat16* Ap = (phase == 1) ? Al : Ah;
        const __nv_bfloat16* Bp = (phase == 2) ? Bl : Bh;
        uint32_t sA = sbase + s * 16384, sB = sA + 8192;
#pragma unroll
        for (int j = 0; j < 2; j++) {
            int idx = tid + j * 256;                   // 512 chunks
            int row = idx >> 2, c = idx & 3;
            int cs = c ^ ((row >> 1) & 3);
            cp_async16(sA + row * 64 + cs * 16, Ap + (size_t)(m0 + row) * DMODEL + kk + c * 8);
            cp_async16(sB + row * 64 + cs * 16, Bp + (size_t)(n0 + row) * DMODEL + kk + c * 8);
        }
        CP_COMMIT();
    };

    issue_tile(0, 0);
    issue_tile(1, 1);
    for (int ki = 0; ki < NKITER; ki++) {
        int s = ki % STAGES;
        if (ki + 1 < NKITER) { CP_WAIT(1); } else { CP_WAIT(0); }
        __syncthreads();
        if (ki + 2 < NKITER) issue_tile(ki + 2, (ki + 2) % STAGES);
        uint32_t sA = sbase + s * 16384, sB = sA + 8192;
#pragma unroll
        for (int kq = 0; kq < 2; kq++) {
            uint32_t af[4][4], bf[4][2];
#pragma unroll
            for (int im = 0; im < 4; im++) {
                int row = wm * 64 + im * 16 + (lane & 15);
                int c = kq * 2 + (lane >> 4);
                int cs = c ^ ((row >> 1) & 3);
                ldsm_x4(af[im], sA + row * 64 + cs * 16);
            }
#pragma unroll
            for (int jn = 0; jn < 4; jn++) {
                int row = wn * 32 + jn * 8 + (lane & 7);
                int c = kq * 2 + ((lane >> 3) & 1);
                int cs = c ^ ((row >> 1) & 3);
                ldsm_x2(bf[jn], sB + row * 64 + cs * 16);
            }
#pragma unroll
            for (int im = 0; im < 4; im++)
#pragma unroll
                for (int jn = 0; jn < 4; jn++) mma16816(acc[im][jn], af[im], bf[jn]);
        }
    }

    // epilogue
#pragma unroll
    for (int im = 0; im < 4; im++) {
#pragma unroll
        for (int jn = 0; jn < 4; jn++) {
            int col = n0 + wn * 32 + jn * 8 + 2 * (lane & 3);
            float b0 = bias[col], b1 = bias[col + 1];
#pragma unroll
            for (int half = 0; half < 2; half++) {
                int m = m0 + wm * 64 + im * 16 + (lane >> 2) + half * 8;
                float v0 = (acc[im][jn][half * 2 + 0] + b0) * scale;
                float v1 = (acc[im][jn][half * 2 + 1] + b1) * scale;
                if (MODE == 0) {
                    int bidx = m >> 9, nseq = m & 511;
                    int h = col >> 6, d = col & 63;
                    size_t idx = (((size_t)(bidx * NH + h)) * SEQ + nseq) * HDIM + d;
                    uint32_t hh, ll;
                    packhl(v0, v1, hh, ll);
                    *(uint32_t*)(OH + idx) = hh;
                    *(uint32_t*)(OL + idx) = ll;
                } else {
                    *(float2*)(OF + (size_t)m * DMODEL + col) = make_float2(v0, v1);
                }
            }
        }
    }
}

__global__ __launch_bounds__(256) void k_mma_qkv(const float* __restrict__ bq,
                                                 const float* __restrict__ bk,
                                                 const float* __restrict__ bv) {
    int z = blockIdx.z;
    const __nv_bfloat16* Ah = g_actH + (size_t)z * DMODEL * DMODEL;
    const __nv_bfloat16* Al = g_actL + (size_t)z * DMODEL * DMODEL;
    const __nv_bfloat16* Bh = g_WtH + (size_t)z * DMODEL * DMODEL;
    const __nv_bfloat16* Bl = g_WtL + (size_t)z * DMODEL * DMODEL;
    const float* bias = (z == 0) ? bq : (z == 1) ? bk : bv;
    __nv_bfloat16* OH = (z == 0) ? g_QH : (z == 1) ? g_KH : g_VH;
    __nv_bfloat16* OL = (z == 0) ? g_QL : (z == 1) ? g_KL : g_VL;
    float scale = (z == 0) ? 0.125f : 1.0f;
    mma_body<0>(Ah, Al, Bh, Bl, bias, OH, OL, nullptr, scale);
}

__global__ __launch_bounds__(256) void k_mma_out(const float* __restrict__ bo,
                                                 float* __restrict__ out) {
    mma_body<1>(g_attH, g_attL,
                g_WtH + (size_t)3 * DMODEL * DMODEL, g_WtL + (size_t)3 * DMODEL * DMODEL,
                bo, nullptr, nullptr, out, 1.0f);
}

// ---------------- tensor-core flash attention, 8 warps ----------------
// 256 threads. q-block 64. Warp w: q-rows (w&3)*16..+16, column half g=w>>2
// (cols k0+32g .. k0+32g+32 of each 64-wide k-block). K/V smem shared by both
// groups; partial (m,l,o) merged at the end via smem.
__global__ __launch_bounds__(256) void k_attn() {
    __shared__ __align__(1024) char smbuf[49152];
    uint32_t sQH = smem_u32(smbuf), sQL = sQH + 8192;
    uint32_t sKH = sQH + 16384, sKL = sQH + 24576;
    uint32_t sVH = sQH + 32768, sVL = sQH + 40960;
    int b = blockIdx.z, h = blockIdx.y, q0 = blockIdx.x * 64;
    int tid = threadIdx.x, lane = tid & 31, wid = tid >> 5;
    int wq = wid & 3, g = wid >> 2;
    size_t hb = (size_t)(b * NH + h) * SEQ * HDIM;
    const __nv_bfloat16 *QHp = g_QH + hb, *QLp = g_QL + hb;
    const __nv_bfloat16 *KHp = g_KH + hb, *KLp = g_KL + hb;
    const __nv_bfloat16 *VHp = g_VH + hb, *VLp = g_VL + hb;
    const __half* Bg = g_bias + ((size_t)(b * NH + h) * SEQ + q0) * SEQ;

    // load Q tile (hi/lo), swizzled rows of 8x16B chunks
#pragma unroll
    for (int u = 0; u < 2; u++) {
        int idx = u * 256 + tid;
        int row = idx >> 3, c = idx & 7, cs = c ^ (row & 7);
        size_t go = (size_t)(q0 + row) * HDIM + c * 8;
        cp_async16(sQH + row * 128 + cs * 16, QHp + go);
        cp_async16(sQL + row * 128 + cs * 16, QLp + go);
    }
    CP_COMMIT();
    CP_WAIT(0);
    __syncthreads();

    // Q fragments (A operand, m16 x k16 per kk)
    uint32_t qh[4][4], ql[4][4];
#pragma unroll
    for (int kk = 0; kk < 4; kk++) {
        int row = wq * 16 + (lane & 15);
        int c = kk * 2 + (lane >> 4), cs = c ^ (row & 7);
        ldsm_x4(qh[kk], sQH + row * 128 + cs * 16);
        ldsm_x4(ql[kk], sQL + row * 128 + cs * 16);
    }

    float o[8][4];
#pragma unroll
    for (int j = 0; j < 8; j++)
#pragma unroll
        for (int r = 0; r < 4; r++) o[j][r] = 0.f;
    float mA = -1e30f, mB = -1e30f, lA = 0.f, lB = 0.f;
    int br0 = wq * 16 + (lane >> 2);
    int bc = 2 * (lane & 3);
    int goff = g * 32;

    for (int k0 = 0; k0 < SEQ; k0 += 64) {
        __syncthreads();   // prev iter's reads of K/V smem done
#pragma unroll
        for (int u = 0; u < 2; u++) {
            int idx = u * 256 + tid;
            int row = idx >> 3, c = idx & 7, cs = c ^ (row & 7);
            size_t go = (size_t)(k0 + row) * HDIM + c * 8;
            cp_async16(sKH + row * 128 + cs * 16, KHp + go);
            cp_async16(sKL + row * 128 + cs * 16, KLp + go);
            cp_async16(sVH + row * 128 + cs * 16, VHp + go);
            cp_async16(sVL + row * 128 + cs * 16, VLp + go);
        }
        CP_COMMIT();
        // prefetch bias fragments (fp16, hidden under cp.async wait)
        float2 bias0[4], bias1[4];
#pragma unroll
        for (int jt = 0; jt < 4; jt++) {
            __half2 t0 = *(const __half2*)(Bg + (size_t)br0 * SEQ + k0 + goff + jt * 8 + bc);
            __half2 t1 = *(const __half2*)(Bg + (size_t)(br0 + 8) * SEQ + k0 + goff + jt * 8 + bc);
            bias0[jt] = __half22float2(t0);
            bias1[jt] = __half22float2(t1);
        }
        CP_WAIT(0);
        __syncthreads();

        // S tiles: 4 n-tiles (this group's 32 cols), 3-term mma
        float s[4][4];
#pragma unroll
        for (int jt = 0; jt < 4; jt++) {
            s[jt][0] = s[jt][1] = s[jt][2] = s[jt][3] = 0.f;
#pragma unroll
            for (int kk = 0; kk < 4; kk++) {
                uint32_t kh[2], kl[2];
                int row = goff + jt * 8 + (lane & 7);
                int c = kk * 2 + ((lane >> 3) & 1), cs = c ^ (row & 7);
                ldsm_x2(kh, sKH + row * 128 + cs * 16);
                ldsm_x2(kl, sKL + row * 128 + cs * 16);
                mma16816(s[jt], qh[kk], kh);
                mma16816(s[jt], ql[kk], kh);
                mma16816(s[jt], qh[kk], kl);
            }
        }

        // bias + online softmax over this group's 32 columns
        float mx0 = mA, mx1 = mB;
#pragma unroll
        for (int jt = 0; jt < 4; jt++) {
            s[jt][0] += bias0[jt].x; s[jt][1] += bias0[jt].y;
            s[jt][2] += bias1[jt].x; s[jt][3] += bias1[jt].y;
            mx0 = fmaxf(mx0, fmaxf(s[jt][0], s[jt][1]));
            mx1 = fmaxf(mx1, fmaxf(s[jt][2], s[jt][3]));
        }
        mx0 = fmaxf(mx0, __shfl_xor_sync(0xffffffffu, mx0, 1));
        mx0 = fmaxf(mx0, __shfl_xor_sync(0xffffffffu, mx0, 2));
        mx1 = fmaxf(mx1, __shfl_xor_sync(0xffffffffu, mx1, 1));
        mx1 = fmaxf(mx1, __shfl_xor_sync(0xffffffffu, mx1, 2));
        float corr0 = __expf(mA - mx0), corr1 = __expf(mB - mx1);
        mA = mx0; mB = mx1;
        float rs0 = 0.f, rs1 = 0.f;
#pragma unroll
        for (int jt = 0; jt < 4; jt++) {
            s[jt][0] = __expf(s[jt][0] - mA);
            s[jt][1] = __expf(s[jt][1] - mA);
            s[jt][2] = __expf(s[jt][2] - mB);
            s[jt][3] = __expf(s[jt][3] - mB);
            rs0 += s[jt][0] + s[jt][1];
            rs1 += s[jt][2] + s[jt][3];
        }
        rs0 += __shfl_xor_sync(0xffffffffu, rs0, 1);
        rs0 += __shfl_xor_sync(0xffffffffu, rs0, 2);
        rs1 += __shfl_xor_sync(0xffffffffu, rs1, 1);
        rs1 += __shfl_xor_sync(0xffffffffu, rs1, 2);
        lA = lA * corr0 + rs0;
        lB = lB * corr1 + rs1;
#pragma unroll
        for (int j = 0; j < 8; j++) {
            o[j][0] *= corr0; o[j][1] *= corr0;
            o[j][2] *= corr1; o[j][3] *= corr1;
        }

        // P fragments (C layout == A layout): hi + residual lo, 2 k16 chunks
        uint32_t ph[2][4], pl[2][4];
#pragma unroll
        for (int kk = 0; kk < 2; kk++) {
            packhl(s[2 * kk][0], s[2 * kk][1], ph[kk][0], pl[kk][0]);
            packhl(s[2 * kk][2], s[2 * kk][3], ph[kk][1], pl[kk][1]);
            packhl(s[2 * kk + 1][0], s[2 * kk + 1][1], ph[kk][2], pl[kk][2]);
            packhl(s[2 * kk + 1][2], s[2 * kk + 1][3], ph[kk][3], pl[kk][3]);
        }

        // O += P @ V over this group's 32 k-rows (3-term), V via ldmatrix.trans
#pragma unroll
        for (int kk = 0; kk < 2; kk++) {
#pragma unroll
            for (int j = 0; j < 8; j++) {
                uint32_t vh[2], vl[2];
                int row = goff + kk * 16 + (lane & 15);
                int cs = j ^ (row & 7);
                ldsm_x2_trans(vh, sVH + row * 128 + cs * 16);
                ldsm_x2_trans(vl, sVL + row * 128 + cs * 16);
                mma16816(o[j], ph[kk], vh);
                mma16816(o[j], pl[kk], vh);
                mma16816(o[j], ph[kk], vl);
            }
        }
    }

    // merge group 1 into group 0 via smem, then write bf16 hi/lo
    float* scr = (float*)(smbuf + 16384);   // 64x64 f32 (over K region)
    float* sml = (float*)(smbuf + 32768);   // [row][m,l] pairs (over VsH)
    __syncthreads();
    if (g == 1) {
#pragma unroll
        for (int j = 0; j < 8; j++) {
            scr[br0 * 64 + j * 8 + bc] = o[j][0];
            scr[br0 * 64 + j * 8 + bc + 1] = o[j][1];
            scr[(br0 + 8) * 64 + j * 8 + bc] = o[j][2];
            scr[(br0 + 8) * 64 + j * 8 + bc + 1] = o[j][3];
        }
        if ((lane & 3) == 0) {
            sml[br0 * 2] = mA; sml[br0 * 2 + 1] = lA;
            sml[(br0 + 8) * 2] = mB; sml[(br0 + 8) * 2 + 1] = lB;
        }
    }
    __syncthreads();
    if (g == 0) {
        float m0p = sml[br0 * 2], l0p = sml[br0 * 2 + 1];
        float m1p = sml[(br0 + 8) * 2], l1p = sml[(br0 + 8) * 2 + 1];
        float M0 = fmaxf(mA, m0p), M1 = fmaxf(mB, m1p);
        float c0 = __expf(mA - M0), c0p = __expf(m0p - M0);
        float c1 = __expf(mB - M1), c1p = __expf(m1p - M1);
        float r0 = 1.f / (lA * c0 + l0p * c0p);
        float r1 = 1.f / (lB * c1 + l1p * c1p);
        int rq0 = q0 + br0;
#pragma unroll
        for (int j = 0; j < 8; j++) {
            float v0 = (o[j][0] * c0 + scr[br0 * 64 + j * 8 + bc] * c0p) * r0;
            float v1 = (o[j][1] * c0 + scr[br0 * 64 + j * 8 + bc + 1] * c0p) * r0;
            float v2 = (o[j][2] * c1 + scr[(br0 + 8) * 64 + j * 8 + bc] * c1p) * r1;
            float v3 = (o[j][3] * c1 + scr[(br0 + 8) * 64 + j * 8 + bc + 1] * c1p) * r1;
            size_t i0 = ((size_t)(b * SEQ + rq0) * NH + h) * HDIM + j * 8 + bc;
            size_t i1 = ((size_t)(b * SEQ + rq0 + 8) * NH + h) * HDIM + j * 8 + bc;
            uint32_t hh, ll;
            packhl(v0, v1, hh, ll);
            *(uint32_t*)(g_attH + i0) = hh;
            *(uint32_t*)(g_attL + i0) = ll;
            packhl(v2, v3, hh, ll);
            *(uint32_t*)(g_attH + i1) = hh;
            *(uint32_t*)(g_attL + i1) = ll;
        }
    }
}

// ---------------- launch ----------------
extern "C" void kernel_launch(void* const* d_in, const int* in_sizes, int n_in,
                              void* d_out, int out_size) {
    (void)in_sizes; (void)n_in; (void)out_size;
    const float* query = (const float*)d_in[0];
    const float* key   = (const float*)d_in[1];
    const float* value = (const float*)d_in[2];
    const float* qx    = (const float*)d_in[3];
    const float* qy    = (const float*)d_in[4];
    const float* kx    = (const float*)d_in[5];
    const float* ky    = (const float*)d_in[6];
    const float* Wq    = (const float*)d_in[7];
    const float* bq    = (const float*)d_in[8];
    const float* Wk    = (const float*)d_in[9];
    const float* bk    = (const float*)d_in[10];
    const float* Wv    = (const float*)d_in[11];
    const float* bv    = (const float*)d_in[12];
    const float* Wo    = (const float*)d_in[13];
    const float* bo    = (const float*)d_in[14];
    const float* xt    = (const float*)d_in[15];
    const float* yt    = (const float*)d_in[16];
    const float* Wb    = (const float*)d_in[17];
    const float* bb    = (const float*)d_in[18];
    float* out = (float*)d_out;

    k_project<<<(2 * NEMB * NH + 255) / 256, 256>>>(xt, yt, Wb);
    k_bias<<<dim3(SEQ / 16, SEQ / 16, NB), 256>>>(qx, qy, kx, ky, bb);
    k_convA<<<dim3(DMODEL * DMODEL / 4 / 256, 1, 3), 256>>>(query, key, value);
    k_convW<<<dim3(32, 32, 4), dim3(32, 8)>>>(Wq, Wk, Wv, Wo);
    k_mma_qkv<<<dim3(8, 8, 3), 256>>>(bq, bk, bv);
    k_attn<<<dim3(SEQ / 64, NH, NB), 256>>>();
    k_mma_out<<<dim3(8, 8), 256>>>(bo, out);
}

// round 7
// speedup vs baseline: 1.6079x; 1.3633x over previous
#include <cuda_runtime.h>
#include <cuda_fp16.h>
#include <cstdint>

#define NH     16
#define DMODEL 1024
#define HDIM   64
#define NEMB   40001
#define NB     2
#define SEQ    512

// ---------------- device scratch ----------------
__device__ float g_Tx[NEMB * NH];
__device__ float g_Ty[NEMB * NH];
__device__ __half g_bias[(size_t)NB * NH * SEQ * SEQ];   // fp16 bias (16.7MB)

// fp16 hi/lo split operands
__device__ __half g_actH[3 * DMODEL * DMODEL];   // q,k,v activations [m][k]
__device__ __half g_actL[3 * DMODEL * DMODEL];
__device__ __half g_WtH[4 * DMODEL * DMODEL];    // Wq,Wk,Wv,Wo transposed [n][k] (hi only)
// projected Q/K/V in [b][h][seq][d], fp16 hi/lo (Q pre-scaled by 0.125)
__device__ __half g_QH[NB * NH * SEQ * HDIM], g_QL[NB * NH * SEQ * HDIM];
__device__ __half g_KH[NB * NH * SEQ * HDIM], g_KL[NB * NH * SEQ * HDIM];
__device__ __half g_VH[NB * NH * SEQ * HDIM];
// attention output hi/lo, [b*q][h*64+d] row-major 1024x1024
__device__ __half g_attH[DMODEL * DMODEL];
__device__ __half g_attL[DMODEL * DMODEL];

// ---------------- non-gated PTX helpers ----------------
__device__ __forceinline__ uint32_t smem_u32(const void* p) {
    uint32_t a;
    asm("{ .reg .u64 t; cvta.to.shared.u64 t, %1; cvt.u32.u64 %0, t; }" : "=r"(a) : "l"(p));
    return a;
}
__device__ __forceinline__ void cp_async16(uint32_t saddr, const void* gptr) {
    asm volatile("cp.async.cg.shared.global [%0], [%1], 16;" :: "r"(saddr), "l"(gptr) : "memory");
}
#define CP_COMMIT() asm volatile("cp.async.commit_group;" ::: "memory")
#define CP_WAIT(n)  asm volatile("cp.async.wait_group %0;" :: "n"(n) : "memory")

__device__ __forceinline__ void ldsm_x4(uint32_t* r, uint32_t addr) {
    asm volatile("ldmatrix.sync.aligned.m8n8.x4.shared.b16 {%0,%1,%2,%3}, [%4];"
                 : "=r"(r[0]), "=r"(r[1]), "=r"(r[2]), "=r"(r[3]) : "r"(addr));
}
__device__ __forceinline__ void ldsm_x2(uint32_t* r, uint32_t addr) {
    asm volatile("ldmatrix.sync.aligned.m8n8.x2.shared.b16 {%0,%1}, [%2];"
                 : "=r"(r[0]), "=r"(r[1]) : "r"(addr));
}
__device__ __forceinline__ void ldsm_x2_trans(uint32_t* r, uint32_t addr) {
    asm volatile("ldmatrix.sync.aligned.m8n8.x2.trans.shared.b16 {%0,%1}, [%2];"
                 : "=r"(r[0]), "=r"(r[1]) : "r"(addr));
}
__device__ __forceinline__ void mma16816(float* d, const uint32_t* a, const uint32_t* b) {
    asm volatile("mma.sync.aligned.m16n8k16.row.col.f32.f16.f16.f32 "
                 "{%0,%1,%2,%3}, {%4,%5,%6,%7}, {%8,%9}, {%0,%1,%2,%3};"
                 : "+f"(d[0]), "+f"(d[1]), "+f"(d[2]), "+f"(d[3])
                 : "r"(a[0]), "r"(a[1]), "r"(a[2]), "r"(a[3]), "r"(b[0]), "r"(b[1]));
}
// pack two floats into fp16x2 hi part + fp16x2 residual part
__device__ __forceinline__ void packhl(float a, float b, uint32_t& hh, uint32_t& ll) {
    __half2 h2 = __floats2half2_rn(a, b);
    float2 f = __half22float2(h2);
    __half2 l2 = __floats2half2_rn(a - f.x, b - f.y);
    hh = *reinterpret_cast<uint32_t*>(&h2);
    ll = *reinterpret_cast<uint32_t*>(&l2);
}

// ---------------- kernel 1: project embedding tables through Wb ----------------
__global__ __launch_bounds__(256) void k_project(const float* __restrict__ xt,
                                                 const float* __restrict__ yt,
                                                 const float* __restrict__ Wb) {
    int id = blockIdx.x * 256 + threadIdx.x;
    if (id >= 2 * NEMB * NH) return;
    int which = (id >= NEMB * NH);
    int rid = which ? id - NEMB * NH : id;
    int r = rid >> 4, h = rid & 15;
    const float4* row = (const float4*)((which ? yt : xt) + (size_t)r * 256 + h * 16);
    const float4* wb = (const float4*)Wb;
    float s = 0.f;
#pragma unroll
    for (int q = 0; q < 4; q++) {
        float4 v = row[q], w = wb[q];
        s += v.x * w.x + v.y * w.y + v.z * w.z + v.w * w.w;
    }
    (which ? g_Ty : g_Tx)[rid] = s;
}

// ---------------- kernel 2: positional bias (fp16 output) ----------------
__global__ __launch_bounds__(256) void k_bias(const float* __restrict__ qx,
                                              const float* __restrict__ qy,
                                              const float* __restrict__ kx,
                                              const float* __restrict__ ky,
                                              const float* __restrict__ bbp) {
    __shared__ float sm[16 * 256];
    int b = blockIdx.z;
    int i0 = blockIdx.y * 16, j0 = blockIdx.x * 16;
    int t = threadIdx.x;
    int i = i0 + (t >> 4), j = j0 + (t & 15);
    float bb = bbp[0];
    float dx = qx[b * SEQ + j] - kx[b * SEQ + i];
    float dy = qy[b * SEQ + j] - ky[b * SEQ + i];
    dx = fminf(fmaxf(dx, -1000.f), 1000.f);
    dy = fminf(fmaxf(dy, -1000.f), 1000.f);
    int ix = (int)rintf((dx + 1000.f) * 20.f);
    int iy = (int)rintf((dy + 1000.f) * 20.f);
    const float4* px = (const float4*)(g_Tx + (size_t)ix * 16);
    const float4* py = (const float4*)(g_Ty + (size_t)iy * 16);
#pragma unroll
    for (int q = 0; q < 4; q++) {
        float4 a = px[q], c = py[q];
        float v0 = a.x + c.x + bb, v1 = a.y + c.y + bb;
        float v2 = a.z + c.z + bb, v3 = a.w + c.w + bb;
        sm[(q * 4 + 0) * 256 + t] = 1.f / (1.f + __expf(-v0));
        sm[(q * 4 + 1) * 256 + t] = 1.f / (1.f + __expf(-v1));
        sm[(q * 4 + 2) * 256 + t] = 1.f / (1.f + __expf(-v2));
        sm[(q * 4 + 3) * 256 + t] = 1.f / (1.f + __expf(-v3));
    }
    __syncthreads();
    int h = t >> 4, w = t & 15;
#pragma unroll
    for (int ii = 0; ii < 16; ii++) {
        g_bias[(((size_t)(b * NH + h)) * SEQ + (i0 + ii)) * SEQ + (j0 + w)] =
            __float2half(sm[h * 256 + ii * 16 + w]);
    }
}

// ---------------- fp16 hi/lo split helpers ----------------
__device__ __forceinline__ void split4h(float4 x, __half2* ph, __half2* pl) {
    __half2 h01 = __floats2half2_rn(x.x, x.y);
    __half2 h23 = __floats2half2_rn(x.z, x.w);
    float2 f01 = __half22float2(h01), f23 = __half22float2(h23);
    ph[0] = h01; ph[1] = h23;
    pl[0] = __floats2half2_rn(x.x - f01.x, x.y - f01.y);
    pl[1] = __floats2half2_rn(x.z - f23.x, x.w - f23.y);
}

__global__ __launch_bounds__(256) void k_convA(const float* __restrict__ q,
                                               const float* __restrict__ k,
                                               const float* __restrict__ v) {
    int z = blockIdx.z;
    const float* src = (z == 0) ? q : (z == 1) ? k : v;
    __half* H = g_actH + (size_t)z * DMODEL * DMODEL;
    __half* L = g_actL + (size_t)z * DMODEL * DMODEL;
    int i = blockIdx.x * 256 + threadIdx.x;
    float4 x = ((const float4*)src)[i];
    split4h(x, (__half2*)(H + (size_t)i * 4), (__half2*)(L + (size_t)i * 4));
}

__global__ void k_convW(const float* __restrict__ Wq, const float* __restrict__ Wk,
                        const float* __restrict__ Wv, const float* __restrict__ Wo) {
    __shared__ float t[32][33];
    int z = blockIdx.z;
    const float* W = (z == 0) ? Wq : (z == 1) ? Wk : (z == 2) ? Wv : Wo;
    __half* H = g_WtH + (size_t)z * DMODEL * DMODEL;
    int nb = blockIdx.x * 32, kb = blockIdx.y * 32;
    int tx = threadIdx.x, ty = threadIdx.y;  // 32 x 8
#pragma unroll
    for (int i = 0; i < 4; i++)
        t[ty + i * 8][tx] = W[(size_t)(kb + ty + i * 8) * DMODEL + nb + tx];
    __syncthreads();
#pragma unroll
    for (int i = 0; i < 4; i++) {
        int n = nb + ty + i * 8, k = kb + tx;
        H[(size_t)n * DMODEL + k] = __float2half(t[tx][ty + i * 8]);
    }
}

// ---------------- warp-mma GEMM: C = (Ah+Al) @ Bh^T + bias ----------------
// 2-term fp16 split folded into one K=2048 GEMM (phases: AhBh, AlBh).
// BM=BN=128, BK=32, 8 warps (2m x 4n), 3-stage cp.async pipeline.
#define NKITER 64
#define STAGES 3

template <int MODE>
__device__ __forceinline__ void mma_body(const __half* __restrict__ Ah,
                                         const __half* __restrict__ Al,
                                         const __half* __restrict__ Bh,
                                         const float* __restrict__ bias,
                                         __half* __restrict__ OH,
                                         __half* __restrict__ OL,
                                         float* __restrict__ OF,
                                         float scale) {
    __shared__ __align__(1024) char smem[STAGES][16384];   // per stage: A 8KB | B 8KB
    int tid = threadIdx.x, lane = tid & 31, wid = tid >> 5;
    int wm = wid & 1, wn = wid >> 1;                  // 2 x 4 warp grid
    int m0 = blockIdx.y * 128, n0 = blockIdx.x * 128;
    uint32_t sbase = smem_u32(smem);

    float acc[4][4][4];
#pragma unroll
    for (int i = 0; i < 4; i++)
#pragma unroll
        for (int j = 0; j < 4; j++)
#pragma unroll
            for (int r = 0; r < 4; r++) acc[i][j][r] = 0.f;

    auto issue_tile = [&](int ki, int s) {
        int phase = ki >> 5;
        int kk = (ki & 31) * 32;
        const __half* Ap = phase ? Al : Ah;
        uint32_t sA = sbase + s * 16384, sB = sA + 8192;
#pragma unroll
        for (int j = 0; j < 2; j++) {
            int idx = tid + j * 256;                   // 512 chunks
            int row = idx >> 2, c = idx & 3;
            int cs = c ^ ((row >> 1) & 3);
            cp_async16(sA + row * 64 + cs * 16, Ap + (size_t)(m0 + row) * DMODEL + kk + c * 8);
            cp_async16(sB + row * 64 + cs * 16, Bh + (size_t)(n0 + row) * DMODEL + kk + c * 8);
        }
        CP_COMMIT();
    };

    issue_tile(0, 0);
    issue_tile(1, 1);
    for (int ki = 0; ki < NKITER; ki++) {
        int s = ki % STAGES;
        if (ki + 1 < NKITER) { CP_WAIT(1); } else { CP_WAIT(0); }
        __syncthreads();
        if (ki + 2 < NKITER) issue_tile(ki + 2, (ki + 2) % STAGES);
        uint32_t sA = sbase + s * 16384, sB = sA + 8192;
#pragma unroll
        for (int kq = 0; kq < 2; kq++) {
            uint32_t af[4][4], bf[4][2];
#pragma unroll
            for (int im = 0; im < 4; im++) {
                int row = wm * 64 + im * 16 + (lane & 15);
                int c = kq * 2 + (lane >> 4);
                int cs = c ^ ((row >> 1) & 3);
                ldsm_x4(af[im], sA + row * 64 + cs * 16);
            }
#pragma unroll
            for (int jn = 0; jn < 4; jn++) {
                int row = wn * 32 + jn * 8 + (lane & 7);
                int c = kq * 2 + ((lane >> 3) & 1);
                int cs = c ^ ((row >> 1) & 3);
                ldsm_x2(bf[jn], sB + row * 64 + cs * 16);
            }
#pragma unroll
            for (int im = 0; im < 4; im++)
#pragma unroll
                for (int jn = 0; jn < 4; jn++) mma16816(acc[im][jn], af[im], bf[jn]);
        }
    }

    // epilogue
#pragma unroll
    for (int im = 0; im < 4; im++) {
#pragma unroll
        for (int jn = 0; jn < 4; jn++) {
            int col = n0 + wn * 32 + jn * 8 + 2 * (lane & 3);
            float b0 = bias[col], b1 = bias[col + 1];
#pragma unroll
            for (int half = 0; half < 2; half++) {
                int m = m0 + wm * 64 + im * 16 + (lane >> 2) + half * 8;
                float v0 = (acc[im][jn][half * 2 + 0] + b0) * scale;
                float v1 = (acc[im][jn][half * 2 + 1] + b1) * scale;
                if (MODE == 0) {
                    int bidx = m >> 9, nseq = m & 511;
                    int h = col >> 6, d = col & 63;
                    size_t idx = (((size_t)(bidx * NH + h)) * SEQ + nseq) * HDIM + d;
                    uint32_t hh, ll;
                    packhl(v0, v1, hh, ll);
                    *(uint32_t*)(OH + idx) = hh;
                    if (OL) *(uint32_t*)(OL + idx) = ll;
                } else {
                    *(float2*)(OF + (size_t)m * DMODEL + col) = make_float2(v0, v1);
                }
            }
        }
    }
}

__global__ __launch_bounds__(256) void k_mma_qkv(const float* __restrict__ bq,
                                                 const float* __restrict__ bk,
                                                 const float* __restrict__ bv) {
    int z = blockIdx.z;
    const __half* Ah = g_actH + (size_t)z * DMODEL * DMODEL;
    const __half* Al = g_actL + (size_t)z * DMODEL * DMODEL;
    const __half* Bh = g_WtH + (size_t)z * DMODEL * DMODEL;
    const float* bias = (z == 0) ? bq : (z == 1) ? bk : bv;
    __half* OH = (z == 0) ? g_QH : (z == 1) ? g_KH : g_VH;
    __half* OL = (z == 0) ? g_QL : (z == 1) ? g_KL : nullptr;   // V needs hi only
    float scale = (z == 0) ? 0.125f : 1.0f;
    mma_body<0>(Ah, Al, Bh, bias, OH, OL, nullptr, scale);
}

__global__ __launch_bounds__(256) void k_mma_out(const float* __restrict__ bo,
                                                 float* __restrict__ out) {
    mma_body<1>(g_attH, g_attL, g_WtH + (size_t)3 * DMODEL * DMODEL,
                bo, nullptr, nullptr, out, 1.0f);
}

// ---------------- tensor-core flash attention, 8 warps, fp16 ----------------
// 256 threads. q-block 64. Warp w: q-rows (w&3)*16..+16, column half g=w>>2.
// S = QhKh + QlKh + QhKl (3-term); PV = PhVh + PlVh (2-term, V hi only).
__global__ __launch_bounds__(256) void k_attn() {
    __shared__ __align__(1024) char smbuf[40960];
    uint32_t sQH = smem_u32(smbuf), sQL = sQH + 8192;
    uint32_t sKH = sQH + 16384, sKL = sQH + 24576;
    uint32_t sVH = sQH + 32768;
    int b = blockIdx.z, h = blockIdx.y, q0 = blockIdx.x * 64;
    int tid = threadIdx.x, lane = tid & 31, wid = tid >> 5;
    int wq = wid & 3, g = wid >> 2;
    size_t hb = (size_t)(b * NH + h) * SEQ * HDIM;
    const __half *QHp = g_QH + hb, *QLp = g_QL + hb;
    const __half *KHp = g_KH + hb, *KLp = g_KL + hb;
    const __half *VHp = g_VH + hb;
    const __half* Bg = g_bias + ((size_t)(b * NH + h) * SEQ + q0) * SEQ;

    // load Q tile (hi/lo), swizzled rows of 8x16B chunks
#pragma unroll
    for (int u = 0; u < 2; u++) {
        int idx = u * 256 + tid;
        int row = idx >> 3, c = idx & 7, cs = c ^ (row & 7);
        size_t go = (size_t)(q0 + row) * HDIM + c * 8;
        cp_async16(sQH + row * 128 + cs * 16, QHp + go);
        cp_async16(sQL + row * 128 + cs * 16, QLp + go);
    }
    CP_COMMIT();
    CP_WAIT(0);
    __syncthreads();

    // Q fragments (A operand, m16 x k16 per kk)
    uint32_t qh[4][4], ql[4][4];
#pragma unroll
    for (int kk = 0; kk < 4; kk++) {
        int row = wq * 16 + (lane & 15);
        int c = kk * 2 + (lane >> 4), cs = c ^ (row & 7);
        ldsm_x4(qh[kk], sQH + row * 128 + cs * 16);
        ldsm_x4(ql[kk], sQL + row * 128 + cs * 16);
    }

    float o[8][4];
#pragma unroll
    for (int j = 0; j < 8; j++)
#pragma unroll
        for (int r = 0; r < 4; r++) o[j][r] = 0.f;
    float mA = -1e30f, mB = -1e30f, lA = 0.f, lB = 0.f;
    int br0 = wq * 16 + (lane >> 2);
    int bc = 2 * (lane & 3);
    int goff = g * 32;

    for (int k0 = 0; k0 < SEQ; k0 += 64) {
        __syncthreads();   // prev iter's reads of K/V smem done
#pragma unroll
        for (int u = 0; u < 2; u++) {
            int idx = u * 256 + tid;
            int row = idx >> 3, c = idx & 7, cs = c ^ (row & 7);
            size_t go = (size_t)(k0 + row) * HDIM + c * 8;
            cp_async16(sKH + row * 128 + cs * 16, KHp + go);
            cp_async16(sKL + row * 128 + cs * 16, KLp + go);
            cp_async16(sVH + row * 128 + cs * 16, VHp + go);
        }
        CP_COMMIT();
        // prefetch bias fragments (fp16, hidden under cp.async wait)
        float2 bias0[4], bias1[4];
#pragma unroll
        for (int jt = 0; jt < 4; jt++) {
            __half2 t0 = *(const __half2*)(Bg + (size_t)br0 * SEQ + k0 + goff + jt * 8 + bc);
            __half2 t1 = *(const __half2*)(Bg + (size_t)(br0 + 8) * SEQ + k0 + goff + jt * 8 + bc);
            bias0[jt] = __half22float2(t0);
            bias1[jt] = __half22float2(t1);
        }
        CP_WAIT(0);
        __syncthreads();

        // S tiles: 4 n-tiles (this group's 32 cols), 3-term mma
        float s[4][4];
#pragma unroll
        for (int jt = 0; jt < 4; jt++) {
            s[jt][0] = s[jt][1] = s[jt][2] = s[jt][3] = 0.f;
#pragma unroll
            for (int kk = 0; kk < 4; kk++) {
                uint32_t kh[2], kl[2];
                int row = goff + jt * 8 + (lane & 7);
                int c = kk * 2 + ((lane >> 3) & 1), cs = c ^ (row & 7);
                ldsm_x2(kh, sKH + row * 128 + cs * 16);
                ldsm_x2(kl, sKL + row * 128 + cs * 16);
                mma16816(s[jt], qh[kk], kh);
                mma16816(s[jt], ql[kk], kh);
                mma16816(s[jt], qh[kk], kl);
            }
        }

        // bias + online softmax over this group's 32 columns
        float mx0 = mA, mx1 = mB;
#pragma unroll
        for (int jt = 0; jt < 4; jt++) {
            s[jt][0] += bias0[jt].x; s[jt][1] += bias0[jt].y;
            s[jt][2] += bias1[jt].x; s[jt][3] += bias1[jt].y;
            mx0 = fmaxf(mx0, fmaxf(s[jt][0], s[jt][1]));
            mx1 = fmaxf(mx1, fmaxf(s[jt][2], s[jt][3]));
        }
        mx0 = fmaxf(mx0, __shfl_xor_sync(0xffffffffu, mx0, 1));
        mx0 = fmaxf(mx0, __shfl_xor_sync(0xffffffffu, mx0, 2));
        mx1 = fmaxf(mx1, __shfl_xor_sync(0xffffffffu, mx1, 1));
        mx1 = fmaxf(mx1, __shfl_xor_sync(0xffffffffu, mx1, 2));
        float corr0 = __expf(mA - mx0), corr1 = __expf(mB - mx1);
        mA = mx0; mB = mx1;
        float rs0 = 0.f, rs1 = 0.f;
#pragma unroll
        for (int jt = 0; jt < 4; jt++) {
            s[jt][0] = __expf(s[jt][0] - mA);
            s[jt][1] = __expf(s[jt][1] - mA);
            s[jt][2] = __expf(s[jt][2] - mB);
            s[jt][3] = __expf(s[jt][3] - mB);
            rs0 += s[jt][0] + s[jt][1];
            rs1 += s[jt][2] + s[jt][3];
        }
        rs0 += __shfl_xor_sync(0xffffffffu, rs0, 1);
        rs0 += __shfl_xor_sync(0xffffffffu, rs0, 2);
        rs1 += __shfl_xor_sync(0xffffffffu, rs1, 1);
        rs1 += __shfl_xor_sync(0xffffffffu, rs1, 2);
        lA = lA * corr0 + rs0;
        lB = lB * corr1 + rs1;
#pragma unroll
        for (int j = 0; j < 8; j++) {
            o[j][0] *= corr0; o[j][1] *= corr0;
            o[j][2] *= corr1; o[j][3] *= corr1;
        }

        // P fragments (C layout == A layout): hi + residual lo, 2 k16 chunks
        uint32_t ph[2][4], pl[2][4];
#pragma unroll
        for (int kk = 0; kk < 2; kk++) {
            packhl(s[2 * kk][0], s[2 * kk][1], ph[kk][0], pl[kk][0]);
            packhl(s[2 * kk][2], s[2 * kk][3], ph[kk][1], pl[kk][1]);
            packhl(s[2 * kk + 1][0], s[2 * kk + 1][1], ph[kk][2], pl[kk][2]);
            packhl(s[2 * kk + 1][2], s[2 * kk + 1][3], ph[kk][3], pl[kk][3]);
        }

        // O += P @ V over this group's 32 k-rows (2-term), V via ldmatrix.trans
#pragma unroll
        for (int kk = 0; kk < 2; kk++) {
#pragma unroll
            for (int j = 0; j < 8; j++) {
                uint32_t vh[2];
                int row = goff + kk * 16 + (lane & 15);
                int cs = j ^ (row & 7);
                ldsm_x2_trans(vh, sVH + row * 128 + cs * 16);
                mma16816(o[j], ph[kk], vh);
                mma16816(o[j], pl[kk], vh);
            }
        }
    }

    // merge group 1 into group 0 via smem, then write fp16 hi/lo
    float* scr = (float*)(smbuf + 16384);   // 64x64 f32 (over K region)
    float* sml = (float*)(smbuf + 32768);   // [row][m,l] pairs (over VH)
    __syncthreads();
    if (g == 1) {
#pragma unroll
        for (int j = 0; j < 8; j++) {
            scr[br0 * 64 + j * 8 + bc] = o[j][0];
            scr[br0 * 64 + j * 8 + bc + 1] = o[j][1];
            scr[(br0 + 8) * 64 + j * 8 + bc] = o[j][2];
            scr[(br0 + 8) * 64 + j * 8 + bc + 1] = o[j][3];
        }
        if ((lane & 3) == 0) {
            sml[br0 * 2] = mA; sml[br0 * 2 + 1] = lA;
            sml[(br0 + 8) * 2] = mB; sml[(br0 + 8) * 2 + 1] = lB;
        }
    }
    __syncthreads();
    if (g == 0) {
        float m0p = sml[br0 * 2], l0p = sml[br0 * 2 + 1];
        float m1p = sml[(br0 + 8) * 2], l1p = sml[(br0 + 8) * 2 + 1];
        float M0 = fmaxf(mA, m0p), M1 = fmaxf(mB, m1p);
        float c0 = __expf(mA - M0), c0p = __expf(m0p - M0);
        float c1 = __expf(mB - M1), c1p = __expf(m1p - M1);
        float r0 = 1.f / (lA * c0 + l0p * c0p);
        float r1 = 1.f / (lB * c1 + l1p * c1p);
        int rq0 = q0 + br0;
#pragma unroll
        for (int j = 0; j < 8; j++) {
            float v0 = (o[j][0] * c0 + scr[br0 * 64 + j * 8 + bc] * c0p) * r0;
            float v1 = (o[j][1] * c0 + scr[br0 * 64 + j * 8 + bc + 1] * c0p) * r0;
            float v2 = (o[j][2] * c1 + scr[(br0 + 8) * 64 + j * 8 + bc] * c1p) * r1;
            float v3 = (o[j][3] * c1 + scr[(br0 + 8) * 64 + j * 8 + bc + 1] * c1p) * r1;
            size_t i0 = ((size_t)(b * SEQ + rq0) * NH + h) * HDIM + j * 8 + bc;
            size_t i1 = ((size_t)(b * SEQ + rq0 + 8) * NH + h) * HDIM + j * 8 + bc;
            uint32_t hh, ll;
            packhl(v0, v1, hh, ll);
            *(uint32_t*)(g_attH + i0) = hh;
            *(uint32_t*)(g_attL + i0) = ll;
            packhl(v2, v3, hh, ll);
            *(uint32_t*)(g_attH + i1) = hh;
            *(uint32_t*)(g_attL + i1) = ll;
        }
    }
}

// ---------------- launch ----------------
extern "C" void kernel_launch(void* const* d_in, const int* in_sizes, int n_in,
                              void* d_out, int out_size) {
    (void)in_sizes; (void)n_in; (void)out_size;
    const float* query = (const float*)d_in[0];
    const float* key   = (const float*)d_in[1];
    const float* value = (const float*)d_in[2];
    const float* qx    = (const float*)d_in[3];
    const float* qy    = (const float*)d_in[4];
    const float* kx    = (const float*)d_in[5];
    const float* ky    = (const float*)d_in[6];
    const float* Wq    = (const float*)d_in[7];
    const float* bq    = (const float*)d_in[8];
    const float* Wk    = (const float*)d_in[9];
    const float* bk    = (const float*)d_in[10];
    const float* Wv    = (const float*)d_in[11];
    const float* bv    = (const float*)d_in[12];
    const float* Wo    = (const float*)d_in[13];
    const float* bo    = (const float*)d_in[14];
    const float* xt    = (const float*)d_in[15];
    const float* yt    = (const float*)d_in[16];
    const float* Wb    = (const float*)d_in[17];
    const float* bb    = (const float*)d_in[18];
    float* out = (float*)d_out;

    k_project<<<(2 * NEMB * NH + 255) / 256, 256>>>(xt, yt, Wb);
    k_bias<<<dim3(SEQ / 16, SEQ / 16, NB), 256>>>(qx, qy, kx, ky, bb);
    k_convA<<<dim3(DMODEL * DMODEL / 4 / 256, 1, 3), 256>>>(query, key, value);
    k_convW<<<dim3(32, 32, 4), dim3(32, 8)>>>(Wq, Wk, Wv, Wo);
    k_mma_qkv<<<dim3(8, 8, 3), 256>>>(bq, bk, bv);
    k_attn<<<dim3(SEQ / 64, NH, NB), 256>>>();
    k_mma_out<<<dim3(8, 8), 256>>>(bo, out);
}

// round 8
// speedup vs baseline: 1.6429x; 1.0218x over previous
#include <cuda_runtime.h>
#include <cuda_fp16.h>
#include <cstdint>

#define NH     16
#define DMODEL 1024
#define HDIM   64
#define NEMB   40001
#define NB     2
#define SEQ    512

// ---------------- device scratch ----------------
__device__ float g_Tx[NEMB * NH];
__device__ float g_Ty[NEMB * NH];
__device__ __half g_bias[(size_t)NB * NH * SEQ * SEQ];   // fp16 bias (16.7MB)

// fp16 hi/lo split operands
__device__ __half g_actH[3 * DMODEL * DMODEL];   // q,k,v activations [m][k]
__device__ __half g_actL[3 * DMODEL * DMODEL];
__device__ __half g_WtH[4 * DMODEL * DMODEL];    // Wq,Wk,Wv,Wo transposed [n][k] (hi only)
// projected Q/K/V in [b][h][seq][d], fp16 hi/lo (Q pre-scaled by 0.125)
__device__ __half g_QH[NB * NH * SEQ * HDIM], g_QL[NB * NH * SEQ * HDIM];
__device__ __half g_KH[NB * NH * SEQ * HDIM], g_KL[NB * NH * SEQ * HDIM];
__device__ __half g_VH[NB * NH * SEQ * HDIM];
// attention output hi/lo, [b*q][h*64+d] row-major 1024x1024
__device__ __half g_attH[DMODEL * DMODEL];
__device__ __half g_attL[DMODEL * DMODEL];

// ---------------- non-gated PTX helpers ----------------
__device__ __forceinline__ uint32_t smem_u32(const void* p) {
    uint32_t a;
    asm("{ .reg .u64 t; cvta.to.shared.u64 t, %1; cvt.u32.u64 %0, t; }" : "=r"(a) : "l"(p));
    return a;
}
__device__ __forceinline__ void cp_async16(uint32_t saddr, const void* gptr) {
    asm volatile("cp.async.cg.shared.global [%0], [%1], 16;" :: "r"(saddr), "l"(gptr) : "memory");
}
#define CP_COMMIT() asm volatile("cp.async.commit_group;" ::: "memory")
#define CP_WAIT(n)  asm volatile("cp.async.wait_group %0;" :: "n"(n) : "memory")

__device__ __forceinline__ void ldsm_x4(uint32_t* r, uint32_t addr) {
    asm volatile("ldmatrix.sync.aligned.m8n8.x4.shared.b16 {%0,%1,%2,%3}, [%4];"
                 : "=r"(r[0]), "=r"(r[1]), "=r"(r[2]), "=r"(r[3]) : "r"(addr));
}
__device__ __forceinline__ void ldsm_x2(uint32_t* r, uint32_t addr) {
    asm volatile("ldmatrix.sync.aligned.m8n8.x2.shared.b16 {%0,%1}, [%2];"
                 : "=r"(r[0]), "=r"(r[1]) : "r"(addr));
}
__device__ __forceinline__ void ldsm_x2_trans(uint32_t* r, uint32_t addr) {
    asm volatile("ldmatrix.sync.aligned.m8n8.x2.trans.shared.b16 {%0,%1}, [%2];"
                 : "=r"(r[0]), "=r"(r[1]) : "r"(addr));
}
__device__ __forceinline__ void mma16816(float* d, const uint32_t* a, const uint32_t* b) {
    asm volatile("mma.sync.aligned.m16n8k16.row.col.f32.f16.f16.f32 "
                 "{%0,%1,%2,%3}, {%4,%5,%6,%7}, {%8,%9}, {%0,%1,%2,%3};"
                 : "+f"(d[0]), "+f"(d[1]), "+f"(d[2]), "+f"(d[3])
                 : "r"(a[0]), "r"(a[1]), "r"(a[2]), "r"(a[3]), "r"(b[0]), "r"(b[1]));
}
// pack two floats into fp16x2 hi part + fp16x2 residual part
__device__ __forceinline__ void packhl(float a, float b, uint32_t& hh, uint32_t& ll) {
    __half2 h2 = __floats2half2_rn(a, b);
    float2 f = __half22float2(h2);
    __half2 l2 = __floats2half2_rn(a - f.x, b - f.y);
    hh = *reinterpret_cast<uint32_t*>(&h2);
    ll = *reinterpret_cast<uint32_t*>(&l2);
}

// ---------------- kernel 1: project embedding tables through Wb ----------------
__global__ __launch_bounds__(256) void k_project(const float* __restrict__ xt,
                                                 const float* __restrict__ yt,
                                                 const float* __restrict__ Wb) {
    int id = blockIdx.x * 256 + threadIdx.x;
    if (id >= 2 * NEMB * NH) return;
    int which = (id >= NEMB * NH);
    int rid = which ? id - NEMB * NH : id;
    int r = rid >> 4, h = rid & 15;
    const float4* row = (const float4*)((which ? yt : xt) + (size_t)r * 256 + h * 16);
    const float4* wb = (const float4*)Wb;
    float s = 0.f;
#pragma unroll
    for (int q = 0; q < 4; q++) {
        float4 v = row[q], w = wb[q];
        s += v.x * w.x + v.y * w.y + v.z * w.z + v.w * w.w;
    }
    (which ? g_Ty : g_Tx)[rid] = s;
}

// ---------------- kernel 2: positional bias (fp16 output) ----------------
__global__ __launch_bounds__(256) void k_bias(const float* __restrict__ qx,
                                              const float* __restrict__ qy,
                                              const float* __restrict__ kx,
                                              const float* __restrict__ ky,
                                              const float* __restrict__ bbp) {
    __shared__ float sm[16 * 256];
    int b = blockIdx.z;
    int i0 = blockIdx.y * 16, j0 = blockIdx.x * 16;
    int t = threadIdx.x;
    int i = i0 + (t >> 4), j = j0 + (t & 15);
    float bb = bbp[0];
    float dx = qx[b * SEQ + j] - kx[b * SEQ + i];
    float dy = qy[b * SEQ + j] - ky[b * SEQ + i];
    dx = fminf(fmaxf(dx, -1000.f), 1000.f);
    dy = fminf(fmaxf(dy, -1000.f), 1000.f);
    int ix = (int)rintf((dx + 1000.f) * 20.f);
    int iy = (int)rintf((dy + 1000.f) * 20.f);
    const float4* px = (const float4*)(g_Tx + (size_t)ix * 16);
    const float4* py = (const float4*)(g_Ty + (size_t)iy * 16);
#pragma unroll
    for (int q = 0; q < 4; q++) {
        float4 a = px[q], c = py[q];
        float v0 = a.x + c.x + bb, v1 = a.y + c.y + bb;
        float v2 = a.z + c.z + bb, v3 = a.w + c.w + bb;
        sm[(q * 4 + 0) * 256 + t] = 1.f / (1.f + __expf(-v0));
        sm[(q * 4 + 1) * 256 + t] = 1.f / (1.f + __expf(-v1));
        sm[(q * 4 + 2) * 256 + t] = 1.f / (1.f + __expf(-v2));
        sm[(q * 4 + 3) * 256 + t] = 1.f / (1.f + __expf(-v3));
    }
    __syncthreads();
    int h = t >> 4, w = t & 15;
#pragma unroll
    for (int ii = 0; ii < 16; ii++) {
        g_bias[(((size_t)(b * NH + h)) * SEQ + (i0 + ii)) * SEQ + (j0 + w)] =
            __float2half(sm[h * 256 + ii * 16 + w]);
    }
}

// ---------------- fp16 hi/lo split helpers ----------------
__device__ __forceinline__ void split4h(float4 x, __half2* ph, __half2* pl) {
    __half2 h01 = __floats2half2_rn(x.x, x.y);
    __half2 h23 = __floats2half2_rn(x.z, x.w);
    float2 f01 = __half22float2(h01), f23 = __half22float2(h23);
    ph[0] = h01; ph[1] = h23;
    pl[0] = __floats2half2_rn(x.x - f01.x, x.y - f01.y);
    pl[1] = __floats2half2_rn(x.z - f23.x, x.w - f23.y);
}

__global__ __launch_bounds__(256) void k_convA(const float* __restrict__ q,
                                               const float* __restrict__ k,
                                               const float* __restrict__ v) {
    int z = blockIdx.z;
    const float* src = (z == 0) ? q : (z == 1) ? k : v;
    __half* H = g_actH + (size_t)z * DMODEL * DMODEL;
    __half* L = g_actL + (size_t)z * DMODEL * DMODEL;
    int i = blockIdx.x * 256 + threadIdx.x;
    float4 x = ((const float4*)src)[i];
    split4h(x, (__half2*)(H + (size_t)i * 4), (__half2*)(L + (size_t)i * 4));
}

__global__ void k_convW(const float* __restrict__ Wq, const float* __restrict__ Wk,
                        const float* __restrict__ Wv, const float* __restrict__ Wo) {
    __shared__ float t[32][33];
    int z = blockIdx.z;
    const float* W = (z == 0) ? Wq : (z == 1) ? Wk : (z == 2) ? Wv : Wo;
    __half* H = g_WtH + (size_t)z * DMODEL * DMODEL;
    int nb = blockIdx.x * 32, kb = blockIdx.y * 32;
    int tx = threadIdx.x, ty = threadIdx.y;  // 32 x 8
#pragma unroll
    for (int i = 0; i < 4; i++)
        t[ty + i * 8][tx] = W[(size_t)(kb + ty + i * 8) * DMODEL + nb + tx];
    __syncthreads();
#pragma unroll
    for (int i = 0; i < 4; i++) {
        int n = nb + ty + i * 8, k = kb + tx;
        H[(size_t)n * DMODEL + k] = __float2half(t[tx][ty + i * 8]);
    }
}

// ---------------- warp-mma GEMM: C = (Ah+Al) @ Bh^T + bias ----------------
// 2-term fp16 split folded into one K=2048 GEMM (phases: AhBh, AlBh).
// BM=BN=128, BK=32, 8 warps (2m x 4n), 3-stage cp.async pipeline.
#define NKITER 64
#define STAGES 3

template <int MODE>
__device__ __forceinline__ void mma_body(const __half* __restrict__ Ah,
                                         const __half* __restrict__ Al,
                                         const __half* __restrict__ Bh,
                                         const float* __restrict__ bias,
                                         __half* __restrict__ OH,
                                         __half* __restrict__ OL,
                                         float* __restrict__ OF,
                                         float scale) {
    __shared__ __align__(1024) char smem[STAGES][16384];   // per stage: A 8KB | B 8KB
    int tid = threadIdx.x, lane = tid & 31, wid = tid >> 5;
    int wm = wid & 1, wn = wid >> 1;                  // 2 x 4 warp grid
    int m0 = blockIdx.y * 128, n0 = blockIdx.x * 128;
    uint32_t sbase = smem_u32(smem);

    float acc[4][4][4];
#pragma unroll
    for (int i = 0; i < 4; i++)
#pragma unroll
        for (int j = 0; j < 4; j++)
#pragma unroll
            for (int r = 0; r < 4; r++) acc[i][j][r] = 0.f;

    auto issue_tile = [&](int ki, int s) {
        int phase = ki >> 5;
        int kk = (ki & 31) * 32;
        const __half* Ap = phase ? Al : Ah;
        uint32_t sA = sbase + s * 16384, sB = sA + 8192;
#pragma unroll
        for (int j = 0; j < 2; j++) {
            int idx = tid + j * 256;                   // 512 chunks
            int row = idx >> 2, c = idx & 3;
            int cs = c ^ ((row >> 1) & 3);
            cp_async16(sA + row * 64 + cs * 16, Ap + (size_t)(m0 + row) * DMODEL + kk + c * 8);
            cp_async16(sB + row * 64 + cs * 16, Bh + (size_t)(n0 + row) * DMODEL + kk + c * 8);
        }
        CP_COMMIT();
    };

    issue_tile(0, 0);
    issue_tile(1, 1);
    for (int ki = 0; ki < NKITER; ki++) {
        int s = ki % STAGES;
        if (ki + 1 < NKITER) { CP_WAIT(1); } else { CP_WAIT(0); }
        __syncthreads();
        if (ki + 2 < NKITER) issue_tile(ki + 2, (ki + 2) % STAGES);
        uint32_t sA = sbase + s * 16384, sB = sA + 8192;
#pragma unroll
        for (int kq = 0; kq < 2; kq++) {
            uint32_t af[4][4], bf[4][2];
#pragma unroll
            for (int im = 0; im < 4; im++) {
                int row = wm * 64 + im * 16 + (lane & 15);
                int c = kq * 2 + (lane >> 4);
                int cs = c ^ ((row >> 1) & 3);
                ldsm_x4(af[im], sA + row * 64 + cs * 16);
            }
#pragma unroll
            for (int jn = 0; jn < 4; jn++) {
                int row = wn * 32 + jn * 8 + (lane & 7);
                int c = kq * 2 + ((lane >> 3) & 1);
                int cs = c ^ ((row >> 1) & 3);
                ldsm_x2(bf[jn], sB + row * 64 + cs * 16);
            }
#pragma unroll
            for (int im = 0; im < 4; im++)
#pragma unroll
                for (int jn = 0; jn < 4; jn++) mma16816(acc[im][jn], af[im], bf[jn]);
        }
    }

    // epilogue
#pragma unroll
    for (int im = 0; im < 4; im++) {
#pragma unroll
        for (int jn = 0; jn < 4; jn++) {
            int col = n0 + wn * 32 + jn * 8 + 2 * (lane & 3);
            float b0 = bias[col], b1 = bias[col + 1];
#pragma unroll
            for (int half = 0; half < 2; half++) {
                int m = m0 + wm * 64 + im * 16 + (lane >> 2) + half * 8;
                float v0 = (acc[im][jn][half * 2 + 0] + b0) * scale;
                float v1 = (acc[im][jn][half * 2 + 1] + b1) * scale;
                if (MODE == 0) {
                    int bidx = m >> 9, nseq = m & 511;
                    int h = col >> 6, d = col & 63;
                    size_t idx = (((size_t)(bidx * NH + h)) * SEQ + nseq) * HDIM + d;
                    uint32_t hh, ll;
                    packhl(v0, v1, hh, ll);
                    *(uint32_t*)(OH + idx) = hh;
                    if (OL) *(uint32_t*)(OL + idx) = ll;
                } else {
                    *(float2*)(OF + (size_t)m * DMODEL + col) = make_float2(v0, v1);
                }
            }
        }
    }
}

__global__ __launch_bounds__(256) void k_mma_qkv(const float* __restrict__ bq,
                                                 const float* __restrict__ bk,
                                                 const float* __restrict__ bv) {
    int z = blockIdx.z;
    const __half* Ah = g_actH + (size_t)z * DMODEL * DMODEL;
    const __half* Al = g_actL + (size_t)z * DMODEL * DMODEL;
    const __half* Bh = g_WtH + (size_t)z * DMODEL * DMODEL;
    const float* bias = (z == 0) ? bq : (z == 1) ? bk : bv;
    __half* OH = (z == 0) ? g_QH : (z == 1) ? g_KH : g_VH;
    __half* OL = (z == 0) ? g_QL : (z == 1) ? g_KL : nullptr;   // V needs hi only
    float scale = (z == 0) ? 0.125f : 1.0f;
    mma_body<0>(Ah, Al, Bh, bias, OH, OL, nullptr, scale);
}

__global__ __launch_bounds__(256) void k_mma_out(const float* __restrict__ bo,
                                                 float* __restrict__ out) {
    mma_body<1>(g_attH, g_attL, g_WtH + (size_t)3 * DMODEL * DMODEL,
                bo, nullptr, nullptr, out, 1.0f);
}

// ---------------- tensor-core flash attention, 8 warps, fp16 ----------------
// 256 threads. q-block 64. Warp w: q-rows (w&3)*16..+16, column half g=w>>2.
// S = QhKh + QlKh + QhKl (3-term); PV = PhVh + PlVh (2-term, V hi only).
__global__ __launch_bounds__(256) void k_attn() {
    __shared__ __align__(1024) char smbuf[40960];
    uint32_t sQH = smem_u32(smbuf), sQL = sQH + 8192;
    uint32_t sKH = sQH + 16384, sKL = sQH + 24576;
    uint32_t sVH = sQH + 32768;
    int b = blockIdx.z, h = blockIdx.y, q0 = blockIdx.x * 64;
    int tid = threadIdx.x, lane = tid & 31, wid = tid >> 5;
    int wq = wid & 3, g = wid >> 2;
    size_t hb = (size_t)(b * NH + h) * SEQ * HDIM;
    const __half *QHp = g_QH + hb, *QLp = g_QL + hb;
    const __half *KHp = g_KH + hb, *KLp = g_KL + hb;
    const __half *VHp = g_VH + hb;
    const __half* Bg = g_bias + ((size_t)(b * NH + h) * SEQ + q0) * SEQ;

    // load Q tile (hi/lo), swizzled rows of 8x16B chunks
#pragma unroll
    for (int u = 0; u < 2; u++) {
        int idx = u * 256 + tid;
        int row = idx >> 3, c = idx & 7, cs = c ^ (row & 7);
        size_t go = (size_t)(q0 + row) * HDIM + c * 8;
        cp_async16(sQH + row * 128 + cs * 16, QHp + go);
        cp_async16(sQL + row * 128 + cs * 16, QLp + go);
    }
    CP_COMMIT();
    CP_WAIT(0);
    __syncthreads();

    // Q fragments (A operand, m16 x k16 per kk)
    uint32_t qh[4][4], ql[4][4];
#pragma unroll
    for (int kk = 0; kk < 4; kk++) {
        int row = wq * 16 + (lane & 15);
        int c = kk * 2 + (lane >> 4), cs = c ^ (row & 7);
        ldsm_x4(qh[kk], sQH + row * 128 + cs * 16);
        ldsm_x4(ql[kk], sQL + row * 128 + cs * 16);
    }

    float o[8][4];
#pragma unroll
    for (int j = 0; j < 8; j++)
#pragma unroll
        for (int r = 0; r < 4; r++) o[j][r] = 0.f;
    float mA = -1e30f, mB = -1e30f, lA = 0.f, lB = 0.f;
    int br0 = wq * 16 + (lane >> 2);
    int bc = 2 * (lane & 3);
    int goff = g * 32;

    for (int k0 = 0; k0 < SEQ; k0 += 64) {
        __syncthreads();   // prev iter's reads of K/V smem done
#pragma unroll
        for (int u = 0; u < 2; u++) {
            int idx = u * 256 + tid;
            int row = idx >> 3, c = idx & 7, cs = c ^ (row & 7);
            size_t go = (size_t)(k0 + row) * HDIM + c * 8;
            cp_async16(sKH + row * 128 + cs * 16, KHp + go);
            cp_async16(sKL + row * 128 + cs * 16, KLp + go);
            cp_async16(sVH + row * 128 + cs * 16, VHp + go);
        }
        CP_COMMIT();
        // prefetch bias fragments (fp16, hidden under cp.async wait)
        float2 bias0[4], bias1[4];
#pragma unroll
        for (int jt = 0; jt < 4; jt++) {
            __half2 t0 = *(const __half2*)(Bg + (size_t)br0 * SEQ + k0 + goff + jt * 8 + bc);
            __half2 t1 = *(const __half2*)(Bg + (size_t)(br0 + 8) * SEQ + k0 + goff + jt * 8 + bc);
            bias0[jt] = __half22float2(t0);
            bias1[jt] = __half22float2(t1);
        }
        CP_WAIT(0);
        __syncthreads();

        // S tiles: 4 n-tiles (this group's 32 cols), 3-term mma
        float s[4][4];
#pragma unroll
        for (int jt = 0; jt < 4; jt++) {
            s[jt][0] = s[jt][1] = s[jt][2] = s[jt][3] = 0.f;
#pragma unroll
            for (int kk = 0; kk < 4; kk++) {
                uint32_t kh[2], kl[2];
                int row = goff + jt * 8 + (lane & 7);
                int c = kk * 2 + ((lane >> 3) & 1), cs = c ^ (row & 7);
                ldsm_x2(kh, sKH + row * 128 + cs * 16);
                ldsm_x2(kl, sKL + row * 128 + cs * 16);
                mma16816(s[jt], qh[kk], kh);
                mma16816(s[jt], ql[kk], kh);
                mma16816(s[jt], qh[kk], kl);
            }
        }

        // bias + online softmax over this group's 32 columns
        float mx0 = mA, mx1 = mB;
#pragma unroll
        for (int jt = 0; jt < 4; jt++) {
            s[jt][0] += bias0[jt].x; s[jt][1] += bias0[jt].y;
            s[jt][2] += bias1[jt].x; s[jt][3] += bias1[jt].y;
            mx0 = fmaxf(mx0, fmaxf(s[jt][0], s[jt][1]));
            mx1 = fmaxf(mx1, fmaxf(s[jt][2], s[jt][3]));
        }
        mx0 = fmaxf(mx0, __shfl_xor_sync(0xffffffffu, mx0, 1));
        mx0 = fmaxf(mx0, __shfl_xor_sync(0xffffffffu, mx0, 2));
        mx1 = fmaxf(mx1, __shfl_xor_sync(0xffffffffu, mx1, 1));
        mx1 = fmaxf(mx1, __shfl_xor_sync(0xffffffffu, mx1, 2));
        float corr0 = __expf(mA - mx0), corr1 = __expf(mB - mx1);
        mA = mx0; mB = mx1;
        float rs0 = 0.f, rs1 = 0.f;
#pragma unroll
        for (int jt = 0; jt < 4; jt++) {
            s[jt][0] = __expf(s[jt][0] - mA);
            s[jt][1] = __expf(s[jt][1] - mA);
            s[jt][2] = __expf(s[jt][2] - mB);
            s[jt][3] = __expf(s[jt][3] - mB);
            rs0 += s[jt][0] + s[jt][1];
            rs1 += s[jt][2] + s[jt][3];
        }
        rs0 += __shfl_xor_sync(0xffffffffu, rs0, 1);
        rs0 += __shfl_xor_sync(0xffffffffu, rs0, 2);
        rs1 += __shfl_xor_sync(0xffffffffu, rs1, 1);
        rs1 += __shfl_xor_sync(0xffffffffu, rs1, 2);
        lA = lA * corr0 + rs0;
        lB = lB * corr1 + rs1;
#pragma unroll
        for (int j = 0; j < 8; j++) {
            o[j][0] *= corr0; o[j][1] *= corr0;
            o[j][2] *= corr1; o[j][3] *= corr1;
        }

        // P fragments (C layout == A layout): hi + residual lo, 2 k16 chunks
        uint32_t ph[2][4], pl[2][4];
#pragma unroll
        for (int kk = 0; kk < 2; kk++) {
            packhl(s[2 * kk][0], s[2 * kk][1], ph[kk][0], pl[kk][0]);
            packhl(s[2 * kk][2], s[2 * kk][3], ph[kk][1], pl[kk][1]);
            packhl(s[2 * kk + 1][0], s[2 * kk + 1][1], ph[kk][2], pl[kk][2]);
            packhl(s[2 * kk + 1][2], s[2 * kk + 1][3], ph[kk][3], pl[kk][3]);
        }

        // O += P @ V over this group's 32 k-rows (2-term), V via ldmatrix.trans
#pragma unroll
        for (int kk = 0; kk < 2; kk++) {
#pragma unroll
            for (int j = 0; j < 8; j++) {
                uint32_t vh[2];
                int row = goff + kk * 16 + (lane & 15);
                int cs = j ^ (row & 7);
                ldsm_x2_trans(vh, sVH + row * 128 + cs * 16);
                mma16816(o[j], ph[kk], vh);
                mma16816(o[j], pl[kk], vh);
            }
        }
    }

    // merge group 1 into group 0 via smem, then write fp16 hi/lo
    float* scr = (float*)(smbuf + 16384);   // 64x64 f32 (over K region)
    float* sml = (float*)(smbuf + 32768);   // [row][m,l] pairs (over VH)
    __syncthreads();
    if (g == 1) {
#pragma unroll
        for (int j = 0; j < 8; j++) {
            scr[br0 * 64 + j * 8 + bc] = o[j][0];
            scr[br0 * 64 + j * 8 + bc + 1] = o[j][1];
            scr[(br0 + 8) * 64 + j * 8 + bc] = o[j][2];
            scr[(br0 + 8) * 64 + j * 8 + bc + 1] = o[j][3];
        }
        if ((lane & 3) == 0) {
            sml[br0 * 2] = mA; sml[br0 * 2 + 1] = lA;
            sml[(br0 + 8) * 2] = mB; sml[(br0 + 8) * 2 + 1] = lB;
        }
    }
    __syncthreads();
    if (g == 0) {
        float m0p = sml[br0 * 2], l0p = sml[br0 * 2 + 1];
        float m1p = sml[(br0 + 8) * 2], l1p = sml[(br0 + 8) * 2 + 1];
        float M0 = fmaxf(mA, m0p), M1 = fmaxf(mB, m1p);
        float c0 = __expf(mA - M0), c0p = __expf(m0p - M0);
        float c1 = __expf(mB - M1), c1p = __expf(m1p - M1);
        float r0 = 1.f / (lA * c0 + l0p * c0p);
        float r1 = 1.f / (lB * c1 + l1p * c1p);
        int rq0 = q0 + br0;
#pragma unroll
        for (int j = 0; j < 8; j++) {
            float v0 = (o[j][0] * c0 + scr[br0 * 64 + j * 8 + bc] * c0p) * r0;
            float v1 = (o[j][1] * c0 + scr[br0 * 64 + j * 8 + bc + 1] * c0p) * r0;
            float v2 = (o[j][2] * c1 + scr[(br0 + 8) * 64 + j * 8 + bc] * c1p) * r1;
            float v3 = (o[j][3] * c1 + scr[(br0 + 8) * 64 + j * 8 + bc + 1] * c1p) * r1;
            size_t i0 = ((size_t)(b * SEQ + rq0) * NH + h) * HDIM + j * 8 + bc;
            size_t i1 = ((size_t)(b * SEQ + rq0 + 8) * NH + h) * HDIM + j * 8 + bc;
            uint32_t hh, ll;
            packhl(v0, v1, hh, ll);
            *(uint32_t*)(g_attH + i0) = hh;
            *(uint32_t*)(g_attL + i0) = ll;
            packhl(v2, v3, hh, ll);
            *(uint32_t*)(g_attH + i1) = hh;
            *(uint32_t*)(g_attL + i1) = ll;
        }
    }
}

// ---------------- launch: two-stream fork/join for graph-level overlap ----------------
extern "C" void kernel_launch(void* const* d_in, const int* in_sizes, int n_in,
                              void* d_out, int out_size) {
    (void)in_sizes; (void)n_in; (void)out_size;
    const float* query = (const float*)d_in[0];
    const float* key   = (const float*)d_in[1];
    const float* value = (const float*)d_in[2];
    const float* qx    = (const float*)d_in[3];
    const float* qy    = (const float*)d_in[4];
    const float* kx    = (const float*)d_in[5];
    const float* ky    = (const float*)d_in[6];
    const float* Wq    = (const float*)d_in[7];
    const float* bq    = (const float*)d_in[8];
    const float* Wk    = (const float*)d_in[9];
    const float* bk    = (const float*)d_in[10];
    const float* Wv    = (const float*)d_in[11];
    const float* bv    = (const float*)d_in[12];
    const float* Wo    = (const float*)d_in[13];
    const float* bo    = (const float*)d_in[14];
    const float* xt    = (const float*)d_in[15];
    const float* yt    = (const float*)d_in[16];
    const float* Wb    = (const float*)d_in[17];
    const float* bb    = (const float*)d_in[18];
    float* out = (float*)d_out;

    // one-time side-stream/event creation (same topology every call; no device allocs)
    static cudaStream_t s1 = nullptr;
    static cudaEvent_t eFork = nullptr, eJoin = nullptr;
    if (!s1) {
        cudaStreamCreateWithFlags(&s1, cudaStreamNonBlocking);
        cudaEventCreateWithFlags(&eFork, cudaEventDisableTiming);
        cudaEventCreateWithFlags(&eJoin, cudaEventDisableTiming);
    }

    // fork: side stream runs the memory-bound bias chain
    cudaEventRecord(eFork, 0);
    cudaStreamWaitEvent(s1, eFork, 0);
    k_project<<<(2 * NEMB * NH + 255) / 256, 256, 0, s1>>>(xt, yt, Wb);
    k_bias<<<dim3(SEQ / 16, SEQ / 16, NB), 256, 0, s1>>>(qx, qy, kx, ky, bb);
    cudaEventRecord(eJoin, s1);

    // main stream: mma-bound projection chain (overlaps with bias chain)
    k_convA<<<dim3(DMODEL * DMODEL / 4 / 256, 1, 3), 256>>>(query, key, value);
    k_convW<<<dim3(32, 32, 4), dim3(32, 8)>>>(Wq, Wk, Wv, Wo);
    k_mma_qkv<<<dim3(8, 8, 3), 256>>>(bq, bk, bv);

    // join: attention needs both chains
    cudaStreamWaitEvent(0, eJoin, 0);
    k_attn<<<dim3(SEQ / 64, NH, NB), 256>>>();
    k_mma_out<<<dim3(8, 8), 256>>>(bo, out);
}

// round 9
// speedup vs baseline: 1.6573x; 1.0088x over previous
#include <cuda_runtime.h>
#include <cuda_fp16.h>
#include <cstdint>

#define NH     16
#define DMODEL 1024
#define HDIM   64
#define NEMB   40001
#define NB     2
#define SEQ    512

// ---------------- device scratch ----------------
__device__ float g_Tx[NEMB * NH];
__device__ float g_Ty[NEMB * NH];
__device__ __half g_bias[(size_t)NB * NH * SEQ * SEQ];   // fp16 bias (16.7MB)

// fp16 hi/lo split operands
__device__ __half g_actH[3 * DMODEL * DMODEL];   // q,k,v activations [m][k]
__device__ __half g_actL[3 * DMODEL * DMODEL];
__device__ __half g_WtH[4 * DMODEL * DMODEL];    // Wq,Wk,Wv,Wo transposed [n][k] (hi only)
// projected Q/K/V in [b][h][seq][d], fp16 hi/lo (Q pre-scaled by 0.125)
__device__ __half g_QH[NB * NH * SEQ * HDIM], g_QL[NB * NH * SEQ * HDIM];
__device__ __half g_KH[NB * NH * SEQ * HDIM], g_KL[NB * NH * SEQ * HDIM];
__device__ __half g_VH[NB * NH * SEQ * HDIM];
// attention output hi/lo, [b*q][h*64+d] row-major 1024x1024
__device__ __half g_attH[DMODEL * DMODEL];
__device__ __half g_attL[DMODEL * DMODEL];

// ---------------- non-gated PTX helpers ----------------
__device__ __forceinline__ uint32_t smem_u32(const void* p) {
    uint32_t a;
    asm("{ .reg .u64 t; cvta.to.shared.u64 t, %1; cvt.u32.u64 %0, t; }" : "=r"(a) : "l"(p));
    return a;
}
__device__ __forceinline__ void cp_async16(uint32_t saddr, const void* gptr) {
    asm volatile("cp.async.cg.shared.global [%0], [%1], 16;" :: "r"(saddr), "l"(gptr) : "memory");
}
#define CP_COMMIT() asm volatile("cp.async.commit_group;" ::: "memory")
#define CP_WAIT(n)  asm volatile("cp.async.wait_group %0;" :: "n"(n) : "memory")

__device__ __forceinline__ void ldsm_x4(uint32_t* r, uint32_t addr) {
    asm volatile("ldmatrix.sync.aligned.m8n8.x4.shared.b16 {%0,%1,%2,%3}, [%4];"
                 : "=r"(r[0]), "=r"(r[1]), "=r"(r[2]), "=r"(r[3]) : "r"(addr));
}
__device__ __forceinline__ void ldsm_x2(uint32_t* r, uint32_t addr) {
    asm volatile("ldmatrix.sync.aligned.m8n8.x2.shared.b16 {%0,%1}, [%2];"
                 : "=r"(r[0]), "=r"(r[1]) : "r"(addr));
}
__device__ __forceinline__ void ldsm_x2_trans(uint32_t* r, uint32_t addr) {
    asm volatile("ldmatrix.sync.aligned.m8n8.x2.trans.shared.b16 {%0,%1}, [%2];"
                 : "=r"(r[0]), "=r"(r[1]) : "r"(addr));
}
__device__ __forceinline__ void mma16816(float* d, const uint32_t* a, const uint32_t* b) {
    asm volatile("mma.sync.aligned.m16n8k16.row.col.f32.f16.f16.f32 "
                 "{%0,%1,%2,%3}, {%4,%5,%6,%7}, {%8,%9}, {%0,%1,%2,%3};"
                 : "+f"(d[0]), "+f"(d[1]), "+f"(d[2]), "+f"(d[3])
                 : "r"(a[0]), "r"(a[1]), "r"(a[2]), "r"(a[3]), "r"(b[0]), "r"(b[1]));
}
// pack two floats into fp16x2 hi part + fp16x2 residual part
__device__ __forceinline__ void packhl(float a, float b, uint32_t& hh, uint32_t& ll) {
    __half2 h2 = __floats2half2_rn(a, b);
    float2 f = __half22float2(h2);
    __half2 l2 = __floats2half2_rn(a - f.x, b - f.y);
    hh = *reinterpret_cast<uint32_t*>(&h2);
    ll = *reinterpret_cast<uint32_t*>(&l2);
}

// ---------------- kernel 1: project embedding tables through Wb ----------------
__global__ __launch_bounds__(256) void k_project(const float* __restrict__ xt,
                                                 const float* __restrict__ yt,
                                                 const float* __restrict__ Wb) {
    int id = blockIdx.x * 256 + threadIdx.x;
    if (id >= 2 * NEMB * NH) return;
    int which = (id >= NEMB * NH);
    int rid = which ? id - NEMB * NH : id;
    int r = rid >> 4, h = rid & 15;
    const float4* row = (const float4*)((which ? yt : xt) + (size_t)r * 256 + h * 16);
    const float4* wb = (const float4*)Wb;
    float s = 0.f;
#pragma unroll
    for (int q = 0; q < 4; q++) {
        float4 v = row[q], w = wb[q];
        s += v.x * w.x + v.y * w.y + v.z * w.z + v.w * w.w;
    }
    (which ? g_Ty : g_Tx)[rid] = s;
}

// ---------------- kernel 2: positional bias (fp16 output) ----------------
__global__ __launch_bounds__(256) void k_bias(const float* __restrict__ qx,
                                              const float* __restrict__ qy,
                                              const float* __restrict__ kx,
                                              const float* __restrict__ ky,
                                              const float* __restrict__ bbp) {
    __shared__ float sm[16 * 256];
    int b = blockIdx.z;
    int i0 = blockIdx.y * 16, j0 = blockIdx.x * 16;
    int t = threadIdx.x;
    int i = i0 + (t >> 4), j = j0 + (t & 15);
    float bb = bbp[0];
    float dx = qx[b * SEQ + j] - kx[b * SEQ + i];
    float dy = qy[b * SEQ + j] - ky[b * SEQ + i];
    dx = fminf(fmaxf(dx, -1000.f), 1000.f);
    dy = fminf(fmaxf(dy, -1000.f), 1000.f);
    int ix = (int)rintf((dx + 1000.f) * 20.f);
    int iy = (int)rintf((dy + 1000.f) * 20.f);
    const float4* px = (const float4*)(g_Tx + (size_t)ix * 16);
    const float4* py = (const float4*)(g_Ty + (size_t)iy * 16);
#pragma unroll
    for (int q = 0; q < 4; q++) {
        float4 a = px[q], c = py[q];
        float v0 = a.x + c.x + bb, v1 = a.y + c.y + bb;
        float v2 = a.z + c.z + bb, v3 = a.w + c.w + bb;
        sm[(q * 4 + 0) * 256 + t] = 1.f / (1.f + __expf(-v0));
        sm[(q * 4 + 1) * 256 + t] = 1.f / (1.f + __expf(-v1));
        sm[(q * 4 + 2) * 256 + t] = 1.f / (1.f + __expf(-v2));
        sm[(q * 4 + 3) * 256 + t] = 1.f / (1.f + __expf(-v3));
    }
    __syncthreads();
    int h = t >> 4, w = t & 15;
#pragma unroll
    for (int ii = 0; ii < 16; ii++) {
        g_bias[(((size_t)(b * NH + h)) * SEQ + (i0 + ii)) * SEQ + (j0 + w)] =
            __float2half(sm[h * 256 + ii * 16 + w]);
    }
}

// ---------------- fp16 hi/lo split helpers ----------------
__device__ __forceinline__ void split4h(float4 x, __half2* ph, __half2* pl) {
    __half2 h01 = __floats2half2_rn(x.x, x.y);
    __half2 h23 = __floats2half2_rn(x.z, x.w);
    float2 f01 = __half22float2(h01), f23 = __half22float2(h23);
    ph[0] = h01; ph[1] = h23;
    pl[0] = __floats2half2_rn(x.x - f01.x, x.y - f01.y);
    pl[1] = __floats2half2_rn(x.z - f23.x, x.w - f23.y);
}

// ---------------- merged conversion kernel: activations + weights ----------------
// blocks [0, 3072): convA (z = b/1024)       blocks [3072, 7168): convW
__global__ __launch_bounds__(256) void k_conv(const float* __restrict__ q,
                                              const float* __restrict__ k,
                                              const float* __restrict__ v,
                                              const float* __restrict__ Wq,
                                              const float* __restrict__ Wk,
                                              const float* __restrict__ Wv,
                                              const float* __restrict__ Wo) {
    __shared__ float t[32][33];
    int bidx = blockIdx.x, tid = threadIdx.x;
    if (bidx < 3072) {
        int z = bidx >> 10;
        const float* src = (z == 0) ? q : (z == 1) ? k : v;
        __half* H = g_actH + (size_t)z * DMODEL * DMODEL;
        __half* L = g_actL + (size_t)z * DMODEL * DMODEL;
        int i = (bidx & 1023) * 256 + tid;
        float4 x = ((const float4*)src)[i];
        split4h(x, (__half2*)(H + (size_t)i * 4), (__half2*)(L + (size_t)i * 4));
    } else {
        int w = bidx - 3072;
        int z = w >> 10, rem = w & 1023;
        const float* W = (z == 0) ? Wq : (z == 1) ? Wk : (z == 2) ? Wv : Wo;
        __half* H = g_WtH + (size_t)z * DMODEL * DMODEL;
        int nb = (rem & 31) * 32, kb = (rem >> 5) * 32;
        int tx = tid & 31, ty = tid >> 5;   // 32 x 8
#pragma unroll
        for (int i = 0; i < 4; i++)
            t[ty + i * 8][tx] = W[(size_t)(kb + ty + i * 8) * DMODEL + nb + tx];
        __syncthreads();
#pragma unroll
        for (int i = 0; i < 4; i++) {
            int n = nb + ty + i * 8, kk = kb + tx;
            H[(size_t)n * DMODEL + kk] = __float2half(t[tx][ty + i * 8]);
        }
    }
}

// ---------------- warp-mma GEMM: C = (Ah+Al) @ Bh^T + bias ----------------
// 2-term fp16 split folded into one K=2048 GEMM (phases: AhBh, AlBh).
// BM=BN=128, BK=32, 8 warps (2m x 4n), 3-stage cp.async pipeline.
#define NKITER 64
#define STAGES 3

template <int MODE>
__device__ __forceinline__ void mma_body(const __half* __restrict__ Ah,
                                         const __half* __restrict__ Al,
                                         const __half* __restrict__ Bh,
                                         const float* __restrict__ bias,
                                         __half* __restrict__ OH,
                                         __half* __restrict__ OL,
                                         float* __restrict__ OF,
                                         float scale) {
    __shared__ __align__(1024) char smem[STAGES][16384];   // per stage: A 8KB | B 8KB
    int tid = threadIdx.x, lane = tid & 31, wid = tid >> 5;
    int wm = wid & 1, wn = wid >> 1;                  // 2 x 4 warp grid
    int m0 = blockIdx.y * 128, n0 = blockIdx.x * 128;
    uint32_t sbase = smem_u32(smem);

    float acc[4][4][4];
#pragma unroll
    for (int i = 0; i < 4; i++)
#pragma unroll
        for (int j = 0; j < 4; j++)
#pragma unroll
            for (int r = 0; r < 4; r++) acc[i][j][r] = 0.f;

    auto issue_tile = [&](int ki, int s) {
        int phase = ki >> 5;
        int kk = (ki & 31) * 32;
        const __half* Ap = phase ? Al : Ah;
        uint32_t sA = sbase + s * 16384, sB = sA + 8192;
#pragma unroll
        for (int j = 0; j < 2; j++) {
            int idx = tid + j * 256;                   // 512 chunks
            int row = idx >> 2, c = idx & 3;
            int cs = c ^ ((row >> 1) & 3);
            cp_async16(sA + row * 64 + cs * 16, Ap + (size_t)(m0 + row) * DMODEL + kk + c * 8);
            cp_async16(sB + row * 64 + cs * 16, Bh + (size_t)(n0 + row) * DMODEL + kk + c * 8);
        }
        CP_COMMIT();
    };

    issue_tile(0, 0);
    issue_tile(1, 1);
    for (int ki = 0; ki < NKITER; ki++) {
        int s = ki % STAGES;
        if (ki + 1 < NKITER) { CP_WAIT(1); } else { CP_WAIT(0); }
        __syncthreads();
        if (ki + 2 < NKITER) issue_tile(ki + 2, (ki + 2) % STAGES);
        uint32_t sA = sbase + s * 16384, sB = sA + 8192;
#pragma unroll
        for (int kq = 0; kq < 2; kq++) {
            uint32_t af[4][4], bf[4][2];
#pragma unroll
            for (int im = 0; im < 4; im++) {
                int row = wm * 64 + im * 16 + (lane & 15);
                int c = kq * 2 + (lane >> 4);
                int cs = c ^ ((row >> 1) & 3);
                ldsm_x4(af[im], sA + row * 64 + cs * 16);
            }
#pragma unroll
            for (int jn = 0; jn < 4; jn++) {
                int row = wn * 32 + jn * 8 + (lane & 7);
                int c = kq * 2 + ((lane >> 3) & 1);
                int cs = c ^ ((row >> 1) & 3);
                ldsm_x2(bf[jn], sB + row * 64 + cs * 16);
            }
#pragma unroll
            for (int im = 0; im < 4; im++)
#pragma unroll
                for (int jn = 0; jn < 4; jn++) mma16816(acc[im][jn], af[im], bf[jn]);
        }
    }

    // epilogue
#pragma unroll
    for (int im = 0; im < 4; im++) {
#pragma unroll
        for (int jn = 0; jn < 4; jn++) {
            int col = n0 + wn * 32 + jn * 8 + 2 * (lane & 3);
            float b0 = bias[col], b1 = bias[col + 1];
#pragma unroll
            for (int half = 0; half < 2; half++) {
                int m = m0 + wm * 64 + im * 16 + (lane >> 2) + half * 8;
                float v0 = (acc[im][jn][half * 2 + 0] + b0) * scale;
                float v1 = (acc[im][jn][half * 2 + 1] + b1) * scale;
                if (MODE == 0) {
                    int bidx = m >> 9, nseq = m & 511;
                    int h = col >> 6, d = col & 63;
                    size_t idx = (((size_t)(bidx * NH + h)) * SEQ + nseq) * HDIM + d;
                    uint32_t hh, ll;
                    packhl(v0, v1, hh, ll);
                    *(uint32_t*)(OH + idx) = hh;
                    if (OL) *(uint32_t*)(OL + idx) = ll;
                } else {
                    *(float2*)(OF + (size_t)m * DMODEL + col) = make_float2(v0, v1);
                }
            }
        }
    }
}

__global__ __launch_bounds__(256) void k_mma_qkv(const float* __restrict__ bq,
                                                 const float* __restrict__ bk,
                                                 const float* __restrict__ bv) {
    int z = blockIdx.z;
    const __half* Ah = g_actH + (size_t)z * DMODEL * DMODEL;
    const __half* Al = g_actL + (size_t)z * DMODEL * DMODEL;
    const __half* Bh = g_WtH + (size_t)z * DMODEL * DMODEL;
    const float* bias = (z == 0) ? bq : (z == 1) ? bk : bv;
    __half* OH = (z == 0) ? g_QH : (z == 1) ? g_KH : g_VH;
    __half* OL = (z == 0) ? g_QL : (z == 1) ? g_KL : nullptr;   // V needs hi only
    float scale = (z == 0) ? 0.125f : 1.0f;
    mma_body<0>(Ah, Al, Bh, bias, OH, OL, nullptr, scale);
}

__global__ __launch_bounds__(256) void k_mma_out(const float* __restrict__ bo,
                                                 float* __restrict__ out) {
    mma_body<1>(g_attH, g_attL, g_WtH + (size_t)3 * DMODEL * DMODEL,
                bo, nullptr, nullptr, out, 1.0f);
}

// ---------------- tensor-core flash attention, 8 warps, fixed-max softmax ----------------
// 256 threads. q-block 64. Warp w: q-rows (w&3)*16..+16, column half g=w>>2.
// Logits bounded (|s|*0.125 <~ 3, bias in (0,1)) -> exp without max subtraction is
// safe in fp32 (sum <= 512*e^4). No max tracking, no rescale: l accumulates locally,
// reduced once at the end. Merge across groups is a pure sum.
__global__ __launch_bounds__(256) void k_attn() {
    __shared__ __align__(1024) char smbuf[40960];
    uint32_t sQH = smem_u32(smbuf), sQL = sQH + 8192;
    uint32_t sKH = sQH + 16384, sKL = sQH + 24576;
    uint32_t sVH = sQH + 32768;
    int b = blockIdx.z, h = blockIdx.y, q0 = blockIdx.x * 64;
    int tid = threadIdx.x, lane = tid & 31, wid = tid >> 5;
    int wq = wid & 3, g = wid >> 2;
    size_t hb = (size_t)(b * NH + h) * SEQ * HDIM;
    const __half *QHp = g_QH + hb, *QLp = g_QL + hb;
    const __half *KHp = g_KH + hb, *KLp = g_KL + hb;
    const __half *VHp = g_VH + hb;
    const __half* Bg = g_bias + ((size_t)(b * NH + h) * SEQ + q0) * SEQ;

    // load Q tile (hi/lo), swizzled rows of 8x16B chunks
#pragma unroll
    for (int u = 0; u < 2; u++) {
        int idx = u * 256 + tid;
        int row = idx >> 3, c = idx & 7, cs = c ^ (row & 7);
        size_t go = (size_t)(q0 + row) * HDIM + c * 8;
        cp_async16(sQH + row * 128 + cs * 16, QHp + go);
        cp_async16(sQL + row * 128 + cs * 16, QLp + go);
    }
    CP_COMMIT();
    CP_WAIT(0);
    __syncthreads();

    // Q fragments (A operand, m16 x k16 per kk)
    uint32_t qh[4][4], ql[4][4];
#pragma unroll
    for (int kk = 0; kk < 4; kk++) {
        int row = wq * 16 + (lane & 15);
        int c = kk * 2 + (lane >> 4), cs = c ^ (row & 7);
        ldsm_x4(qh[kk], sQH + row * 128 + cs * 16);
        ldsm_x4(ql[kk], sQL + row * 128 + cs * 16);
    }

    float o[8][4];
#pragma unroll
    for (int j = 0; j < 8; j++)
#pragma unroll
        for (int r = 0; r < 4; r++) o[j][r] = 0.f;
    float lA = 0.f, lB = 0.f;     // local row-sum accumulators (quad-reduced at end)
    int br0 = wq * 16 + (lane >> 2);
    int bc = 2 * (lane & 3);
    int goff = g * 32;

    for (int k0 = 0; k0 < SEQ; k0 += 64) {
        __syncthreads();   // prev iter's reads of K/V smem done
#pragma unroll
        for (int u = 0; u < 2; u++) {
            int idx = u * 256 + tid;
            int row = idx >> 3, c = idx & 7, cs = c ^ (row & 7);
            size_t go = (size_t)(k0 + row) * HDIM + c * 8;
            cp_async16(sKH + row * 128 + cs * 16, KHp + go);
            cp_async16(sKL + row * 128 + cs * 16, KLp + go);
            cp_async16(sVH + row * 128 + cs * 16, VHp + go);
        }
        CP_COMMIT();
        // prefetch bias fragments (fp16, hidden under cp.async wait)
        float2 bias0[4], bias1[4];
#pragma unroll
        for (int jt = 0; jt < 4; jt++) {
            __half2 t0 = *(const __half2*)(Bg + (size_t)br0 * SEQ + k0 + goff + jt * 8 + bc);
            __half2 t1 = *(const __half2*)(Bg + (size_t)(br0 + 8) * SEQ + k0 + goff + jt * 8 + bc);
            bias0[jt] = __half22float2(t0);
            bias1[jt] = __half22float2(t1);
        }
        CP_WAIT(0);
        __syncthreads();

        // S tiles: 4 n-tiles (this group's 32 cols), 3-term mma
        float s[4][4];
#pragma unroll
        for (int jt = 0; jt < 4; jt++) {
            s[jt][0] = s[jt][1] = s[jt][2] = s[jt][3] = 0.f;
#pragma unroll
            for (int kk = 0; kk < 4; kk++) {
                uint32_t kh[2], kl[2];
                int row = goff + jt * 8 + (lane & 7);
                int c = kk * 2 + ((lane >> 3) & 1), cs = c ^ (row & 7);
                ldsm_x2(kh, sKH + row * 128 + cs * 16);
                ldsm_x2(kl, sKL + row * 128 + cs * 16);
                mma16816(s[jt], qh[kk], kh);
                mma16816(s[jt], ql[kk], kh);
                mma16816(s[jt], qh[kk], kl);
            }
        }

        // bias + exp (no max subtraction), accumulate local row sums
#pragma unroll
        for (int jt = 0; jt < 4; jt++) {
            s[jt][0] = __expf(s[jt][0] + bias0[jt].x);
            s[jt][1] = __expf(s[jt][1] + bias0[jt].y);
            s[jt][2] = __expf(s[jt][2] + bias1[jt].x);
            s[jt][3] = __expf(s[jt][3] + bias1[jt].y);
            lA += s[jt][0] + s[jt][1];
            lB += s[jt][2] + s[jt][3];
        }

        // P fragments (C layout == A layout): hi + residual lo, 2 k16 chunks
        uint32_t ph[2][4], pl[2][4];
#pragma unroll
        for (int kk = 0; kk < 2; kk++) {
            packhl(s[2 * kk][0], s[2 * kk][1], ph[kk][0], pl[kk][0]);
            packhl(s[2 * kk][2], s[2 * kk][3], ph[kk][1], pl[kk][1]);
            packhl(s[2 * kk + 1][0], s[2 * kk + 1][1], ph[kk][2], pl[kk][2]);
            packhl(s[2 * kk + 1][2], s[2 * kk + 1][3], ph[kk][3], pl[kk][3]);
        }

        // O += P @ V over this group's 32 k-rows (2-term), V via ldmatrix.trans
#pragma unroll
        for (int kk = 0; kk < 2; kk++) {
#pragma unroll
            for (int j = 0; j < 8; j++) {
                uint32_t vh[2];
                int row = goff + kk * 16 + (lane & 15);
                int cs = j ^ (row & 7);
                ldsm_x2_trans(vh, sVH + row * 128 + cs * 16);
                mma16816(o[j], ph[kk], vh);
                mma16816(o[j], pl[kk], vh);
            }
        }
    }

    // reduce l across the quad (lanes sharing a row)
    lA += __shfl_xor_sync(0xffffffffu, lA, 1);
    lA += __shfl_xor_sync(0xffffffffu, lA, 2);
    lB += __shfl_xor_sync(0xffffffffu, lB, 1);
    lB += __shfl_xor_sync(0xffffffffu, lB, 2);

    // merge group 1 into group 0 (pure sums), then write fp16 hi/lo
    float* scr = (float*)(smbuf + 16384);   // 64x64 f32 (over K region)
    float* sml = (float*)(smbuf + 32768);   // 64 row sums (over VH region)
    __syncthreads();
    if (g == 1) {
#pragma unroll
        for (int j = 0; j < 8; j++) {
            scr[br0 * 64 + j * 8 + bc] = o[j][0];
            scr[br0 * 64 + j * 8 + bc + 1] = o[j][1];
            scr[(br0 + 8) * 64 + j * 8 + bc] = o[j][2];
            scr[(br0 + 8) * 64 + j * 8 + bc + 1] = o[j][3];
        }
        if ((lane & 3) == 0) {
            sml[br0] = lA;
            sml[br0 + 8] = lB;
        }
    }
    __syncthreads();
    if (g == 0) {
        float r0 = 1.f / (lA + sml[br0]);
        float r1 = 1.f / (lB + sml[br0 + 8]);
        int rq0 = q0 + br0;
#pragma unroll
        for (int j = 0; j < 8; j++) {
            float v0 = (o[j][0] + scr[br0 * 64 + j * 8 + bc]) * r0;
            float v1 = (o[j][1] + scr[br0 * 64 + j * 8 + bc + 1]) * r0;
            float v2 = (o[j][2] + scr[(br0 + 8) * 64 + j * 8 + bc]) * r1;
            float v3 = (o[j][3] + scr[(br0 + 8) * 64 + j * 8 + bc + 1]) * r1;
            size_t i0 = ((size_t)(b * SEQ + rq0) * NH + h) * HDIM + j * 8 + bc;
            size_t i1 = ((size_t)(b * SEQ + rq0 + 8) * NH + h) * HDIM + j * 8 + bc;
            uint32_t hh, ll;
            packhl(v0, v1, hh, ll);
            *(uint32_t*)(g_attH + i0) = hh;
            *(uint32_t*)(g_attL + i0) = ll;
            packhl(v2, v3, hh, ll);
            *(uint32_t*)(g_attH + i1) = hh;
            *(uint32_t*)(g_attL + i1) = ll;
        }
    }
}

// ---------------- launch: two-stream fork/join for graph-level overlap ----------------
extern "C" void kernel_launch(void* const* d_in, const int* in_sizes, int n_in,
                              void* d_out, int out_size) {
    (void)in_sizes; (void)n_in; (void)out_size;
    const float* query = (const float*)d_in[0];
    const float* key   = (const float*)d_in[1];
    const float* value = (const float*)d_in[2];
    const float* qx    = (const float*)d_in[3];
    const float* qy    = (const float*)d_in[4];
    const float* kx    = (const float*)d_in[5];
    const float* ky    = (const float*)d_in[6];
    const float* Wq    = (const float*)d_in[7];
    const float* bq    = (const float*)d_in[8];
    const float* Wk    = (const float*)d_in[9];
    const float* bk    = (const float*)d_in[10];
    const float* Wv    = (const float*)d_in[11];
    const float* bv    = (const float*)d_in[12];
    const float* Wo    = (const float*)d_in[13];
    const float* bo    = (const float*)d_in[14];
    const float* xt    = (const float*)d_in[15];
    const float* yt    = (const float*)d_in[16];
    const float* Wb    = (const float*)d_in[17];
    const float* bb    = (const float*)d_in[18];
    float* out = (float*)d_out;

    // one-time side-stream/event creation (same topology every call; no device allocs)
    static cudaStream_t s1 = nullptr;
    static cudaEvent_t eFork = nullptr, eJoin = nullptr;
    if (!s1) {
        cudaStreamCreateWithFlags(&s1, cudaStreamNonBlocking);
        cudaEventCreateWithFlags(&eFork, cudaEventDisableTiming);
        cudaEventCreateWithFlags(&eJoin, cudaEventDisableTiming);
    }

    // fork: side stream runs the memory-bound bias chain
    cudaEventRecord(eFork, 0);
    cudaStreamWaitEvent(s1, eFork, 0);
    k_project<<<(2 * NEMB * NH + 255) / 256, 256, 0, s1>>>(xt, yt, Wb);
    k_bias<<<dim3(SEQ / 16, SEQ / 16, NB), 256, 0, s1>>>(qx, qy, kx, ky, bb);
    cudaEventRecord(eJoin, s1);

    // main stream: mma-bound projection chain (overlaps with bias chain)
    k_conv<<<7168, 256>>>(query, key, value, Wq, Wk, Wv, Wo);
    k_mma_qkv<<<dim3(8, 8, 3), 256>>>(bq, bk, bv);

    // join: attention needs both chains
    cudaStreamWaitEvent(0, eJoin, 0);
    k_attn<<<dim3(SEQ / 64, NH, NB), 256>>>();
    k_mma_out<<<dim3(8, 8), 256>>>(bo, out);
}

// round 10
// speedup vs baseline: 1.9932x; 1.2027x over previous
#include <cuda_runtime.h>
#include <cuda_fp16.h>
#include <cstdint>

#define NH     16
#define DMODEL 1024
#define HDIM   64
#define NEMB   40001
#define NB     2
#define SEQ    512

// ---------------- device scratch ----------------
__device__ float g_Tx[NEMB * NH];
__device__ float g_Ty[NEMB * NH];
__device__ __half g_bias[(size_t)NB * NH * SEQ * SEQ];   // fp16 bias (16.7MB)

// fp16 hi/lo split operands
__device__ __half g_actH[3 * DMODEL * DMODEL];   // q,k,v activations [m][k]
__device__ __half g_actL[3 * DMODEL * DMODEL];
__device__ __half g_WtH[4 * DMODEL * DMODEL];    // Wq,Wk,Wv,Wo transposed [n][k] (hi only)
// projected Q/K/V in [b][h][seq][d], fp16 hi/lo (Q pre-scaled by 0.125)
__device__ __half g_QH[NB * NH * SEQ * HDIM], g_QL[NB * NH * SEQ * HDIM];
__device__ __half g_KH[NB * NH * SEQ * HDIM], g_KL[NB * NH * SEQ * HDIM];
__device__ __half g_VH[NB * NH * SEQ * HDIM];
// attention output hi/lo, [b*q][h*64+d] row-major 1024x1024
__device__ __half g_attH[DMODEL * DMODEL];
__device__ __half g_attL[DMODEL * DMODEL];

// ---------------- non-gated PTX helpers ----------------
__device__ __forceinline__ uint32_t smem_u32(const void* p) {
    uint32_t a;
    asm("{ .reg .u64 t; cvta.to.shared.u64 t, %1; cvt.u32.u64 %0, t; }" : "=r"(a) : "l"(p));
    return a;
}
__device__ __forceinline__ void cp_async16(uint32_t saddr, const void* gptr) {
    asm volatile("cp.async.cg.shared.global [%0], [%1], 16;" :: "r"(saddr), "l"(gptr) : "memory");
}
#define CP_COMMIT() asm volatile("cp.async.commit_group;" ::: "memory")
#define CP_WAIT(n)  asm volatile("cp.async.wait_group %0;" :: "n"(n) : "memory")

__device__ __forceinline__ void ldsm_x4(uint32_t* r, uint32_t addr) {
    asm volatile("ldmatrix.sync.aligned.m8n8.x4.shared.b16 {%0,%1,%2,%3}, [%4];"
                 : "=r"(r[0]), "=r"(r[1]), "=r"(r[2]), "=r"(r[3]) : "r"(addr));
}
__device__ __forceinline__ void ldsm_x2(uint32_t* r, uint32_t addr) {
    asm volatile("ldmatrix.sync.aligned.m8n8.x2.shared.b16 {%0,%1}, [%2];"
                 : "=r"(r[0]), "=r"(r[1]) : "r"(addr));
}
__device__ __forceinline__ void ldsm_x2_trans(uint32_t* r, uint32_t addr) {
    asm volatile("ldmatrix.sync.aligned.m8n8.x2.trans.shared.b16 {%0,%1}, [%2];"
                 : "=r"(r[0]), "=r"(r[1]) : "r"(addr));
}
__device__ __forceinline__ void mma16816(float* d, const uint32_t* a, const uint32_t* b) {
    asm volatile("mma.sync.aligned.m16n8k16.row.col.f32.f16.f16.f32 "
                 "{%0,%1,%2,%3}, {%4,%5,%6,%7}, {%8,%9}, {%0,%1,%2,%3};"
                 : "+f"(d[0]), "+f"(d[1]), "+f"(d[2]), "+f"(d[3])
                 : "r"(a[0]), "r"(a[1]), "r"(a[2]), "r"(a[3]), "r"(b[0]), "r"(b[1]));
}
// pack two floats into fp16x2 hi part + fp16x2 residual part
__device__ __forceinline__ void packhl(float a, float b, uint32_t& hh, uint32_t& ll) {
    __half2 h2 = __floats2half2_rn(a, b);
    float2 f = __half22float2(h2);
    __half2 l2 = __floats2half2_rn(a - f.x, b - f.y);
    hh = *reinterpret_cast<uint32_t*>(&h2);
    ll = *reinterpret_cast<uint32_t*>(&l2);
}

// ---------------- kernel 1: project embedding tables through Wb ----------------
__global__ __launch_bounds__(256) void k_project(const float* __restrict__ xt,
                                                 const float* __restrict__ yt,
                                                 const float* __restrict__ Wb) {
    int id = blockIdx.x * 256 + threadIdx.x;
    if (id >= 2 * NEMB * NH) return;
    int which = (id >= NEMB * NH);
    int rid = which ? id - NEMB * NH : id;
    int r = rid >> 4, h = rid & 15;
    const float4* row = (const float4*)((which ? yt : xt) + (size_t)r * 256 + h * 16);
    const float4* wb = (const float4*)Wb;
    float s = 0.f;
#pragma unroll
    for (int q = 0; q < 4; q++) {
        float4 v = row[q], w = wb[q];
        s += v.x * w.x + v.y * w.y + v.z * w.z + v.w * w.w;
    }
    (which ? g_Ty : g_Tx)[rid] = s;
}

// ---------------- kernel 2: positional bias (fp16 output) ----------------
__global__ __launch_bounds__(256) void k_bias(const float* __restrict__ qx,
                                              const float* __restrict__ qy,
                                              const float* __restrict__ kx,
                                              const float* __restrict__ ky,
                                              const float* __restrict__ bbp) {
    __shared__ float sm[16 * 256];
    int b = blockIdx.z;
    int i0 = blockIdx.y * 16, j0 = blockIdx.x * 16;
    int t = threadIdx.x;
    int i = i0 + (t >> 4), j = j0 + (t & 15);
    float bb = bbp[0];
    float dx = qx[b * SEQ + j] - kx[b * SEQ + i];
    float dy = qy[b * SEQ + j] - ky[b * SEQ + i];
    dx = fminf(fmaxf(dx, -1000.f), 1000.f);
    dy = fminf(fmaxf(dy, -1000.f), 1000.f);
    int ix = (int)rintf((dx + 1000.f) * 20.f);
    int iy = (int)rintf((dy + 1000.f) * 20.f);
    const float4* px = (const float4*)(g_Tx + (size_t)ix * 16);
    const float4* py = (const float4*)(g_Ty + (size_t)iy * 16);
#pragma unroll
    for (int q = 0; q < 4; q++) {
        float4 a = px[q], c = py[q];
        float v0 = a.x + c.x + bb, v1 = a.y + c.y + bb;
        float v2 = a.z + c.z + bb, v3 = a.w + c.w + bb;
        sm[(q * 4 + 0) * 256 + t] = 1.f / (1.f + __expf(-v0));
        sm[(q * 4 + 1) * 256 + t] = 1.f / (1.f + __expf(-v1));
        sm[(q * 4 + 2) * 256 + t] = 1.f / (1.f + __expf(-v2));
        sm[(q * 4 + 3) * 256 + t] = 1.f / (1.f + __expf(-v3));
    }
    __syncthreads();
    int h = t >> 4, w = t & 15;
#pragma unroll
    for (int ii = 0; ii < 16; ii++) {
        g_bias[(((size_t)(b * NH + h)) * SEQ + (i0 + ii)) * SEQ + (j0 + w)] =
            __float2half(sm[h * 256 + ii * 16 + w]);
    }
}

// ---------------- fp16 hi/lo split helpers ----------------
__device__ __forceinline__ void split4h(float4 x, __half2* ph, __half2* pl) {
    __half2 h01 = __floats2half2_rn(x.x, x.y);
    __half2 h23 = __floats2half2_rn(x.z, x.w);
    float2 f01 = __half22float2(h01), f23 = __half22float2(h23);
    ph[0] = h01; ph[1] = h23;
    pl[0] = __floats2half2_rn(x.x - f01.x, x.y - f01.y);
    pl[1] = __floats2half2_rn(x.z - f23.x, x.w - f23.y);
}

// ---------------- merged conversion kernel: activations + weights ----------------
__global__ __launch_bounds__(256) void k_conv(const float* __restrict__ q,
                                              const float* __restrict__ k,
                                              const float* __restrict__ v,
                                              const float* __restrict__ Wq,
                                              const float* __restrict__ Wk,
                                              const float* __restrict__ Wv,
                                              const float* __restrict__ Wo) {
    __shared__ float t[32][33];
    int bidx = blockIdx.x, tid = threadIdx.x;
    if (bidx < 3072) {
        int z = bidx >> 10;
        const float* src = (z == 0) ? q : (z == 1) ? k : v;
        __half* H = g_actH + (size_t)z * DMODEL * DMODEL;
        __half* L = g_actL + (size_t)z * DMODEL * DMODEL;
        int i = (bidx & 1023) * 256 + tid;
        float4 x = ((const float4*)src)[i];
        split4h(x, (__half2*)(H + (size_t)i * 4), (__half2*)(L + (size_t)i * 4));
    } else {
        int w = bidx - 3072;
        int z = w >> 10, rem = w & 1023;
        const float* W = (z == 0) ? Wq : (z == 1) ? Wk : (z == 2) ? Wv : Wo;
        __half* H = g_WtH + (size_t)z * DMODEL * DMODEL;
        int nb = (rem & 31) * 32, kb = (rem >> 5) * 32;
        int tx = tid & 31, ty = tid >> 5;   // 32 x 8
#pragma unroll
        for (int i = 0; i < 4; i++)
            t[ty + i * 8][tx] = W[(size_t)(kb + ty + i * 8) * DMODEL + nb + tx];
        __syncthreads();
#pragma unroll
        for (int i = 0; i < 4; i++) {
            int n = nb + ty + i * 8, kk = kb + tx;
            H[(size_t)n * DMODEL + kk] = __float2half(t[tx][ty + i * 8]);
        }
    }
}

// ---------------- warp-mma GEMM: C = (Ah+Al) @ Bh^T + bias ----------------
// 2-term fp16 split folded into one K=2048 GEMM (phases: AhBh, AlBh).
// BM=BN=64, BK=32, 128 threads, 4 warps (2m x 2n, warp tile 32x32),
// 3-stage cp.async pipeline. Small CTA -> ~4-5 resident CTAs/SM.
#define NKITER 64
#define STAGES 3

template <int MODE>
__device__ __forceinline__ void mma_body(const __half* __restrict__ Ah,
                                         const __half* __restrict__ Al,
                                         const __half* __restrict__ Bh,
                                         const float* __restrict__ bias,
                                         __half* __restrict__ OH,
                                         __half* __restrict__ OL,
                                         float* __restrict__ OF,
                                         float scale) {
    __shared__ __align__(1024) char smem[STAGES][8192];   // per stage: A 4KB | B 4KB
    int tid = threadIdx.x, lane = tid & 31, wid = tid >> 5;
    int wm = wid & 1, wn = wid >> 1;                  // 2 x 2 warp grid
    int m0 = blockIdx.y * 64, n0 = blockIdx.x * 64;
    uint32_t sbase = smem_u32(smem);

    float acc[2][4][4];
#pragma unroll
    for (int i = 0; i < 2; i++)
#pragma unroll
        for (int j = 0; j < 4; j++)
#pragma unroll
            for (int r = 0; r < 4; r++) acc[i][j][r] = 0.f;

    auto issue_tile = [&](int ki, int s) {
        int phase = ki >> 5;
        int kk = (ki & 31) * 32;
        const __half* Ap = phase ? Al : Ah;
        uint32_t sA = sbase + s * 8192, sB = sA + 4096;
#pragma unroll
        for (int j = 0; j < 2; j++) {
            int idx = tid + j * 128;                   // 256 chunks each for A, B
            int row = idx >> 2, c = idx & 3;
            int cs = c ^ ((row >> 1) & 3);
            cp_async16(sA + row * 64 + cs * 16, Ap + (size_t)(m0 + row) * DMODEL + kk + c * 8);
            cp_async16(sB + row * 64 + cs * 16, Bh + (size_t)(n0 + row) * DMODEL + kk + c * 8);
        }
        CP_COMMIT();
    };

    issue_tile(0, 0);
    issue_tile(1, 1);
    for (int ki = 0; ki < NKITER; ki++) {
        int s = ki % STAGES;
        if (ki + 1 < NKITER) { CP_WAIT(1); } else { CP_WAIT(0); }
        __syncthreads();
        if (ki + 2 < NKITER) issue_tile(ki + 2, (ki + 2) % STAGES);
        uint32_t sA = sbase + s * 8192, sB = sA + 4096;
#pragma unroll
        for (int kq = 0; kq < 2; kq++) {
            uint32_t af[2][4], bf[4][2];
#pragma unroll
            for (int im = 0; im < 2; im++) {
                int row = wm * 32 + im * 16 + (lane & 15);
                int c = kq * 2 + (lane >> 4);
                int cs = c ^ ((row >> 1) & 3);
                ldsm_x4(af[im], sA + row * 64 + cs * 16);
            }
#pragma unroll
            for (int jn = 0; jn < 4; jn++) {
                int row = wn * 32 + jn * 8 + (lane & 7);
                int c = kq * 2 + ((lane >> 3) & 1);
                int cs = c ^ ((row >> 1) & 3);
                ldsm_x2(bf[jn], sB + row * 64 + cs * 16);
            }
#pragma unroll
            for (int im = 0; im < 2; im++)
#pragma unroll
                for (int jn = 0; jn < 4; jn++) mma16816(acc[im][jn], af[im], bf[jn]);
        }
    }

    // epilogue
#pragma unroll
    for (int im = 0; im < 2; im++) {
#pragma unroll
        for (int jn = 0; jn < 4; jn++) {
            int col = n0 + wn * 32 + jn * 8 + 2 * (lane & 3);
            float b0 = bias[col], b1 = bias[col + 1];
#pragma unroll
            for (int half = 0; half < 2; half++) {
                int m = m0 + wm * 32 + im * 16 + (lane >> 2) + half * 8;
                float v0 = (acc[im][jn][half * 2 + 0] + b0) * scale;
                float v1 = (acc[im][jn][half * 2 + 1] + b1) * scale;
                if (MODE == 0) {
                    int bidx = m >> 9, nseq = m & 511;
                    int h = col >> 6, d = col & 63;
                    size_t idx = (((size_t)(bidx * NH + h)) * SEQ + nseq) * HDIM + d;
                    uint32_t hh, ll;
                    packhl(v0, v1, hh, ll);
                    *(uint32_t*)(OH + idx) = hh;
                    if (OL) *(uint32_t*)(OL + idx) = ll;
                } else {
                    *(float2*)(OF + (size_t)m * DMODEL + col) = make_float2(v0, v1);
                }
            }
        }
    }
}

__global__ __launch_bounds__(128) void k_mma_qkv(const float* __restrict__ bq,
                                                 const float* __restrict__ bk,
                                                 const float* __restrict__ bv) {
    int z = blockIdx.z;
    const __half* Ah = g_actH + (size_t)z * DMODEL * DMODEL;
    const __half* Al = g_actL + (size_t)z * DMODEL * DMODEL;
    const __half* Bh = g_WtH + (size_t)z * DMODEL * DMODEL;
    const float* bias = (z == 0) ? bq : (z == 1) ? bk : bv;
    __half* OH = (z == 0) ? g_QH : (z == 1) ? g_KH : g_VH;
    __half* OL = (z == 0) ? g_QL : (z == 1) ? g_KL : nullptr;   // V needs hi only
    float scale = (z == 0) ? 0.125f : 1.0f;
    mma_body<0>(Ah, Al, Bh, bias, OH, OL, nullptr, scale);
}

__global__ __launch_bounds__(128) void k_mma_out(const float* __restrict__ bo,
                                                 float* __restrict__ out) {
    mma_body<1>(g_attH, g_attL, g_WtH + (size_t)3 * DMODEL * DMODEL,
                bo, nullptr, nullptr, out, 1.0f);
}

// ---------------- tensor-core flash attention, 8 warps, fixed-max softmax ----------------
__global__ __launch_bounds__(256) void k_attn() {
    __shared__ __align__(1024) char smbuf[40960];
    uint32_t sQH = smem_u32(smbuf), sQL = sQH + 8192;
    uint32_t sKH = sQH + 16384, sKL = sQH + 24576;
    uint32_t sVH = sQH + 32768;
    int b = blockIdx.z, h = blockIdx.y, q0 = blockIdx.x * 64;
    int tid = threadIdx.x, lane = tid & 31, wid = tid >> 5;
    int wq = wid & 3, g = wid >> 2;
    size_t hb = (size_t)(b * NH + h) * SEQ * HDIM;
    const __half *QHp = g_QH + hb, *QLp = g_QL + hb;
    const __half *KHp = g_KH + hb, *KLp = g_KL + hb;
    const __half *VHp = g_VH + hb;
    const __half* Bg = g_bias + ((size_t)(b * NH + h) * SEQ + q0) * SEQ;

#pragma unroll
    for (int u = 0; u < 2; u++) {
        int idx = u * 256 + tid;
        int row = idx >> 3, c = idx & 7, cs = c ^ (row & 7);
        size_t go = (size_t)(q0 + row) * HDIM + c * 8;
        cp_async16(sQH + row * 128 + cs * 16, QHp + go);
        cp_async16(sQL + row * 128 + cs * 16, QLp + go);
    }
    CP_COMMIT();
    CP_WAIT(0);
    __syncthreads();

    uint32_t qh[4][4], ql[4][4];
#pragma unroll
    for (int kk = 0; kk < 4; kk++) {
        int row = wq * 16 + (lane & 15);
        int c = kk * 2 + (lane >> 4), cs = c ^ (row & 7);
        ldsm_x4(qh[kk], sQH + row * 128 + cs * 16);
        ldsm_x4(ql[kk], sQL + row * 128 + cs * 16);
    }

    float o[8][4];
#pragma unroll
    for (int j = 0; j < 8; j++)
#pragma unroll
        for (int r = 0; r < 4; r++) o[j][r] = 0.f;
    float lA = 0.f, lB = 0.f;
    int br0 = wq * 16 + (lane >> 2);
    int bc = 2 * (lane & 3);
    int goff = g * 32;

    for (int k0 = 0; k0 < SEQ; k0 += 64) {
        __syncthreads();
#pragma unroll
        for (int u = 0; u < 2; u++) {
            int idx = u * 256 + tid;
            int row = idx >> 3, c = idx & 7, cs = c ^ (row & 7);
            size_t go = (size_t)(k0 + row) * HDIM + c * 8;
            cp_async16(sKH + row * 128 + cs * 16, KHp + go);
            cp_async16(sKL + row * 128 + cs * 16, KLp + go);
            cp_async16(sVH + row * 128 + cs * 16, VHp + go);
        }
        CP_COMMIT();
        float2 bias0[4], bias1[4];
#pragma unroll
        for (int jt = 0; jt < 4; jt++) {
            __half2 t0 = *(const __half2*)(Bg + (size_t)br0 * SEQ + k0 + goff + jt * 8 + bc);
            __half2 t1 = *(const __half2*)(Bg + (size_t)(br0 + 8) * SEQ + k0 + goff + jt * 8 + bc);
            bias0[jt] = __half22float2(t0);
            bias1[jt] = __half22float2(t1);
        }
        CP_WAIT(0);
        __syncthreads();

        float s[4][4];
#pragma unroll
        for (int jt = 0; jt < 4; jt++) {
            s[jt][0] = s[jt][1] = s[jt][2] = s[jt][3] = 0.f;
#pragma unroll
            for (int kk = 0; kk < 4; kk++) {
                uint32_t kh[2], kl[2];
                int row = goff + jt * 8 + (lane & 7);
                int c = kk * 2 + ((lane >> 3) & 1), cs = c ^ (row & 7);
                ldsm_x2(kh, sKH + row * 128 + cs * 16);
                ldsm_x2(kl, sKL + row * 128 + cs * 16);
                mma16816(s[jt], qh[kk], kh);
                mma16816(s[jt], ql[kk], kh);
                mma16816(s[jt], qh[kk], kl);
            }
        }

#pragma unroll
        for (int jt = 0; jt < 4; jt++) {
            s[jt][0] = __expf(s[jt][0] + bias0[jt].x);
            s[jt][1] = __expf(s[jt][1] + bias0[jt].y);
            s[jt][2] = __expf(s[jt][2] + bias1[jt].x);
            s[jt][3] = __expf(s[jt][3] + bias1[jt].y);
            lA += s[jt][0] + s[jt][1];
            lB += s[jt][2] + s[jt][3];
        }

        uint32_t ph[2][4], pl[2][4];
#pragma unroll
        for (int kk = 0; kk < 2; kk++) {
            packhl(s[2 * kk][0], s[2 * kk][1], ph[kk][0], pl[kk][0]);
            packhl(s[2 * kk][2], s[2 * kk][3], ph[kk][1], pl[kk][1]);
            packhl(s[2 * kk + 1][0], s[2 * kk + 1][1], ph[kk][2], pl[kk][2]);
            packhl(s[2 * kk + 1][2], s[2 * kk + 1][3], ph[kk][3], pl[kk][3]);
        }

#pragma unroll
        for (int kk = 0; kk < 2; kk++) {
#pragma unroll
            for (int j = 0; j < 8; j++) {
                uint32_t vh[2];
                int row = goff + kk * 16 + (lane & 15);
                int cs = j ^ (row & 7);
                ldsm_x2_trans(vh, sVH + row * 128 + cs * 16);
                mma16816(o[j], ph[kk], vh);
                mma16816(o[j], pl[kk], vh);
            }
        }
    }

    lA += __shfl_xor_sync(0xffffffffu, lA, 1);
    lA += __shfl_xor_sync(0xffffffffu, lA, 2);
    lB += __shfl_xor_sync(0xffffffffu, lB, 1);
    lB += __shfl_xor_sync(0xffffffffu, lB, 2);

    float* scr = (float*)(smbuf + 16384);
    float* sml = (float*)(smbuf + 32768);
    __syncthreads();
    if (g == 1) {
#pragma unroll
        for (int j = 0; j < 8; j++) {
            scr[br0 * 64 + j * 8 + bc] = o[j][0];
            scr[br0 * 64 + j * 8 + bc + 1] = o[j][1];
            scr[(br0 + 8) * 64 + j * 8 + bc] = o[j][2];
            scr[(br0 + 8) * 64 + j * 8 + bc + 1] = o[j][3];
        }
        if ((lane & 3) == 0) {
            sml[br0] = lA;
            sml[br0 + 8] = lB;
        }
    }
    __syncthreads();
    if (g == 0) {
        float r0 = 1.f / (lA + sml[br0]);
        float r1 = 1.f / (lB + sml[br0 + 8]);
        int rq0 = q0 + br0;
#pragma unroll
        for (int j = 0; j < 8; j++) {
            float v0 = (o[j][0] + scr[br0 * 64 + j * 8 + bc]) * r0;
            float v1 = (o[j][1] + scr[br0 * 64 + j * 8 + bc + 1]) * r0;
            float v2 = (o[j][2] + scr[(br0 + 8) * 64 + j * 8 + bc]) * r1;
            float v3 = (o[j][3] + scr[(br0 + 8) * 64 + j * 8 + bc + 1]) * r1;
            size_t i0 = ((size_t)(b * SEQ + rq0) * NH + h) * HDIM + j * 8 + bc;
            size_t i1 = ((size_t)(b * SEQ + rq0 + 8) * NH + h) * HDIM + j * 8 + bc;
            uint32_t hh, ll;
            packhl(v0, v1, hh, ll);
            *(uint32_t*)(g_attH + i0) = hh;
            *(uint32_t*)(g_attL + i0) = ll;
            packhl(v2, v3, hh, ll);
            *(uint32_t*)(g_attH + i1) = hh;
            *(uint32_t*)(g_attL + i1) = ll;
        }
    }
}

// ---------------- launch: two-stream fork/join for graph-level overlap ----------------
extern "C" void kernel_launch(void* const* d_in, const int* in_sizes, int n_in,
                              void* d_out, int out_size) {
    (void)in_sizes; (void)n_in; (void)out_size;
    const float* query = (const float*)d_in[0];
    const float* key   = (const float*)d_in[1];
    const float* value = (const float*)d_in[2];
    const float* qx    = (const float*)d_in[3];
    const float* qy    = (const float*)d_in[4];
    const float* kx    = (const float*)d_in[5];
    const float* ky    = (const float*)d_in[6];
    const float* Wq    = (const float*)d_in[7];
    const float* bq    = (const float*)d_in[8];
    const float* Wk    = (const float*)d_in[9];
    const float* bk    = (const float*)d_in[10];
    const float* Wv    = (const float*)d_in[11];
    const float* bv    = (const float*)d_in[12];
    const float* Wo    = (const float*)d_in[13];
    const float* bo    = (const float*)d_in[14];
    const float* xt    = (const float*)d_in[15];
    const float* yt    = (const float*)d_in[16];
    const float* Wb    = (const float*)d_in[17];
    const float* bb    = (const float*)d_in[18];
    float* out = (float*)d_out;

    static cudaStream_t s1 = nullptr;
    static cudaEvent_t eFork = nullptr, eJoin = nullptr;
    if (!s1) {
        cudaStreamCreateWithFlags(&s1, cudaStreamNonBlocking);
        cudaEventCreateWithFlags(&eFork, cudaEventDisableTiming);
        cudaEventCreateWithFlags(&eJoin, cudaEventDisableTiming);
    }

    // fork: side stream runs the memory-bound bias chain
    cudaEventRecord(eFork, 0);
    cudaStreamWaitEvent(s1, eFork, 0);
    k_project<<<(2 * NEMB * NH + 255) / 256, 256, 0, s1>>>(xt, yt, Wb);
    k_bias<<<dim3(SEQ / 16, SEQ / 16, NB), 256, 0, s1>>>(qx, qy, kx, ky, bb);
    cudaEventRecord(eJoin, s1);

    // main stream: mma-bound projection chain (overlaps with bias chain)
    k_conv<<<7168, 256>>>(query, key, value, Wq, Wk, Wv, Wo);
    k_mma_qkv<<<dim3(DMODEL / 64, (NB * SEQ) / 64, 3), 128>>>(bq, bk, bv);

    // join: attention needs both chains
    cudaStreamWaitEvent(0, eJoin, 0);
    k_attn<<<dim3(SEQ / 64, NH, NB), 256>>>();
    k_mma_out<<<dim3(DMODEL / 64, DMODEL / 64), 128>>>(bo, out);
}

// round 11
// speedup vs baseline: 2.1267x; 1.0670x over previous
#include <cuda_runtime.h>
#include <cuda_fp16.h>
#include <cstdint>

#define NH     16
#define DMODEL 1024
#define HDIM   64
#define NEMB   40001
#define NB     2
#define SEQ    512

// ---------------- device scratch ----------------
__device__ float g_Tx[NEMB * NH];
__device__ float g_Ty[NEMB * NH];
__device__ __half g_bias[(size_t)NB * NH * SEQ * SEQ];   // fp16 bias (16.7MB)

// fp16 hi/lo split operands
__device__ __half g_actH[3 * DMODEL * DMODEL];   // q,k,v activations [m][k]
__device__ __half g_actL[3 * DMODEL * DMODEL];
__device__ __half g_WtH[4 * DMODEL * DMODEL];    // Wq,Wk,Wv,Wo transposed [n][k] (hi only)
// projected Q/K/V in [b][h][seq][d], fp16 hi/lo (Q pre-scaled by 0.125)
__device__ __half g_QH[NB * NH * SEQ * HDIM], g_QL[NB * NH * SEQ * HDIM];
__device__ __half g_KH[NB * NH * SEQ * HDIM], g_KL[NB * NH * SEQ * HDIM];
__device__ __half g_VH[NB * NH * SEQ * HDIM];
// attention output hi/lo, [b*q][h*64+d] row-major 1024x1024
__device__ __half g_attH[DMODEL * DMODEL];
__device__ __half g_attL[DMODEL * DMODEL];

// ---------------- non-gated PTX helpers ----------------
__device__ __forceinline__ uint32_t smem_u32(const void* p) {
    uint32_t a;
    asm("{ .reg .u64 t; cvta.to.shared.u64 t, %1; cvt.u32.u64 %0, t; }" : "=r"(a) : "l"(p));
    return a;
}
__device__ __forceinline__ void cp_async16(uint32_t saddr, const void* gptr) {
    asm volatile("cp.async.cg.shared.global [%0], [%1], 16;" :: "r"(saddr), "l"(gptr) : "memory");
}
#define CP_COMMIT() asm volatile("cp.async.commit_group;" ::: "memory")
#define CP_WAIT(n)  asm volatile("cp.async.wait_group %0;" :: "n"(n) : "memory")

__device__ __forceinline__ void ldsm_x4(uint32_t* r, uint32_t addr) {
    asm volatile("ldmatrix.sync.aligned.m8n8.x4.shared.b16 {%0,%1,%2,%3}, [%4];"
                 : "=r"(r[0]), "=r"(r[1]), "=r"(r[2]), "=r"(r[3]) : "r"(addr));
}
__device__ __forceinline__ void ldsm_x2(uint32_t* r, uint32_t addr) {
    asm volatile("ldmatrix.sync.aligned.m8n8.x2.shared.b16 {%0,%1}, [%2];"
                 : "=r"(r[0]), "=r"(r[1]) : "r"(addr));
}
__device__ __forceinline__ void ldsm_x2_trans(uint32_t* r, uint32_t addr) {
    asm volatile("ldmatrix.sync.aligned.m8n8.x2.trans.shared.b16 {%0,%1}, [%2];"
                 : "=r"(r[0]), "=r"(r[1]) : "r"(addr));
}
__device__ __forceinline__ void mma16816(float* d, const uint32_t* a, const uint32_t* b) {
    asm volatile("mma.sync.aligned.m16n8k16.row.col.f32.f16.f16.f32 "
                 "{%0,%1,%2,%3}, {%4,%5,%6,%7}, {%8,%9}, {%0,%1,%2,%3};"
                 : "+f"(d[0]), "+f"(d[1]), "+f"(d[2]), "+f"(d[3])
                 : "r"(a[0]), "r"(a[1]), "r"(a[2]), "r"(a[3]), "r"(b[0]), "r"(b[1]));
}
// pack two floats into fp16x2 hi part + fp16x2 residual part
__device__ __forceinline__ void packhl(float a, float b, uint32_t& hh, uint32_t& ll) {
    __half2 h2 = __floats2half2_rn(a, b);
    float2 f = __half22float2(h2);
    __half2 l2 = __floats2half2_rn(a - f.x, b - f.y);
    hh = *reinterpret_cast<uint32_t*>(&h2);
    ll = *reinterpret_cast<uint32_t*>(&l2);
}

// ---------------- kernel 1: project embedding tables through Wb ----------------
__global__ __launch_bounds__(256) void k_project(const float* __restrict__ xt,
                                                 const float* __restrict__ yt,
                                                 const float* __restrict__ Wb) {
    int id = blockIdx.x * 256 + threadIdx.x;
    if (id >= 2 * NEMB * NH) return;
    int which = (id >= NEMB * NH);
    int rid = which ? id - NEMB * NH : id;
    int r = rid >> 4, h = rid & 15;
    const float4* row = (const float4*)((which ? yt : xt) + (size_t)r * 256 + h * 16);
    const float4* wb = (const float4*)Wb;
    float s = 0.f;
#pragma unroll
    for (int q = 0; q < 4; q++) {
        float4 v = row[q], w = wb[q];
        s += v.x * w.x + v.y * w.y + v.z * w.z + v.w * w.w;
    }
    (which ? g_Ty : g_Tx)[rid] = s;
}

// ---------------- kernel 2: positional bias (fp16 output) ----------------
__global__ __launch_bounds__(256) void k_bias(const float* __restrict__ qx,
                                              const float* __restrict__ qy,
                                              const float* __restrict__ kx,
                                              const float* __restrict__ ky,
                                              const float* __restrict__ bbp) {
    __shared__ float sm[16 * 256];
    int b = blockIdx.z;
    int i0 = blockIdx.y * 16, j0 = blockIdx.x * 16;
    int t = threadIdx.x;
    int i = i0 + (t >> 4), j = j0 + (t & 15);
    float bb = bbp[0];
    float dx = qx[b * SEQ + j] - kx[b * SEQ + i];
    float dy = qy[b * SEQ + j] - ky[b * SEQ + i];
    dx = fminf(fmaxf(dx, -1000.f), 1000.f);
    dy = fminf(fmaxf(dy, -1000.f), 1000.f);
    int ix = (int)rintf((dx + 1000.f) * 20.f);
    int iy = (int)rintf((dy + 1000.f) * 20.f);
    const float4* px = (const float4*)(g_Tx + (size_t)ix * 16);
    const float4* py = (const float4*)(g_Ty + (size_t)iy * 16);
#pragma unroll
    for (int q = 0; q < 4; q++) {
        float4 a = px[q], c = py[q];
        float v0 = a.x + c.x + bb, v1 = a.y + c.y + bb;
        float v2 = a.z + c.z + bb, v3 = a.w + c.w + bb;
        sm[(q * 4 + 0) * 256 + t] = 1.f / (1.f + __expf(-v0));
        sm[(q * 4 + 1) * 256 + t] = 1.f / (1.f + __expf(-v1));
        sm[(q * 4 + 2) * 256 + t] = 1.f / (1.f + __expf(-v2));
        sm[(q * 4 + 3) * 256 + t] = 1.f / (1.f + __expf(-v3));
    }
    __syncthreads();
    int h = t >> 4, w = t & 15;
#pragma unroll
    for (int ii = 0; ii < 16; ii++) {
        g_bias[(((size_t)(b * NH + h)) * SEQ + (i0 + ii)) * SEQ + (j0 + w)] =
            __float2half(sm[h * 256 + ii * 16 + w]);
    }
}

// ---------------- fp16 hi/lo split helpers ----------------
__device__ __forceinline__ void split4h(float4 x, __half2* ph, __half2* pl) {
    __half2 h01 = __floats2half2_rn(x.x, x.y);
    __half2 h23 = __floats2half2_rn(x.z, x.w);
    float2 f01 = __half22float2(h01), f23 = __half22float2(h23);
    ph[0] = h01; ph[1] = h23;
    pl[0] = __floats2half2_rn(x.x - f01.x, x.y - f01.y);
    pl[1] = __floats2half2_rn(x.z - f23.x, x.w - f23.y);
}

// ---------------- merged conversion kernel: activations + weights ----------------
__global__ __launch_bounds__(256) void k_conv(const float* __restrict__ q,
                                              const float* __restrict__ k,
                                              const float* __restrict__ v,
                                              const float* __restrict__ Wq,
                                              const float* __restrict__ Wk,
                                              const float* __restrict__ Wv,
                                              const float* __restrict__ Wo) {
    __shared__ float t[32][33];
    int bidx = blockIdx.x, tid = threadIdx.x;
    if (bidx < 3072) {
        int z = bidx >> 10;
        const float* src = (z == 0) ? q : (z == 1) ? k : v;
        __half* H = g_actH + (size_t)z * DMODEL * DMODEL;
        __half* L = g_actL + (size_t)z * DMODEL * DMODEL;
        int i = (bidx & 1023) * 256 + tid;
        float4 x = ((const float4*)src)[i];
        split4h(x, (__half2*)(H + (size_t)i * 4), (__half2*)(L + (size_t)i * 4));
    } else {
        int w = bidx - 3072;
        int z = w >> 10, rem = w & 1023;
        const float* W = (z == 0) ? Wq : (z == 1) ? Wk : (z == 2) ? Wv : Wo;
        __half* H = g_WtH + (size_t)z * DMODEL * DMODEL;
        int nb = (rem & 31) * 32, kb = (rem >> 5) * 32;
        int tx = tid & 31, ty = tid >> 5;   // 32 x 8
#pragma unroll
        for (int i = 0; i < 4; i++)
            t[ty + i * 8][tx] = W[(size_t)(kb + ty + i * 8) * DMODEL + nb + tx];
        __syncthreads();
#pragma unroll
        for (int i = 0; i < 4; i++) {
            int n = nb + ty + i * 8, kk = kb + tx;
            H[(size_t)n * DMODEL + kk] = __float2half(t[tx][ty + i * 8]);
        }
    }
}

// ---------------- warp-mma GEMM: C = (Ah+Al) @ Bh^T + bias ----------------
// 2-term fp16 split folded into one K=2048 GEMM (phases: AhBh, AlBh).
// BM=BN=64, BK=64, 128 threads, 4 warps (2m x 2n, warp tile 32x32),
// 2-stage cp.async pipeline, B fragments via batched ldsm_x4.
#define NKITER 32

template <int MODE>
__device__ __forceinline__ void mma_body(const __half* __restrict__ Ah,
                                         const __half* __restrict__ Al,
                                         const __half* __restrict__ Bh,
                                         const float* __restrict__ bias,
                                         __half* __restrict__ OH,
                                         __half* __restrict__ OL,
                                         float* __restrict__ OF,
                                         float scale) {
    __shared__ __align__(1024) char smem[2][16384];   // per stage: A 8KB | B 8KB
    int tid = threadIdx.x, lane = tid & 31, wid = tid >> 5;
    int wm = wid & 1, wn = wid >> 1;                  // 2 x 2 warp grid
    int m0 = blockIdx.y * 64, n0 = blockIdx.x * 64;
    uint32_t sbase = smem_u32(smem);

    float acc[2][4][4];
#pragma unroll
    for (int i = 0; i < 2; i++)
#pragma unroll
        for (int j = 0; j < 4; j++)
#pragma unroll
            for (int r = 0; r < 4; r++) acc[i][j][r] = 0.f;

    auto issue_tile = [&](int ki, int s) {
        int phase = ki >> 4;
        int kk = (ki & 15) * 64;
        const __half* Ap = phase ? Al : Ah;
        uint32_t sA = sbase + s * 16384, sB = sA + 8192;
#pragma unroll
        for (int j = 0; j < 4; j++) {
            int idx = tid + j * 128;                   // 512 chunks each for A, B
            int row = idx >> 3, c = idx & 7;
            int cs = c ^ (row & 7);
            cp_async16(sA + row * 128 + cs * 16, Ap + (size_t)(m0 + row) * DMODEL + kk + c * 8);
            cp_async16(sB + row * 128 + cs * 16, Bh + (size_t)(n0 + row) * DMODEL + kk + c * 8);
        }
        CP_COMMIT();
    };

    issue_tile(0, 0);
    for (int ki = 0; ki < NKITER; ki++) {
        int s = ki & 1;
        if (ki + 1 < NKITER) {
            issue_tile(ki + 1, s ^ 1);
            CP_WAIT(1);
        } else {
            CP_WAIT(0);
        }
        __syncthreads();
        uint32_t sA = sbase + s * 16384, sB = sA + 8192;
#pragma unroll
        for (int kq = 0; kq < 4; kq++) {
            uint32_t af[2][4], bf[4][4];   // bf[jnp][0..3] = two n-tiles' frags
#pragma unroll
            for (int im = 0; im < 2; im++) {
                int row = wm * 32 + im * 16 + (lane & 15);
                int c = kq * 2 + (lane >> 4);
                int cs = c ^ (row & 7);
                ldsm_x4(af[im], sA + row * 128 + cs * 16);
            }
#pragma unroll
            for (int jnp = 0; jnp < 2; jnp++) {
                int mat = lane >> 3;                         // 0..3
                int jn2 = jnp * 2 + (mat >> 1);              // n-tile index
                int cc = kq * 2 + (mat & 1);                 // k-chunk
                int row = wn * 32 + jn2 * 8 + (lane & 7);
                int cs = cc ^ (row & 7);
                ldsm_x4(bf[jnp * 2], sB + row * 128 + cs * 16);
                // bf[jnp*2][0..1] = n-tile jnp*2, bf[jnp*2][2..3] = n-tile jnp*2+1
            }
#pragma unroll
            for (int im = 0; im < 2; im++) {
#pragma unroll
                for (int jnp = 0; jnp < 2; jnp++) {
                    mma16816(acc[im][jnp * 2 + 0], af[im], &bf[jnp * 2][0]);
                    mma16816(acc[im][jnp * 2 + 1], af[im], &bf[jnp * 2][2]);
                }
            }
        }
        __syncthreads();   // all reads of stage s done before it is refilled
    }

    // epilogue
#pragma unroll
    for (int im = 0; im < 2; im++) {
#pragma unroll
        for (int jn = 0; jn < 4; jn++) {
            int col = n0 + wn * 32 + jn * 8 + 2 * (lane & 3);
            float b0 = bias[col], b1 = bias[col + 1];
#pragma unroll
            for (int half = 0; half < 2; half++) {
                int m = m0 + wm * 32 + im * 16 + (lane >> 2) + half * 8;
                float v0 = (acc[im][jn][half * 2 + 0] + b0) * scale;
                float v1 = (acc[im][jn][half * 2 + 1] + b1) * scale;
                if (MODE == 0) {
                    int bidx = m >> 9, nseq = m & 511;
                    int h = col >> 6, d = col & 63;
                    size_t idx = (((size_t)(bidx * NH + h)) * SEQ + nseq) * HDIM + d;
                    uint32_t hh, ll;
                    packhl(v0, v1, hh, ll);
                    *(uint32_t*)(OH + idx) = hh;
                    if (OL) *(uint32_t*)(OL + idx) = ll;
                } else {
                    *(float2*)(OF + (size_t)m * DMODEL + col) = make_float2(v0, v1);
                }
            }
        }
    }
}

__global__ __launch_bounds__(128) void k_mma_qkv(const float* __restrict__ bq,
                                                 const float* __restrict__ bk,
                                                 const float* __restrict__ bv) {
    int z = blockIdx.z;
    const __half* Ah = g_actH + (size_t)z * DMODEL * DMODEL;
    const __half* Al = g_actL + (size_t)z * DMODEL * DMODEL;
    const __half* Bh = g_WtH + (size_t)z * DMODEL * DMODEL;
    const float* bias = (z == 0) ? bq : (z == 1) ? bk : bv;
    __half* OH = (z == 0) ? g_QH : (z == 1) ? g_KH : g_VH;
    __half* OL = (z == 0) ? g_QL : (z == 1) ? g_KL : nullptr;   // V needs hi only
    float scale = (z == 0) ? 0.125f : 1.0f;
    mma_body<0>(Ah, Al, Bh, bias, OH, OL, nullptr, scale);
}

__global__ __launch_bounds__(128) void k_mma_out(const float* __restrict__ bo,
                                                 float* __restrict__ out) {
    mma_body<1>(g_attH, g_attL, g_WtH + (size_t)3 * DMODEL * DMODEL,
                bo, nullptr, nullptr, out, 1.0f);
}

// ---------------- tensor-core flash attention, 8 warps, fixed-max softmax ----------------
__global__ __launch_bounds__(256) void k_attn() {
    __shared__ __align__(1024) char smbuf[40960];
    uint32_t sQH = smem_u32(smbuf), sQL = sQH + 8192;
    uint32_t sKH = sQH + 16384, sKL = sQH + 24576;
    uint32_t sVH = sQH + 32768;
    int b = blockIdx.z, h = blockIdx.y, q0 = blockIdx.x * 64;
    int tid = threadIdx.x, lane = tid & 31, wid = tid >> 5;
    int wq = wid & 3, g = wid >> 2;
    size_t hb = (size_t)(b * NH + h) * SEQ * HDIM;
    const __half *QHp = g_QH + hb, *QLp = g_QL + hb;
    const __half *KHp = g_KH + hb, *KLp = g_KL + hb;
    const __half *VHp = g_VH + hb;
    const __half* Bg = g_bias + ((size_t)(b * NH + h) * SEQ + q0) * SEQ;

#pragma unroll
    for (int u = 0; u < 2; u++) {
        int idx = u * 256 + tid;
        int row = idx >> 3, c = idx & 7, cs = c ^ (row & 7);
        size_t go = (size_t)(q0 + row) * HDIM + c * 8;
        cp_async16(sQH + row * 128 + cs * 16, QHp + go);
        cp_async16(sQL + row * 128 + cs * 16, QLp + go);
    }
    CP_COMMIT();
    CP_WAIT(0);
    __syncthreads();

    uint32_t qh[4][4], ql[4][4];
#pragma unroll
    for (int kk = 0; kk < 4; kk++) {
        int row = wq * 16 + (lane & 15);
        int c = kk * 2 + (lane >> 4), cs = c ^ (row & 7);
        ldsm_x4(qh[kk], sQH + row * 128 + cs * 16);
        ldsm_x4(ql[kk], sQL + row * 128 + cs * 16);
    }

    float o[8][4];
#pragma unroll
    for (int j = 0; j < 8; j++)
#pragma unroll
        for (int r = 0; r < 4; r++) o[j][r] = 0.f;
    float lA = 0.f, lB = 0.f;
    int br0 = wq * 16 + (lane >> 2);
    int bc = 2 * (lane & 3);
    int goff = g * 32;

    for (int k0 = 0; k0 < SEQ; k0 += 64) {
        __syncthreads();
#pragma unroll
        for (int u = 0; u < 2; u++) {
            int idx = u * 256 + tid;
            int row = idx >> 3, c = idx & 7, cs = c ^ (row & 7);
            size_t go = (size_t)(k0 + row) * HDIM + c * 8;
            cp_async16(sKH + row * 128 + cs * 16, KHp + go);
            cp_async16(sKL + row * 128 + cs * 16, KLp + go);
            cp_async16(sVH + row * 128 + cs * 16, VHp + go);
        }
        CP_COMMIT();
        float2 bias0[4], bias1[4];
#pragma unroll
        for (int jt = 0; jt < 4; jt++) {
            __half2 t0 = *(const __half2*)(Bg + (size_t)br0 * SEQ + k0 + goff + jt * 8 + bc);
            __half2 t1 = *(const __half2*)(Bg + (size_t)(br0 + 8) * SEQ + k0 + goff + jt * 8 + bc);
            bias0[jt] = __half22float2(t0);
            bias1[jt] = __half22float2(t1);
        }
        CP_WAIT(0);
        __syncthreads();

        float s[4][4];
#pragma unroll
        for (int jt = 0; jt < 4; jt++) {
            s[jt][0] = s[jt][1] = s[jt][2] = s[jt][3] = 0.f;
#pragma unroll
            for (int kk = 0; kk < 4; kk++) {
                uint32_t kh[2], kl[2];
                int row = goff + jt * 8 + (lane & 7);
                int c = kk * 2 + ((lane >> 3) & 1), cs = c ^ (row & 7);
                ldsm_x2(kh, sKH + row * 128 + cs * 16);
                ldsm_x2(kl, sKL + row * 128 + cs * 16);
                mma16816(s[jt], qh[kk], kh);
                mma16816(s[jt], ql[kk], kh);
                mma16816(s[jt], qh[kk], kl);
            }
        }

#pragma unroll
        for (int jt = 0; jt < 4; jt++) {
            s[jt][0] = __expf(s[jt][0] + bias0[jt].x);
            s[jt][1] = __expf(s[jt][1] + bias0[jt].y);
            s[jt][2] = __expf(s[jt][2] + bias1[jt].x);
            s[jt][3] = __expf(s[jt][3] + bias1[jt].y);
            lA += s[jt][0] + s[jt][1];
            lB += s[jt][2] + s[jt][3];
        }

        uint32_t ph[2][4], pl[2][4];
#pragma unroll
        for (int kk = 0; kk < 2; kk++) {
            packhl(s[2 * kk][0], s[2 * kk][1], ph[kk][0], pl[kk][0]);
            packhl(s[2 * kk][2], s[2 * kk][3], ph[kk][1], pl[kk][1]);
            packhl(s[2 * kk + 1][0], s[2 * kk + 1][1], ph[kk][2], pl[kk][2]);
            packhl(s[2 * kk + 1][2], s[2 * kk + 1][3], ph[kk][3], pl[kk][3]);
        }

#pragma unroll
        for (int kk = 0; kk < 2; kk++) {
#pragma unroll
            for (int j = 0; j < 8; j++) {
                uint32_t vh[2];
                int row = goff + kk * 16 + (lane & 15);
                int cs = j ^ (row & 7);
                ldsm_x2_trans(vh, sVH + row * 128 + cs * 16);
                mma16816(o[j], ph[kk], vh);
                mma16816(o[j], pl[kk], vh);
            }
        }
    }

    lA += __shfl_xor_sync(0xffffffffu, lA, 1);
    lA += __shfl_xor_sync(0xffffffffu, lA, 2);
    lB += __shfl_xor_sync(0xffffffffu, lB, 1);
    lB += __shfl_xor_sync(0xffffffffu, lB, 2);

    float* scr = (float*)(smbuf + 16384);
    float* sml = (float*)(smbuf + 32768);
    __syncthreads();
    if (g == 1) {
#pragma unroll
        for (int j = 0; j < 8; j++) {
            scr[br0 * 64 + j * 8 + bc] = o[j][0];
            scr[br0 * 64 + j * 8 + bc + 1] = o[j][1];
            scr[(br0 + 8) * 64 + j * 8 + bc] = o[j][2];
            scr[(br0 + 8) * 64 + j * 8 + bc + 1] = o[j][3];
        }
        if ((lane & 3) == 0) {
            sml[br0] = lA;
            sml[br0 + 8] = lB;
        }
    }
    __syncthreads();
    if (g == 0) {
        float r0 = 1.f / (lA + sml[br0]);
        float r1 = 1.f / (lB + sml[br0 + 8]);
        int rq0 = q0 + br0;
#pragma unroll
        for (int j = 0; j < 8; j++) {
            float v0 = (o[j][0] + scr[br0 * 64 + j * 8 + bc]) * r0;
            float v1 = (o[j][1] + scr[br0 * 64 + j * 8 + bc + 1]) * r0;
            float v2 = (o[j][2] + scr[(br0 + 8) * 64 + j * 8 + bc]) * r1;
            float v3 = (o[j][3] + scr[(br0 + 8) * 64 + j * 8 + bc + 1]) * r1;
            size_t i0 = ((size_t)(b * SEQ + rq0) * NH + h) * HDIM + j * 8 + bc;
            size_t i1 = ((size_t)(b * SEQ + rq0 + 8) * NH + h) * HDIM + j * 8 + bc;
            uint32_t hh, ll;
            packhl(v0, v1, hh, ll);
            *(uint32_t*)(g_attH + i0) = hh;
            *(uint32_t*)(g_attL + i0) = ll;
            packhl(v2, v3, hh, ll);
            *(uint32_t*)(g_attH + i1) = hh;
            *(uint32_t*)(g_attL + i1) = ll;
        }
    }
}

// ---------------- launch: two-stream fork/join for graph-level overlap ----------------
extern "C" void kernel_launch(void* const* d_in, const int* in_sizes, int n_in,
                              void* d_out, int out_size) {
    (void)in_sizes; (void)n_in; (void)out_size;
    const float* query = (const float*)d_in[0];
    const float* key   = (const float*)d_in[1];
    const float* value = (const float*)d_in[2];
    const float* qx    = (const float*)d_in[3];
    const float* qy    = (const float*)d_in[4];
    const float* kx    = (const float*)d_in[5];
    const float* ky    = (const float*)d_in[6];
    const float* Wq    = (const float*)d_in[7];
    const float* bq    = (const float*)d_in[8];
    const float* Wk    = (const float*)d_in[9];
    const float* bk    = (const float*)d_in[10];
    const float* Wv    = (const float*)d_in[11];
    const float* bv    = (const float*)d_in[12];
    const float* Wo    = (const float*)d_in[13];
    const float* bo    = (const float*)d_in[14];
    const float* xt    = (const float*)d_in[15];
    const float* yt    = (const float*)d_in[16];
    const float* Wb    = (const float*)d_in[17];
    const float* bb    = (const float*)d_in[18];
    float* out = (float*)d_out;

    static cudaStream_t s1 = nullptr;
    static cudaEvent_t eFork = nullptr, eJoin = nullptr;
    if (!s1) {
        cudaStreamCreateWithFlags(&s1, cudaStreamNonBlocking);
        cudaEventCreateWithFlags(&eFork, cudaEventDisableTiming);
        cudaEventCreateWithFlags(&eJoin, cudaEventDisableTiming);
    }

    // fork: side stream runs the memory-bound bias chain
    cudaEventRecord(eFork, 0);
    cudaStreamWaitEvent(s1, eFork, 0);
    k_project<<<(2 * NEMB * NH + 255) / 256, 256, 0, s1>>>(xt, yt, Wb);
    k_bias<<<dim3(SEQ / 16, SEQ / 16, NB), 256, 0, s1>>>(qx, qy, kx, ky, bb);
    cudaEventRecord(eJoin, s1);

    // main stream: mma-bound projection chain (overlaps with bias chain)
    k_conv<<<7168, 256>>>(query, key, value, Wq, Wk, Wv, Wo);
    k_mma_qkv<<<dim3(DMODEL / 64, (NB * SEQ) / 64, 3), 128>>>(bq, bk, bv);

    // join: attention needs both chains
    cudaStreamWaitEvent(0, eJoin, 0);
    k_attn<<<dim3(SEQ / 64, NH, NB), 256>>>();
    k_mma_out<<<dim3(DMODEL / 64, DMODEL / 64), 128>>>(bo, out);
}

// round 12
// speedup vs baseline: 2.2218x; 1.0447x over previous
#include <cuda_runtime.h>
#include <cuda_fp16.h>
#include <cstdint>

#define NH     16
#define DMODEL 1024
#define HDIM   64
#define NEMB   40001
#define NB     2
#define SEQ    512

// ---------------- device scratch ----------------
__device__ float g_Tx[NEMB * NH];
__device__ float g_Ty[NEMB * NH];
__device__ __half g_bias[(size_t)NB * NH * SEQ * SEQ];   // fp16 bias (16.7MB)

// fp16 hi/lo split operands
__device__ __half g_actH[3 * DMODEL * DMODEL];   // q,k,v activations [m][k]
__device__ __half g_actL[3 * DMODEL * DMODEL];
__device__ __half g_WtH[4 * DMODEL * DMODEL];    // Wq,Wk,Wv,Wo transposed [n][k] (hi only)
// projected Q/K/V in [b][h][seq][d], fp16 hi/lo (Q pre-scaled by 0.125)
__device__ __half g_QH[NB * NH * SEQ * HDIM], g_QL[NB * NH * SEQ * HDIM];
__device__ __half g_KH[NB * NH * SEQ * HDIM], g_KL[NB * NH * SEQ * HDIM];
__device__ __half g_VH[NB * NH * SEQ * HDIM];
// attention output hi/lo, [b*q][h*64+d] row-major 1024x1024
__device__ __half g_attH[DMODEL * DMODEL];
__device__ __half g_attL[DMODEL * DMODEL];

// ---------------- non-gated PTX helpers ----------------
__device__ __forceinline__ uint32_t smem_u32(const void* p) {
    uint32_t a;
    asm("{ .reg .u64 t; cvta.to.shared.u64 t, %1; cvt.u32.u64 %0, t; }" : "=r"(a) : "l"(p));
    return a;
}
__device__ __forceinline__ void cp_async16(uint32_t saddr, const void* gptr) {
    asm volatile("cp.async.cg.shared.global [%0], [%1], 16;" :: "r"(saddr), "l"(gptr) : "memory");
}
#define CP_COMMIT() asm volatile("cp.async.commit_group;" ::: "memory")
#define CP_WAIT(n)  asm volatile("cp.async.wait_group %0;" :: "n"(n) : "memory")

__device__ __forceinline__ void ldsm_x4(uint32_t* r, uint32_t addr) {
    asm volatile("ldmatrix.sync.aligned.m8n8.x4.shared.b16 {%0,%1,%2,%3}, [%4];"
                 : "=r"(r[0]), "=r"(r[1]), "=r"(r[2]), "=r"(r[3]) : "r"(addr));
}
__device__ __forceinline__ void ldsm_x2(uint32_t* r, uint32_t addr) {
    asm volatile("ldmatrix.sync.aligned.m8n8.x2.shared.b16 {%0,%1}, [%2];"
                 : "=r"(r[0]), "=r"(r[1]) : "r"(addr));
}
__device__ __forceinline__ void ldsm_x2_trans(uint32_t* r, uint32_t addr) {
    asm volatile("ldmatrix.sync.aligned.m8n8.x2.trans.shared.b16 {%0,%1}, [%2];"
                 : "=r"(r[0]), "=r"(r[1]) : "r"(addr));
}
__device__ __forceinline__ void mma16816(float* d, const uint32_t* a, const uint32_t* b) {
    asm volatile("mma.sync.aligned.m16n8k16.row.col.f32.f16.f16.f32 "
                 "{%0,%1,%2,%3}, {%4,%5,%6,%7}, {%8,%9}, {%0,%1,%2,%3};"
                 : "+f"(d[0]), "+f"(d[1]), "+f"(d[2]), "+f"(d[3])
                 : "r"(a[0]), "r"(a[1]), "r"(a[2]), "r"(a[3]), "r"(b[0]), "r"(b[1]));
}
// pack two floats into fp16x2 hi part + fp16x2 residual part
__device__ __forceinline__ void packhl(float a, float b, uint32_t& hh, uint32_t& ll) {
    __half2 h2 = __floats2half2_rn(a, b);
    float2 f = __half22float2(h2);
    __half2 l2 = __floats2half2_rn(a - f.x, b - f.y);
    hh = *reinterpret_cast<uint32_t*>(&h2);
    ll = *reinterpret_cast<uint32_t*>(&l2);
}

// ---------------- kernel 1: project embedding tables through Wb ----------------
__global__ __launch_bounds__(256) void k_project(const float* __restrict__ xt,
                                                 const float* __restrict__ yt,
                                                 const float* __restrict__ Wb) {
    int id = blockIdx.x * 256 + threadIdx.x;
    if (id >= 2 * NEMB * NH) return;
    int which = (id >= NEMB * NH);
    int rid = which ? id - NEMB * NH : id;
    int r = rid >> 4, h = rid & 15;
    const float4* row = (const float4*)((which ? yt : xt) + (size_t)r * 256 + h * 16);
    const float4* wb = (const float4*)Wb;
    float s = 0.f;
#pragma unroll
    for (int q = 0; q < 4; q++) {
        float4 v = row[q], w = wb[q];
        s += v.x * w.x + v.y * w.y + v.z * w.z + v.w * w.w;
    }
    (which ? g_Ty : g_Tx)[rid] = s;
}

// ---------------- kernel 2: positional bias (fp16 output) ----------------
__global__ __launch_bounds__(256) void k_bias(const float* __restrict__ qx,
                                              const float* __restrict__ qy,
                                              const float* __restrict__ kx,
                                              const float* __restrict__ ky,
                                              const float* __restrict__ bbp) {
    __shared__ float sm[16 * 256];
    int b = blockIdx.z;
    int i0 = blockIdx.y * 16, j0 = blockIdx.x * 16;
    int t = threadIdx.x;
    int i = i0 + (t >> 4), j = j0 + (t & 15);
    float bb = bbp[0];
    float dx = qx[b * SEQ + j] - kx[b * SEQ + i];
    float dy = qy[b * SEQ + j] - ky[b * SEQ + i];
    dx = fminf(fmaxf(dx, -1000.f), 1000.f);
    dy = fminf(fmaxf(dy, -1000.f), 1000.f);
    int ix = (int)rintf((dx + 1000.f) * 20.f);
    int iy = (int)rintf((dy + 1000.f) * 20.f);
    const float4* px = (const float4*)(g_Tx + (size_t)ix * 16);
    const float4* py = (const float4*)(g_Ty + (size_t)iy * 16);
#pragma unroll
    for (int q = 0; q < 4; q++) {
        float4 a = px[q], c = py[q];
        float v0 = a.x + c.x + bb, v1 = a.y + c.y + bb;
        float v2 = a.z + c.z + bb, v3 = a.w + c.w + bb;
        sm[(q * 4 + 0) * 256 + t] = 1.f / (1.f + __expf(-v0));
        sm[(q * 4 + 1) * 256 + t] = 1.f / (1.f + __expf(-v1));
        sm[(q * 4 + 2) * 256 + t] = 1.f / (1.f + __expf(-v2));
        sm[(q * 4 + 3) * 256 + t] = 1.f / (1.f + __expf(-v3));
    }
    __syncthreads();
    int h = t >> 4, w = t & 15;
#pragma unroll
    for (int ii = 0; ii < 16; ii++) {
        g_bias[(((size_t)(b * NH + h)) * SEQ + (i0 + ii)) * SEQ + (j0 + w)] =
            __float2half(sm[h * 256 + ii * 16 + w]);
    }
}

// ---------------- fp16 hi/lo split helpers ----------------
__device__ __forceinline__ void split4h(float4 x, __half2* ph, __half2* pl) {
    __half2 h01 = __floats2half2_rn(x.x, x.y);
    __half2 h23 = __floats2half2_rn(x.z, x.w);
    float2 f01 = __half22float2(h01), f23 = __half22float2(h23);
    ph[0] = h01; ph[1] = h23;
    pl[0] = __floats2half2_rn(x.x - f01.x, x.y - f01.y);
    pl[1] = __floats2half2_rn(x.z - f23.x, x.w - f23.y);
}

// ---------------- merged conversion kernel: activations + weights ----------------
__global__ __launch_bounds__(256) void k_conv(const float* __restrict__ q,
                                              const float* __restrict__ k,
                                              const float* __restrict__ v,
                                              const float* __restrict__ Wq,
                                              const float* __restrict__ Wk,
                                              const float* __restrict__ Wv,
                                              const float* __restrict__ Wo) {
    __shared__ float t[32][33];
    int bidx = blockIdx.x, tid = threadIdx.x;
    if (bidx < 3072) {
        int z = bidx >> 10;
        const float* src = (z == 0) ? q : (z == 1) ? k : v;
        __half* H = g_actH + (size_t)z * DMODEL * DMODEL;
        __half* L = g_actL + (size_t)z * DMODEL * DMODEL;
        int i = (bidx & 1023) * 256 + tid;
        float4 x = ((const float4*)src)[i];
        split4h(x, (__half2*)(H + (size_t)i * 4), (__half2*)(L + (size_t)i * 4));
    } else {
        int w = bidx - 3072;
        int z = w >> 10, rem = w & 1023;
        const float* W = (z == 0) ? Wq : (z == 1) ? Wk : (z == 2) ? Wv : Wo;
        __half* H = g_WtH + (size_t)z * DMODEL * DMODEL;
        int nb = (rem & 31) * 32, kb = (rem >> 5) * 32;
        int tx = tid & 31, ty = tid >> 5;   // 32 x 8
#pragma unroll
        for (int i = 0; i < 4; i++)
            t[ty + i * 8][tx] = W[(size_t)(kb + ty + i * 8) * DMODEL + nb + tx];
        __syncthreads();
#pragma unroll
        for (int i = 0; i < 4; i++) {
            int n = nb + ty + i * 8, kk = kb + tx;
            H[(size_t)n * DMODEL + kk] = __float2half(t[tx][ty + i * 8]);
        }
    }
}

// ---------------- warp-mma GEMM: C = (Ah+Al) @ Bh^T + bias ----------------
// Single pass over K=1024: per stage holds Ah, Al, B tiles; each B fragment is
// loaded once and consumed by BOTH hi and lo mma (B traffic/ldsm halved vs phased).
// BM=BN=64, BK=32, 128 threads, 4 warps (2m x 2n), 3-stage pipeline, 1 sync/iter.
#define NKITER 32
#define STAGES 3

template <int MODE>
__device__ __forceinline__ void mma_body(const __half* __restrict__ Ah,
                                         const __half* __restrict__ Al,
                                         const __half* __restrict__ Bh,
                                         const float* __restrict__ bias,
                                         __half* __restrict__ OH,
                                         __half* __restrict__ OL,
                                         float* __restrict__ OF,
                                         float scale) {
    __shared__ __align__(1024) char smem[STAGES][12288];   // Ah 4KB | Al 4KB | B 4KB
    int tid = threadIdx.x, lane = tid & 31, wid = tid >> 5;
    int wm = wid & 1, wn = wid >> 1;                  // 2 x 2 warp grid
    int m0 = blockIdx.y * 64, n0 = blockIdx.x * 64;
    uint32_t sbase = smem_u32(smem);

    float acc[2][4][4];
#pragma unroll
    for (int i = 0; i < 2; i++)
#pragma unroll
        for (int j = 0; j < 4; j++)
#pragma unroll
            for (int r = 0; r < 4; r++) acc[i][j][r] = 0.f;

    auto issue_tile = [&](int ki, int s) {
        int kk = ki * 32;
        uint32_t sAh = sbase + s * 12288, sAl = sAh + 4096, sB = sAh + 8192;
#pragma unroll
        for (int j = 0; j < 2; j++) {
            int idx = tid + j * 128;                   // 256 chunks per tile
            int row = idx >> 2, c = idx & 3;
            int cs = c ^ ((row >> 1) & 3);
            size_t ga = (size_t)(m0 + row) * DMODEL + kk + c * 8;
            cp_async16(sAh + row * 64 + cs * 16, Ah + ga);
            cp_async16(sAl + row * 64 + cs * 16, Al + ga);
            cp_async16(sB + row * 64 + cs * 16, Bh + (size_t)(n0 + row) * DMODEL + kk + c * 8);
        }
        CP_COMMIT();
    };

    issue_tile(0, 0);
    issue_tile(1, 1);
    for (int ki = 0; ki < NKITER; ki++) {
        int s = ki % STAGES;
        if (ki + 1 < NKITER) { CP_WAIT(1); } else { CP_WAIT(0); }
        __syncthreads();
        if (ki + 2 < NKITER) issue_tile(ki + 2, (ki + 2) % STAGES);
        uint32_t sAh = sbase + s * 12288, sAl = sAh + 4096, sB = sAh + 8192;
#pragma unroll
        for (int kq = 0; kq < 2; kq++) {
            uint32_t ah[2][4], al[2][4];
#pragma unroll
            for (int im = 0; im < 2; im++) {
                int row = wm * 32 + im * 16 + (lane & 15);
                int c = kq * 2 + (lane >> 4);
                int cs = c ^ ((row >> 1) & 3);
                ldsm_x4(ah[im], sAh + row * 64 + cs * 16);
                ldsm_x4(al[im], sAl + row * 64 + cs * 16);
            }
#pragma unroll
            for (int jnp = 0; jnp < 2; jnp++) {
                uint32_t bf[4];                          // 2 n-tiles x 2 k8 halves
                int mat = lane >> 3;
                int jn2 = jnp * 2 + (mat >> 1);
                int cc = kq * 2 + (mat & 1);
                int row = wn * 32 + jn2 * 8 + (lane & 7);
                int cs = cc ^ ((row >> 1) & 3);
                ldsm_x4(bf, sB + row * 64 + cs * 16);
#pragma unroll
                for (int im = 0; im < 2; im++) {
                    mma16816(acc[im][jnp * 2 + 0], ah[im], &bf[0]);
                    mma16816(acc[im][jnp * 2 + 0], al[im], &bf[0]);
                    mma16816(acc[im][jnp * 2 + 1], ah[im], &bf[2]);
                    mma16816(acc[im][jnp * 2 + 1], al[im], &bf[2]);
                }
            }
        }
    }

    // epilogue
#pragma unroll
    for (int im = 0; im < 2; im++) {
#pragma unroll
        for (int jn = 0; jn < 4; jn++) {
            int col = n0 + wn * 32 + jn * 8 + 2 * (lane & 3);
            float b0 = bias[col], b1 = bias[col + 1];
#pragma unroll
            for (int half = 0; half < 2; half++) {
                int m = m0 + wm * 32 + im * 16 + (lane >> 2) + half * 8;
                float v0 = (acc[im][jn][half * 2 + 0] + b0) * scale;
                float v1 = (acc[im][jn][half * 2 + 1] + b1) * scale;
                if (MODE == 0) {
                    int bidx = m >> 9, nseq = m & 511;
                    int h = col >> 6, d = col & 63;
                    size_t idx = (((size_t)(bidx * NH + h)) * SEQ + nseq) * HDIM + d;
                    uint32_t hh, ll;
                    packhl(v0, v1, hh, ll);
                    *(uint32_t*)(OH + idx) = hh;
                    if (OL) *(uint32_t*)(OL + idx) = ll;
                } else {
                    *(float2*)(OF + (size_t)m * DMODEL + col) = make_float2(v0, v1);
                }
            }
        }
    }
}

__global__ __launch_bounds__(128) void k_mma_qkv(const float* __restrict__ bq,
                                                 const float* __restrict__ bk,
                                                 const float* __restrict__ bv) {
    int z = blockIdx.z;
    const __half* Ah = g_actH + (size_t)z * DMODEL * DMODEL;
    const __half* Al = g_actL + (size_t)z * DMODEL * DMODEL;
    const __half* Bh = g_WtH + (size_t)z * DMODEL * DMODEL;
    const float* bias = (z == 0) ? bq : (z == 1) ? bk : bv;
    __half* OH = (z == 0) ? g_QH : (z == 1) ? g_KH : g_VH;
    __half* OL = (z == 0) ? g_QL : (z == 1) ? g_KL : nullptr;   // V needs hi only
    float scale = (z == 0) ? 0.125f : 1.0f;
    mma_body<0>(Ah, Al, Bh, bias, OH, OL, nullptr, scale);
}

__global__ __launch_bounds__(128) void k_mma_out(const float* __restrict__ bo,
                                                 float* __restrict__ out) {
    mma_body<1>(g_attH, g_attL, g_WtH + (size_t)3 * DMODEL * DMODEL,
                bo, nullptr, nullptr, out, 1.0f);
}

// ---------------- tensor-core flash attention, 8 warps, fixed-max softmax ----------------
__global__ __launch_bounds__(256) void k_attn() {
    __shared__ __align__(1024) char smbuf[40960];
    uint32_t sQH = smem_u32(smbuf), sQL = sQH + 8192;
    uint32_t sKH = sQH + 16384, sKL = sQH + 24576;
    uint32_t sVH = sQH + 32768;
    int b = blockIdx.z, h = blockIdx.y, q0 = blockIdx.x * 64;
    int tid = threadIdx.x, lane = tid & 31, wid = tid >> 5;
    int wq = wid & 3, g = wid >> 2;
    size_t hb = (size_t)(b * NH + h) * SEQ * HDIM;
    const __half *QHp = g_QH + hb, *QLp = g_QL + hb;
    const __half *KHp = g_KH + hb, *KLp = g_KL + hb;
    const __half *VHp = g_VH + hb;
    const __half* Bg = g_bias + ((size_t)(b * NH + h) * SEQ + q0) * SEQ;

#pragma unroll
    for (int u = 0; u < 2; u++) {
        int idx = u * 256 + tid;
        int row = idx >> 3, c = idx & 7, cs = c ^ (row & 7);
        size_t go = (size_t)(q0 + row) * HDIM + c * 8;
        cp_async16(sQH + row * 128 + cs * 16, QHp + go);
        cp_async16(sQL + row * 128 + cs * 16, QLp + go);
    }
    CP_COMMIT();
    CP_WAIT(0);
    __syncthreads();

    uint32_t qh[4][4], ql[4][4];
#pragma unroll
    for (int kk = 0; kk < 4; kk++) {
        int row = wq * 16 + (lane & 15);
        int c = kk * 2 + (lane >> 4), cs = c ^ (row & 7);
        ldsm_x4(qh[kk], sQH + row * 128 + cs * 16);
        ldsm_x4(ql[kk], sQL + row * 128 + cs * 16);
    }

    float o[8][4];
#pragma unroll
    for (int j = 0; j < 8; j++)
#pragma unroll
        for (int r = 0; r < 4; r++) o[j][r] = 0.f;
    float lA = 0.f, lB = 0.f;
    int br0 = wq * 16 + (lane >> 2);
    int bc = 2 * (lane & 3);
    int goff = g * 32;

    for (int k0 = 0; k0 < SEQ; k0 += 64) {
        __syncthreads();
#pragma unroll
        for (int u = 0; u < 2; u++) {
            int idx = u * 256 + tid;
            int row = idx >> 3, c = idx & 7, cs = c ^ (row & 7);
            size_t go = (size_t)(k0 + row) * HDIM + c * 8;
            cp_async16(sKH + row * 128 + cs * 16, KHp + go);
            cp_async16(sKL + row * 128 + cs * 16, KLp + go);
            cp_async16(sVH + row * 128 + cs * 16, VHp + go);
        }
        CP_COMMIT();
        float2 bias0[4], bias1[4];
#pragma unroll
        for (int jt = 0; jt < 4; jt++) {
            __half2 t0 = *(const __half2*)(Bg + (size_t)br0 * SEQ + k0 + goff + jt * 8 + bc);
            __half2 t1 = *(const __half2*)(Bg + (size_t)(br0 + 8) * SEQ + k0 + goff + jt * 8 + bc);
            bias0[jt] = __half22float2(t0);
            bias1[jt] = __half22float2(t1);
        }
        CP_WAIT(0);
        __syncthreads();

        float s[4][4];
#pragma unroll
        for (int jt = 0; jt < 4; jt++) {
            s[jt][0] = s[jt][1] = s[jt][2] = s[jt][3] = 0.f;
#pragma unroll
            for (int kk = 0; kk < 4; kk++) {
                uint32_t kh[2], kl[2];
                int row = goff + jt * 8 + (lane & 7);
                int c = kk * 2 + ((lane >> 3) & 1), cs = c ^ (row & 7);
                ldsm_x2(kh, sKH + row * 128 + cs * 16);
                ldsm_x2(kl, sKL + row * 128 + cs * 16);
                mma16816(s[jt], qh[kk], kh);
                mma16816(s[jt], ql[kk], kh);
                mma16816(s[jt], qh[kk], kl);
            }
        }

#pragma unroll
        for (int jt = 0; jt < 4; jt++) {
            s[jt][0] = __expf(s[jt][0] + bias0[jt].x);
            s[jt][1] = __expf(s[jt][1] + bias0[jt].y);
            s[jt][2] = __expf(s[jt][2] + bias1[jt].x);
            s[jt][3] = __expf(s[jt][3] + bias1[jt].y);
            lA += s[jt][0] + s[jt][1];
            lB += s[jt][2] + s[jt][3];
        }

        uint32_t ph[2][4], pl[2][4];
#pragma unroll
        for (int kk = 0; kk < 2; kk++) {
            packhl(s[2 * kk][0], s[2 * kk][1], ph[kk][0], pl[kk][0]);
            packhl(s[2 * kk][2], s[2 * kk][3], ph[kk][1], pl[kk][1]);
            packhl(s[2 * kk + 1][0], s[2 * kk + 1][1], ph[kk][2], pl[kk][2]);
            packhl(s[2 * kk + 1][2], s[2 * kk + 1][3], ph[kk][3], pl[kk][3]);
        }

#pragma unroll
        for (int kk = 0; kk < 2; kk++) {
#pragma unroll
            for (int j = 0; j < 8; j++) {
                uint32_t vh[2];
                int row = goff + kk * 16 + (lane & 15);
                int cs = j ^ (row & 7);
                ldsm_x2_trans(vh, sVH + row * 128 + cs * 16);
                mma16816(o[j], ph[kk], vh);
                mma16816(o[j], pl[kk], vh);
            }
        }
    }

    lA += __shfl_xor_sync(0xffffffffu, lA, 1);
    lA += __shfl_xor_sync(0xffffffffu, lA, 2);
    lB += __shfl_xor_sync(0xffffffffu, lB, 1);
    lB += __shfl_xor_sync(0xffffffffu, lB, 2);

    float* scr = (float*)(smbuf + 16384);
    float* sml = (float*)(smbuf + 32768);
    __syncthreads();
    if (g == 1) {
#pragma unroll
        for (int j = 0; j < 8; j++) {
            scr[br0 * 64 + j * 8 + bc] = o[j][0];
            scr[br0 * 64 + j * 8 + bc + 1] = o[j][1];
            scr[(br0 + 8) * 64 + j * 8 + bc] = o[j][2];
            scr[(br0 + 8) * 64 + j * 8 + bc + 1] = o[j][3];
        }
        if ((lane & 3) == 0) {
            sml[br0] = lA;
            sml[br0 + 8] = lB;
        }
    }
    __syncthreads();
    if (g == 0) {
        float r0 = 1.f / (lA + sml[br0]);
        float r1 = 1.f / (lB + sml[br0 + 8]);
        int rq0 = q0 + br0;
#pragma unroll
        for (int j = 0; j < 8; j++) {
            float v0 = (o[j][0] + scr[br0 * 64 + j * 8 + bc]) * r0;
            float v1 = (o[j][1] + scr[br0 * 64 + j * 8 + bc + 1]) * r0;
            float v2 = (o[j][2] + scr[(br0 + 8) * 64 + j * 8 + bc]) * r1;
            float v3 = (o[j][3] + scr[(br0 + 8) * 64 + j * 8 + bc + 1]) * r1;
            size_t i0 = ((size_t)(b * SEQ + rq0) * NH + h) * HDIM + j * 8 + bc;
            size_t i1 = ((size_t)(b * SEQ + rq0 + 8) * NH + h) * HDIM + j * 8 + bc;
            uint32_t hh, ll;
            packhl(v0, v1, hh, ll);
            *(uint32_t*)(g_attH + i0) = hh;
            *(uint32_t*)(g_attL + i0) = ll;
            packhl(v2, v3, hh, ll);
            *(uint32_t*)(g_attH + i1) = hh;
            *(uint32_t*)(g_attL + i1) = ll;
        }
    }
}

// ---------------- launch: two-stream fork/join for graph-level overlap ----------------
extern "C" void kernel_launch(void* const* d_in, const int* in_sizes, int n_in,
                              void* d_out, int out_size) {
    (void)in_sizes; (void)n_in; (void)out_size;
    const float* query = (const float*)d_in[0];
    const float* key   = (const float*)d_in[1];
    const float* value = (const float*)d_in[2];
    const float* qx    = (const float*)d_in[3];
    const float* qy    = (const float*)d_in[4];
    const float* kx    = (const float*)d_in[5];
    const float* ky    = (const float*)d_in[6];
    const float* Wq    = (const float*)d_in[7];
    const float* bq    = (const float*)d_in[8];
    const float* Wk    = (const float*)d_in[9];
    const float* bk    = (const float*)d_in[10];
    const float* Wv    = (const float*)d_in[11];
    const float* bv    = (const float*)d_in[12];
    const float* Wo    = (const float*)d_in[13];
    const float* bo    = (const float*)d_in[14];
    const float* xt    = (const float*)d_in[15];
    const float* yt    = (const float*)d_in[16];
    const float* Wb    = (const float*)d_in[17];
    const float* bb    = (const float*)d_in[18];
    float* out = (float*)d_out;

    static cudaStream_t s1 = nullptr;
    static cudaEvent_t eFork = nullptr, eJoin = nullptr;
    if (!s1) {
        cudaStreamCreateWithFlags(&s1, cudaStreamNonBlocking);
        cudaEventCreateWithFlags(&eFork, cudaEventDisableTiming);
        cudaEventCreateWithFlags(&eJoin, cudaEventDisableTiming);
    }

    // fork: side stream runs the memory-bound bias chain
    cudaEventRecord(eFork, 0);
    cudaStreamWaitEvent(s1, eFork, 0);
    k_project<<<(2 * NEMB * NH + 255) / 256, 256, 0, s1>>>(xt, yt, Wb);
    k_bias<<<dim3(SEQ / 16, SEQ / 16, NB), 256, 0, s1>>>(qx, qy, kx, ky, bb);
    cudaEventRecord(eJoin, s1);

    // main stream: mma-bound projection chain (overlaps with bias chain)
    k_conv<<<7168, 256>>>(query, key, value, Wq, Wk, Wv, Wo);
    k_mma_qkv<<<dim3(DMODEL / 64, (NB * SEQ) / 64, 3), 128>>>(bq, bk, bv);

    // join: attention needs both chains
    cudaStreamWaitEvent(0, eJoin, 0);
    k_attn<<<dim3(SEQ / 64, NH, NB), 256>>>();
    k_mma_out<<<dim3(DMODEL / 64, DMODEL / 64), 128>>>(bo, out);
}